// round 1
// baseline (speedup 1.0000x reference)
#include <cuda_runtime.h>
#include <math.h>
#include <stdint.h>

// Problem constants
#define Dm    1024
#define Hh    16
#define DHd   64
#define Ee    8
#define HIDm  2048
#define TOPKk 2
#define Bb    2
#define Ll    2048
#define Tt    4096          // B*L
#define QKV3  3072
#define NASS  (Tt*TOPKk)    // 8192 total expert assignments

// ---------------- scratch (static device memory; no allocations allowed) ---
__device__ float g_xn1 [Tt*Dm];
__device__ float g_qkv [Tt*QKV3];
__device__ float g_ao  [Tt*Dm];
__device__ float g_x1  [Tt*Dm];
__device__ float g_xn2 [Tt*Dm];
__device__ float g_probs[Tt*Ee];
__device__ int   g_idx [NASS];
__device__ float g_wts [NASS];
__device__ int   g_counts[Ee];
__device__ int   g_offsets[Ee+1];
__device__ int   g_fill[Ee];
__device__ int   g_assign_row[NASS];
__device__ int   g_pos_of[NASS];
__device__ float g_h  [(size_t)NASS*HIDm];   // 64 MB
__device__ float g_eo [(size_t)NASS*Dm];     // 32 MB
__device__ float g_me [Ee];
__device__ float g_ce [Ee];

// ---------------------------------------------------------------- utilities
__global__ void init_kernel() {
    int i = threadIdx.x;
    if (i < Ee) { g_counts[i] = 0; g_fill[i] = 0; }
}

// LayerNorm: one block per token
__global__ __launch_bounds__(256) void ln_kernel(
    const float* __restrict__ x, const float* __restrict__ g,
    const float* __restrict__ b, float* __restrict__ out)
{
    int t = blockIdx.x, tid = threadIdx.x;
    const float* xr = x + (size_t)t*Dm;
    float s = 0.f, s2 = 0.f;
    for (int d = tid; d < Dm; d += 256) { float v = xr[d]; s += v; s2 += v*v; }
    __shared__ float sh1[256], sh2[256];
    sh1[tid] = s; sh2[tid] = s2; __syncthreads();
    for (int st = 128; st > 0; st >>= 1) {
        if (tid < st) { sh1[tid] += sh1[tid+st]; sh2[tid] += sh2[tid+st]; }
        __syncthreads();
    }
    float mu  = sh1[0] * (1.f/Dm);
    float var = sh2[0] * (1.f/Dm) - mu*mu;
    float inv = rsqrtf(var + 1e-5f);
    float* orow = out + (size_t)t*Dm;
    for (int d = tid; d < Dm; d += 256)
        orow[d] = (xr[d]-mu)*inv*g[d] + b[d];
}

// --------------------------------------------------- NT GEMM: C = A @ B^T + bias (+res)
// A[M,K] row-major, B[N,K] row-major. 64x64 tile, BK=16, 128 threads.
#define BM 64
#define BN 64
#define BKK 16
template<int RES>
__global__ __launch_bounds__(128) void gemm_nt(
    const float* __restrict__ A, const float* __restrict__ B,
    const float* __restrict__ bias, const float* __restrict__ res,
    float* __restrict__ C, int M, int N, int K)
{
    __shared__ float As[BM][BKK+1];
    __shared__ float Bs[BN][BKK+1];
    int n0 = blockIdx.x*BN, m0 = blockIdx.y*BM;
    int tid = threadIdx.x;
    int r0 = (tid>>4)*8, c0 = (tid&15)*4;
    float acc[8][4] = {};
    for (int k0 = 0; k0 < K; k0 += BKK) {
        for (int i = tid; i < BM*BKK; i += 128) {
            int r = i>>4, kk = i&15;
            As[r][kk] = A[(size_t)(m0+r)*K + k0 + kk];
        }
        for (int i = tid; i < BN*BKK; i += 128) {
            int c = i>>4, kk = i&15;
            Bs[c][kk] = B[(size_t)(n0+c)*K + k0 + kk];
        }
        __syncthreads();
        #pragma unroll
        for (int kk = 0; kk < BKK; kk++) {
            float bf[4];
            #pragma unroll
            for (int j = 0; j < 4; j++) bf[j] = Bs[c0+j][kk];
            #pragma unroll
            for (int i = 0; i < 8; i++) {
                float av = As[r0+i][kk];
                #pragma unroll
                for (int j = 0; j < 4; j++) acc[i][j] += av*bf[j];
            }
        }
        __syncthreads();
    }
    #pragma unroll
    for (int i = 0; i < 8; i++) {
        int m = m0 + r0 + i;
        #pragma unroll
        for (int j = 0; j < 4; j++) {
            int n = n0 + c0 + j;
            float v = acc[i][j] + bias[n];
            if (RES) v += res[(size_t)m*N + n];
            C[(size_t)m*N + n] = v;
        }
    }
}

// ---------------------------------------------------------- flash attention
// grid (L/64, H, B), 64 threads. Each thread owns one query row.
__global__ __launch_bounds__(64) void flash_attn_kernel(
    const float* __restrict__ qkv, const unsigned char* __restrict__ mask,
    float* __restrict__ ao)
{
    __shared__ __align__(16) float sm[6144];  // 24KB: reused Q-stage / K,V,S
    __shared__ unsigned char smask[32];
    float* Ks  = sm;            // [32][64]
    float* Vs  = sm + 2048;     // [32][64]
    float* Ssh = sm + 4096;     // [32][64]

    int b = blockIdx.z, h = blockIdx.y, qt = blockIdx.x;
    int tid = threadIdx.x;
    int t0 = b*Ll + qt*64;

    // stage Q tile then copy own row to registers (stride-65 pad -> no conflicts)
    for (int r = 0; r < 64; r++)
        sm[r*65 + tid] = qkv[(size_t)(t0+r)*QKV3 + h*DHd + tid];
    __syncthreads();
    float q[64];
    #pragma unroll
    for (int d = 0; d < 64; d++) q[d] = sm[tid*65 + d];
    __syncthreads();

    float o[64];
    #pragma unroll
    for (int d = 0; d < 64; d++) o[d] = 0.f;
    float m = -1e30f, l = 0.f;

    for (int u0 = 0; u0 < Ll; u0 += 32) {
        for (int i = 0; i < 32; i++) {
            size_t base = (size_t)(b*Ll + u0 + i)*QKV3 + h*DHd + tid;
            Ks[i*64 + tid] = qkv[base + Dm];
            Vs[i*64 + tid] = qkv[base + 2*Dm];
        }
        if (tid < 32) smask[tid] = mask[b*Ll + u0 + tid];
        __syncthreads();

        // S = Q K^T * scale (store per-thread column in smem, track tile max)
        float tmax = -1e30f;
        for (int c = 0; c < 32; c++) {
            const float4* kp = (const float4*)&Ks[c*64];
            float acc = 0.f;
            #pragma unroll
            for (int dd = 0; dd < 16; dd++) {
                float4 kv = kp[dd];
                acc += q[4*dd+0]*kv.x + q[4*dd+1]*kv.y
                     + q[4*dd+2]*kv.z + q[4*dd+3]*kv.w;
            }
            float sv = smask[c] ? -1e9f : acc*0.125f;
            Ssh[c*64 + tid] = sv;
            tmax = fmaxf(tmax, sv);
        }
        float mn = fmaxf(m, tmax);
        float corr = __expf(m - mn);
        l *= corr;
        #pragma unroll
        for (int d = 0; d < 64; d++) o[d] *= corr;
        for (int c = 0; c < 32; c++) {
            float p = __expf(Ssh[c*64 + tid] - mn);
            l += p;
            const float4* vp = (const float4*)&Vs[c*64];
            #pragma unroll
            for (int dd = 0; dd < 16; dd++) {
                float4 vv = vp[dd];
                o[4*dd+0] += p*vv.x; o[4*dd+1] += p*vv.y;
                o[4*dd+2] += p*vv.z; o[4*dd+3] += p*vv.w;
            }
        }
        m = mn;
        __syncthreads();
    }
    float inv = 1.f / l;
    float* orow = ao + (size_t)(t0+tid)*Dm + h*DHd;
    #pragma unroll
    for (int dd = 0; dd < 16; dd++) {
        float4 v4 = make_float4(o[4*dd]*inv, o[4*dd+1]*inv, o[4*dd+2]*inv, o[4*dd+3]*inv);
        ((float4*)orow)[dd] = v4;
    }
}

// ------------------------------------------------------------------- gating
__global__ __launch_bounds__(128) void gate_kernel(
    const float* __restrict__ xn2, const float* __restrict__ Wg,
    const float* __restrict__ bg)
{
    int t = blockIdx.x, tid = threadIdx.x;
    const float* xr = xn2 + (size_t)t*Dm;
    float part[Ee] = {};
    for (int d = tid; d < Dm; d += 128) {
        float xv = xr[d];
        const float* wr = Wg + (size_t)d*Ee;
        #pragma unroll
        for (int e = 0; e < Ee; e++) part[e] += xv*wr[e];
    }
    __shared__ float red[128];
    __shared__ float logits[Ee];
    for (int e = 0; e < Ee; e++) {
        red[tid] = part[e]; __syncthreads();
        for (int st = 64; st > 0; st >>= 1) {
            if (tid < st) red[tid] += red[tid+st];
            __syncthreads();
        }
        if (tid == 0) logits[e] = red[0] + bg[e];
        __syncthreads();
    }
    if (tid == 0) {
        float mx = -1e30f;
        #pragma unroll
        for (int e = 0; e < Ee; e++) mx = fmaxf(mx, logits[e]);
        float p[Ee], se = 0.f;
        #pragma unroll
        for (int e = 0; e < Ee; e++) { p[e] = expf(logits[e]-mx); se += p[e]; }
        float isz = 1.f/se;
        #pragma unroll
        for (int e = 0; e < Ee; e++) { p[e] *= isz; g_probs[t*Ee+e] = p[e]; }
        int i0 = 0;
        #pragma unroll
        for (int e = 1; e < Ee; e++) if (p[e] > p[i0]) i0 = e;
        int i1 = (i0 == 0) ? 1 : 0;
        #pragma unroll
        for (int e = 0; e < Ee; e++) if (e != i0 && p[e] > p[i1]) i1 = e;
        float v0 = p[i0], v1 = p[i1], s01 = v0 + v1;
        g_idx[2*t]   = i0; g_idx[2*t+1] = i1;
        g_wts[2*t]   = v0/s01; g_wts[2*t+1] = v1/s01;
        atomicAdd(&g_counts[i0], 1);
        atomicAdd(&g_counts[i1], 1);
    }
}

__global__ void offsets_kernel() {
    if (threadIdx.x == 0) {
        int o = 0;
        for (int e = 0; e < Ee; e++) { g_offsets[e] = o; o += g_counts[e]; }
        g_offsets[Ee] = o;
    }
}

__global__ void scatter_kernel() {
    int a = blockIdx.x*blockDim.x + threadIdx.x;
    if (a < NASS) {
        int e = g_idx[a];
        int pos = g_offsets[e] + atomicAdd(&g_fill[e], 1);
        g_assign_row[pos] = a >> 1;
        g_pos_of[a] = pos;
    }
}

// --------------------------------------- expert GEMM (NN, gathered A rows)
// C[rows_of_expert, N] = act(A @ W[e] + bias[e]), W[e] is [K,N] row-major.
template<int GATHER, int GELU>
__global__ __launch_bounds__(128) void moe_gemm(
    const float* __restrict__ Ain, const float* __restrict__ W,
    const float* __restrict__ bias, float* __restrict__ Cout,
    int K, int N)
{
    int e = blockIdx.z;
    int cnt = g_counts[e];
    int rt = blockIdx.y;
    if (rt*BM >= cnt) return;
    int off = g_offsets[e];
    int n0 = blockIdx.x*BN;
    const float* Bexp = W + (size_t)e*K*N;
    const float* be   = bias + (size_t)e*N;

    __shared__ float As[BM][BKK+1];
    __shared__ float Bs[BKK][BN];
    __shared__ const float* rowp[BM];
    int tid = threadIdx.x;
    if (tid < BM) {
        int lr = rt*BM + tid;
        if (lr < cnt) {
            int gr = off + lr;
            rowp[tid] = GATHER ? (Ain + (size_t)g_assign_row[gr]*K)
                               : (Ain + (size_t)gr*K);
        } else rowp[tid] = nullptr;
    }
    __syncthreads();

    int r0 = (tid>>4)*8, c0 = (tid&15)*4;
    float acc[8][4] = {};
    for (int k0 = 0; k0 < K; k0 += BKK) {
        for (int i = tid; i < BM*BKK; i += 128) {
            int r = i>>4, kk = i&15;
            const float* p = rowp[r];
            As[r][kk] = p ? p[k0+kk] : 0.f;
        }
        for (int i = tid; i < BKK*BN; i += 128) {
            int kk = i>>6, c = i&63;
            Bs[kk][c] = Bexp[(size_t)(k0+kk)*N + n0 + c];
        }
        __syncthreads();
        #pragma unroll
        for (int kk = 0; kk < BKK; kk++) {
            float4 bf4 = *(const float4*)&Bs[kk][c0];
            float bf[4] = {bf4.x, bf4.y, bf4.z, bf4.w};
            #pragma unroll
            for (int i = 0; i < 8; i++) {
                float av = As[r0+i][kk];
                #pragma unroll
                for (int j = 0; j < 4; j++) acc[i][j] += av*bf[j];
            }
        }
        __syncthreads();
    }
    #pragma unroll
    for (int i = 0; i < 8; i++) {
        int lr = rt*BM + r0 + i;
        if (lr >= cnt) continue;
        int gr = off + lr;
        #pragma unroll
        for (int j = 0; j < 4; j++) {
            int n = n0 + c0 + j;
            float v = acc[i][j] + be[n];
            if (GELU) v = 0.5f*v*(1.f + erff(v*0.70710678118f));
            Cout[(size_t)gr*N + n] = v;
        }
    }
}

// ------------------------------------------------------ combine + moe loss
__global__ __launch_bounds__(256) void combine_kernel(float* __restrict__ out) {
    int t = blockIdx.x, tid = threadIdx.x;
    int p0 = g_pos_of[2*t], p1 = g_pos_of[2*t+1];
    float w0 = g_wts[2*t], w1 = g_wts[2*t+1];
    const float* e0 = g_eo + (size_t)p0*Dm;
    const float* e1 = g_eo + (size_t)p1*Dm;
    const float* xr = g_x1 + (size_t)t*Dm;
    float* orow = out + (size_t)t*Dm;
    for (int d = tid; d < Dm; d += 256)
        orow[d] = xr[d] + w0*e0[d] + w1*e1[d];
}

__global__ __launch_bounds__(256) void mece_kernel() {
    int e = blockIdx.x, tid = threadIdx.x;
    float s = 0.f, c = 0.f;
    for (int t = tid; t < Tt; t += 256) s += g_probs[t*Ee + e];
    for (int a = tid; a < NASS; a += 256) c += (g_idx[a] == e) ? 1.f : 0.f;
    __shared__ float sh1[256], sh2[256];
    sh1[tid] = s; sh2[tid] = c; __syncthreads();
    for (int st = 128; st > 0; st >>= 1) {
        if (tid < st) { sh1[tid] += sh1[tid+st]; sh2[tid] += sh2[tid+st]; }
        __syncthreads();
    }
    if (tid == 0) { g_me[e] = sh1[0]*(1.f/Tt); g_ce[e] = sh2[0]*(1.f/Tt); }
}

__global__ void loss_kernel(float* __restrict__ out, int out_size) {
    if (threadIdx.x == 0 && out_size > Tt*Dm) {
        float L = 0.f;
        for (int e = 0; e < Ee; e++) L += g_me[e]*g_ce[e];
        out[Tt*Dm] = (float)Ee * L;
    }
}

// ------------------------------------------------------------------ driver
extern "C" void kernel_launch(void* const* d_in, const int* in_sizes, int n_in,
                              void* d_out, int out_size)
{
    const float* x     = (const float*)d_in[0];
    const unsigned char* mask = (const unsigned char*)d_in[1];
    const float* ln1_g = (const float*)d_in[2];
    const float* ln1_b = (const float*)d_in[3];
    const float* Wqkv  = (const float*)d_in[4];
    const float* bqkv  = (const float*)d_in[5];
    const float* Wo    = (const float*)d_in[6];
    const float* bo    = (const float*)d_in[7];
    const float* ln2_g = (const float*)d_in[8];
    const float* ln2_b = (const float*)d_in[9];
    const float* Wg    = (const float*)d_in[10];
    const float* bg    = (const float*)d_in[11];
    const float* W1    = (const float*)d_in[12];
    const float* b1    = (const float*)d_in[13];
    const float* W2    = (const float*)d_in[14];
    const float* b2    = (const float*)d_in[15];
    float* out = (float*)d_out;

    float *xn1, *qkv, *ao, *x1, *xn2, *hbuf, *eobuf;
    cudaGetSymbolAddress((void**)&xn1,  g_xn1);
    cudaGetSymbolAddress((void**)&qkv,  g_qkv);
    cudaGetSymbolAddress((void**)&ao,   g_ao);
    cudaGetSymbolAddress((void**)&x1,   g_x1);
    cudaGetSymbolAddress((void**)&xn2,  g_xn2);
    cudaGetSymbolAddress((void**)&hbuf, g_h);
    cudaGetSymbolAddress((void**)&eobuf,g_eo);

    init_kernel<<<1, 32>>>();

    // LN1 -> QKV GEMM
    ln_kernel<<<Tt, 256>>>(x, ln1_g, ln1_b, xn1);
    gemm_nt<0><<<dim3(QKV3/BN, Tt/BM), 128>>>(xn1, Wqkv, bqkv, nullptr, qkv,
                                              Tt, QKV3, Dm);
    // attention
    flash_attn_kernel<<<dim3(Ll/64, Hh, Bb), 64>>>(qkv, mask, ao);

    // output proj + residual
    gemm_nt<1><<<dim3(Dm/BN, Tt/BM), 128>>>(ao, Wo, bo, x, x1, Tt, Dm, Dm);

    // LN2 -> gate -> expert routing
    ln_kernel<<<Tt, 256>>>(x1, ln2_g, ln2_b, xn2);
    gate_kernel<<<Tt, 128>>>(xn2, Wg, bg);
    offsets_kernel<<<1, 32>>>();
    scatter_kernel<<<(NASS+255)/256, 256>>>();

    // sparse MoE: only the selected (token, expert) pairs
    moe_gemm<1,1><<<dim3(HIDm/BN, Tt/BM, Ee), 128>>>(xn2, W1, b1, hbuf, Dm, HIDm);
    moe_gemm<0,0><<<dim3(Dm/BN,   Tt/BM, Ee), 128>>>(hbuf, W2, b2, eobuf, HIDm, Dm);

    // combine + aux loss
    combine_kernel<<<Tt, 256>>>(out);
    mece_kernel<<<Ee, 256>>>();
    loss_kernel<<<1, 32>>>(out, out_size);
}

// round 2
// speedup vs baseline: 2.2788x; 2.2788x over previous
#include <cuda_runtime.h>
#include <math.h>
#include <stdint.h>

// Problem constants
#define Dm    1024
#define Hh    16
#define DHd   64
#define Ee    8
#define HIDm  2048
#define TOPKk 2
#define Bb    2
#define Ll    2048
#define Tt    4096          // B*L
#define QKV3  3072
#define NASS  (Tt*TOPKk)

// ---------------- scratch (static device memory) ---------------------------
__device__ float g_xn1 [Tt*Dm];
__device__ float g_qkv [Tt*QKV3];
__device__ float g_ao  [Tt*Dm];
__device__ float g_x1  [Tt*Dm];
__device__ float g_xn2 [Tt*Dm];
__device__ float g_probs[Tt*Ee];
__device__ int   g_idx [NASS];
__device__ float g_wts [NASS];
__device__ int   g_counts[Ee];
__device__ int   g_offsets[Ee+1];
__device__ int   g_fill[Ee];
__device__ int   g_assign_row[NASS];
__device__ int   g_pos_of[NASS];
__device__ float g_h  [(size_t)NASS*HIDm];
__device__ float g_eo [(size_t)NASS*Dm];
__device__ float g_me [Ee];
__device__ float g_ce [Ee];

// ---------------------------------------------------------------- utilities
__global__ void init_kernel() {
    int i = threadIdx.x;
    if (i < Ee) { g_counts[i] = 0; g_fill[i] = 0; }
}

__global__ __launch_bounds__(256) void ln_kernel(
    const float* __restrict__ x, const float* __restrict__ g,
    const float* __restrict__ b, float* __restrict__ out)
{
    int t = blockIdx.x, tid = threadIdx.x;
    const float* xr = x + (size_t)t*Dm;
    float s = 0.f, s2 = 0.f;
    for (int d = tid; d < Dm; d += 256) { float v = xr[d]; s += v; s2 += v*v; }
    __shared__ float sh1[256], sh2[256];
    sh1[tid] = s; sh2[tid] = s2; __syncthreads();
    for (int st = 128; st > 0; st >>= 1) {
        if (tid < st) { sh1[tid] += sh1[tid+st]; sh2[tid] += sh2[tid+st]; }
        __syncthreads();
    }
    float mu  = sh1[0] * (1.f/Dm);
    float var = sh2[0] * (1.f/Dm) - mu*mu;
    float inv = rsqrtf(var + 1e-5f);
    float* orow = out + (size_t)t*Dm;
    for (int d = tid; d < Dm; d += 256)
        orow[d] = (xr[d]-mu)*inv*g[d] + b[d];
}

// ------------------------------------------------------ tf32 MMA primitives
__device__ __forceinline__ uint32_t f2tf(float x) {
    uint32_t y;
    asm("cvt.rna.tf32.f32 %0, %1;" : "=r"(y) : "f"(x));
    return y;
}
__device__ __forceinline__ void mma_tf32(float* c, const uint32_t* a, const uint32_t* b) {
    asm volatile(
        "mma.sync.aligned.m16n8k8.row.col.f32.tf32.tf32.f32 "
        "{%0,%1,%2,%3}, {%4,%5,%6,%7}, {%8,%9}, {%0,%1,%2,%3};"
        : "+f"(c[0]), "+f"(c[1]), "+f"(c[2]), "+f"(c[3])
        : "r"(a[0]), "r"(a[1]), "r"(a[2]), "r"(a[3]), "r"(b[0]), "r"(b[1]));
}

// ------------------------------------------ tensor-core GEMM (tf32 mma.sync)
// CTA tile 128x128x32, 256 threads = 8 warps (2x4), warp tile 64x32.
// A rows gathered via rowsrc[]; B either NT (B[N,K]) or NN (B[K,N]).
#define BM 128
#define BN 128
#define BK 32
#define KST 36   // padded smem K stride (conflict-free: 36 % 32 == 4)

template<int GATHER, int TRANSB, int GELU, int RES, int MOE>
__global__ __launch_bounds__(256) void mma_gemm(
    const float* __restrict__ A, const float* __restrict__ Bmat,
    const float* __restrict__ bias, const float* __restrict__ res,
    float* __restrict__ C, int M, int N, int K)
{
    __shared__ uint32_t As[BM*KST];
    __shared__ uint32_t Bs[BN*KST];
    __shared__ int rowsrc[BM];

    int e = MOE ? blockIdx.z : 0;
    int cnt = M, off = 0;
    if (MOE) {
        cnt = g_counts[e]; off = g_offsets[e];
        if ((int)blockIdx.y * BM >= cnt) return;
    }
    int m0 = blockIdx.y * BM;
    int n0 = blockIdx.x * BN;
    int tid = threadIdx.x;

    const float* Bbase = Bmat + (size_t)e * K * N;
    const float* bi    = bias + (size_t)e * N;

    if (tid < BM) {
        int lr = m0 + tid;
        int r;
        if (MOE) {
            int l = lr < cnt ? lr : cnt - 1;
            r = GATHER ? g_assign_row[off + l] : (off + l);
        } else r = lr;
        rowsrc[tid] = r;
    }
    __syncthreads();

    int lane = tid & 31;
    int wid  = tid >> 5;
    int wm = (wid >> 2) * 64;   // warp m offset: 0/64
    int wn = (wid & 3) * 32;    // warp n offset: 0/32/64/96
    int g  = lane >> 2;         // 0..7
    int tg = lane & 3;          // 0..3

    float acc[4][4][4];
    #pragma unroll
    for (int i = 0; i < 4; i++)
        #pragma unroll
        for (int j = 0; j < 4; j++)
            #pragma unroll
            for (int q = 0; q < 4; q++) acc[i][j][q] = 0.f;

    float4 pa[4], pb[4];

    auto loadA = [&](int k0) {
        #pragma unroll
        for (int p = 0; p < 4; p++) {
            int r = p*32 + (tid >> 3);
            int c = (tid & 7) * 4;
            pa[p] = *(const float4*)(A + (size_t)rowsrc[r]*K + k0 + c);
        }
    };
    auto loadB = [&](int k0) {
        if (!TRANSB) {
            #pragma unroll
            for (int p = 0; p < 4; p++) {
                int r = p*32 + (tid >> 3);
                int c = (tid & 7) * 4;
                pb[p] = *(const float4*)(Bbase + (size_t)(n0 + r)*K + k0 + c);
            }
        } else {
            #pragma unroll
            for (int p = 0; p < 4; p++) {
                int n  = tid & 127;
                int kg = p*2 + (tid >> 7);   // 0..7
                const float* s = Bbase + (size_t)(k0 + kg*4)*N + n0 + n;
                pb[p].x = s[0];
                pb[p].y = s[(size_t)N];
                pb[p].z = s[(size_t)2*N];
                pb[p].w = s[(size_t)3*N];
            }
        }
    };
    auto storeA = [&]() {
        #pragma unroll
        for (int p = 0; p < 4; p++) {
            int r = p*32 + (tid >> 3);
            int c = (tid & 7) * 4;
            uint4 u = make_uint4(f2tf(pa[p].x), f2tf(pa[p].y), f2tf(pa[p].z), f2tf(pa[p].w));
            *(uint4*)&As[r*KST + c] = u;
        }
    };
    auto storeB = [&]() {
        if (!TRANSB) {
            #pragma unroll
            for (int p = 0; p < 4; p++) {
                int r = p*32 + (tid >> 3);
                int c = (tid & 7) * 4;
                uint4 u = make_uint4(f2tf(pb[p].x), f2tf(pb[p].y), f2tf(pb[p].z), f2tf(pb[p].w));
                *(uint4*)&Bs[r*KST + c] = u;
            }
        } else {
            #pragma unroll
            for (int p = 0; p < 4; p++) {
                int n  = tid & 127;
                int kg = p*2 + (tid >> 7);
                uint4 u = make_uint4(f2tf(pb[p].x), f2tf(pb[p].y), f2tf(pb[p].z), f2tf(pb[p].w));
                *(uint4*)&Bs[n*KST + kg*4] = u;
            }
        }
    };
    auto compute = [&]() {
        #pragma unroll
        for (int ks = 0; ks < 4; ks++) {
            int k0 = ks * 8;
            uint32_t af[4][4];
            #pragma unroll
            for (int mt = 0; mt < 4; mt++) {
                int r = wm + mt*16 + g;
                af[mt][0] = As[r*KST + k0 + tg];
                af[mt][1] = As[(r+8)*KST + k0 + tg];
                af[mt][2] = As[r*KST + k0 + 4 + tg];
                af[mt][3] = As[(r+8)*KST + k0 + 4 + tg];
            }
            uint32_t bf[4][2];
            #pragma unroll
            for (int nt = 0; nt < 4; nt++) {
                int n = wn + nt*8 + g;
                bf[nt][0] = Bs[n*KST + k0 + tg];
                bf[nt][1] = Bs[n*KST + k0 + 4 + tg];
            }
            #pragma unroll
            for (int mt = 0; mt < 4; mt++)
                #pragma unroll
                for (int nt = 0; nt < 4; nt++)
                    mma_tf32(acc[mt][nt], af[mt], bf[nt]);
        }
    };

    int KT = K / BK;
    loadA(0); loadB(0);
    storeA(); storeB();
    __syncthreads();
    for (int t = 0; t < KT; t++) {
        if (t + 1 < KT) { loadA((t+1)*BK); loadB((t+1)*BK); }
        compute();
        __syncthreads();
        if (t + 1 < KT) {
            storeA(); storeB();
            __syncthreads();
        }
    }

    // epilogue
    #pragma unroll
    for (int mt = 0; mt < 4; mt++) {
        #pragma unroll
        for (int h = 0; h < 2; h++) {
            int lr = m0 + wm + mt*16 + g + 8*h;
            if (MOE && lr >= cnt) continue;
            int gr = MOE ? off + (lr - m0) + m0 - m0 : lr;   // MoE rows are contiguous in expert buffer
            if (MOE) gr = off + (lr - m0) + (m0);            // simplify below
            gr = MOE ? (off + lr) : lr;
            // NOTE: for MOE, lr is the LOCAL row within this expert (m0 + ... < cnt),
            // and output row is off + lr in the compacted buffer.
            #pragma unroll
            for (int nt = 0; nt < 4; nt++) {
                int cc = n0 + wn + nt*8 + 2*tg;
                float v0 = acc[mt][nt][2*h + 0] + bi[cc];
                float v1 = acc[mt][nt][2*h + 1] + bi[cc + 1];
                if (GELU) {
                    v0 = 0.5f*v0*(1.f + erff(v0*0.70710678118f));
                    v1 = 0.5f*v1*(1.f + erff(v1*0.70710678118f));
                }
                if (RES) {
                    v0 += res[(size_t)gr*N + cc];
                    v1 += res[(size_t)gr*N + cc + 1];
                }
                *(float2*)&C[(size_t)gr*N + cc] = make_float2(v0, v1);
            }
        }
    }
}

// ---------------------------------------------------------- flash attention
__global__ __launch_bounds__(64) void flash_attn_kernel(
    const float* __restrict__ qkv, const unsigned char* __restrict__ mask,
    float* __restrict__ ao)
{
    __shared__ __align__(16) float sm[6144];
    __shared__ unsigned char smask[32];
    float* Ks  = sm;
    float* Vs  = sm + 2048;
    float* Ssh = sm + 4096;

    int b = blockIdx.z, h = blockIdx.y, qt = blockIdx.x;
    int tid = threadIdx.x;
    int t0 = b*Ll + qt*64;

    for (int r = 0; r < 64; r++)
        sm[r*65 + tid] = qkv[(size_t)(t0+r)*QKV3 + h*DHd + tid];
    __syncthreads();
    float q[64];
    #pragma unroll
    for (int d = 0; d < 64; d++) q[d] = sm[tid*65 + d];
    __syncthreads();

    float o[64];
    #pragma unroll
    for (int d = 0; d < 64; d++) o[d] = 0.f;
    float m = -1e30f, l = 0.f;

    for (int u0 = 0; u0 < Ll; u0 += 32) {
        for (int i = 0; i < 32; i++) {
            size_t base = (size_t)(b*Ll + u0 + i)*QKV3 + h*DHd + tid;
            Ks[i*64 + tid] = qkv[base + Dm];
            Vs[i*64 + tid] = qkv[base + 2*Dm];
        }
        if (tid < 32) smask[tid] = mask[b*Ll + u0 + tid];
        __syncthreads();

        float tmax = -1e30f;
        for (int c = 0; c < 32; c++) {
            const float4* kp = (const float4*)&Ks[c*64];
            float acc = 0.f;
            #pragma unroll
            for (int dd = 0; dd < 16; dd++) {
                float4 kv = kp[dd];
                acc += q[4*dd+0]*kv.x + q[4*dd+1]*kv.y
                     + q[4*dd+2]*kv.z + q[4*dd+3]*kv.w;
            }
            float sv = smask[c] ? -1e9f : acc*0.125f;
            Ssh[c*64 + tid] = sv;
            tmax = fmaxf(tmax, sv);
        }
        float mn = fmaxf(m, tmax);
        float corr = __expf(m - mn);
        l *= corr;
        #pragma unroll
        for (int d = 0; d < 64; d++) o[d] *= corr;
        for (int c = 0; c < 32; c++) {
            float p = __expf(Ssh[c*64 + tid] - mn);
            l += p;
            const float4* vp = (const float4*)&Vs[c*64];
            #pragma unroll
            for (int dd = 0; dd < 16; dd++) {
                float4 vv = vp[dd];
                o[4*dd+0] += p*vv.x; o[4*dd+1] += p*vv.y;
                o[4*dd+2] += p*vv.z; o[4*dd+3] += p*vv.w;
            }
        }
        m = mn;
        __syncthreads();
    }
    float inv = 1.f / l;
    float* orow = ao + (size_t)(t0+tid)*Dm + h*DHd;
    #pragma unroll
    for (int dd = 0; dd < 16; dd++) {
        float4 v4 = make_float4(o[4*dd]*inv, o[4*dd+1]*inv, o[4*dd+2]*inv, o[4*dd+3]*inv);
        ((float4*)orow)[dd] = v4;
    }
}

// ------------------------------------------------------------------- gating
__global__ __launch_bounds__(128) void gate_kernel(
    const float* __restrict__ xn2, const float* __restrict__ Wg,
    const float* __restrict__ bg)
{
    int t = blockIdx.x, tid = threadIdx.x;
    const float* xr = xn2 + (size_t)t*Dm;
    float part[Ee] = {};
    for (int d = tid; d < Dm; d += 128) {
        float xv = xr[d];
        const float* wr = Wg + (size_t)d*Ee;
        #pragma unroll
        for (int e = 0; e < Ee; e++) part[e] += xv*wr[e];
    }
    __shared__ float red[128];
    __shared__ float logits[Ee];
    for (int e = 0; e < Ee; e++) {
        red[tid] = part[e]; __syncthreads();
        for (int st = 64; st > 0; st >>= 1) {
            if (tid < st) red[tid] += red[tid+st];
            __syncthreads();
        }
        if (tid == 0) logits[e] = red[0] + bg[e];
        __syncthreads();
    }
    if (tid == 0) {
        float mx = -1e30f;
        #pragma unroll
        for (int e = 0; e < Ee; e++) mx = fmaxf(mx, logits[e]);
        float p[Ee], se = 0.f;
        #pragma unroll
        for (int e = 0; e < Ee; e++) { p[e] = expf(logits[e]-mx); se += p[e]; }
        float isz = 1.f/se;
        #pragma unroll
        for (int e = 0; e < Ee; e++) { p[e] *= isz; g_probs[t*Ee+e] = p[e]; }
        int i0 = 0;
        #pragma unroll
        for (int e = 1; e < Ee; e++) if (p[e] > p[i0]) i0 = e;
        int i1 = (i0 == 0) ? 1 : 0;
        #pragma unroll
        for (int e = 0; e < Ee; e++) if (e != i0 && p[e] > p[i1]) i1 = e;
        float v0 = p[i0], v1 = p[i1], s01 = v0 + v1;
        g_idx[2*t]   = i0; g_idx[2*t+1] = i1;
        g_wts[2*t]   = v0/s01; g_wts[2*t+1] = v1/s01;
        atomicAdd(&g_counts[i0], 1);
        atomicAdd(&g_counts[i1], 1);
    }
}

__global__ void offsets_kernel() {
    if (threadIdx.x == 0) {
        int o = 0;
        for (int e = 0; e < Ee; e++) { g_offsets[e] = o; o += g_counts[e]; }
        g_offsets[Ee] = o;
    }
}

__global__ void scatter_kernel() {
    int a = blockIdx.x*blockDim.x + threadIdx.x;
    if (a < NASS) {
        int e = g_idx[a];
        int pos = g_offsets[e] + atomicAdd(&g_fill[e], 1);
        g_assign_row[pos] = a >> 1;
        g_pos_of[a] = pos;
    }
}

// ------------------------------------------------------ combine + moe loss
__global__ __launch_bounds__(256) void combine_kernel(float* __restrict__ out) {
    int t = blockIdx.x, tid = threadIdx.x;
    int p0 = g_pos_of[2*t], p1 = g_pos_of[2*t+1];
    float w0 = g_wts[2*t], w1 = g_wts[2*t+1];
    const float* e0 = g_eo + (size_t)p0*Dm;
    const float* e1 = g_eo + (size_t)p1*Dm;
    const float* xr = g_x1 + (size_t)t*Dm;
    float* orow = out + (size_t)t*Dm;
    for (int d = tid; d < Dm; d += 256)
        orow[d] = xr[d] + w0*e0[d] + w1*e1[d];
}

__global__ __launch_bounds__(256) void mece_kernel() {
    int e = blockIdx.x, tid = threadIdx.x;
    float s = 0.f, c = 0.f;
    for (int t = tid; t < Tt; t += 256) s += g_probs[t*Ee + e];
    for (int a = tid; a < NASS; a += 256) c += (g_idx[a] == e) ? 1.f : 0.f;
    __shared__ float sh1[256], sh2[256];
    sh1[tid] = s; sh2[tid] = c; __syncthreads();
    for (int st = 128; st > 0; st >>= 1) {
        if (tid < st) { sh1[tid] += sh1[tid+st]; sh2[tid] += sh2[tid+st]; }
        __syncthreads();
    }
    if (tid == 0) { g_me[e] = sh1[0]*(1.f/Tt); g_ce[e] = sh2[0]*(1.f/Tt); }
}

__global__ void loss_kernel(float* __restrict__ out, int out_size) {
    if (threadIdx.x == 0 && out_size > Tt*Dm) {
        float L = 0.f;
        for (int e = 0; e < Ee; e++) L += g_me[e]*g_ce[e];
        out[Tt*Dm] = (float)Ee * L;
    }
}

// ------------------------------------------------------------------ driver
extern "C" void kernel_launch(void* const* d_in, const int* in_sizes, int n_in,
                              void* d_out, int out_size)
{
    const float* x     = (const float*)d_in[0];
    const unsigned char* mask = (const unsigned char*)d_in[1];
    const float* ln1_g = (const float*)d_in[2];
    const float* ln1_b = (const float*)d_in[3];
    const float* Wqkv  = (const float*)d_in[4];
    const float* bqkv  = (const float*)d_in[5];
    const float* Wo    = (const float*)d_in[6];
    const float* bo    = (const float*)d_in[7];
    const float* ln2_g = (const float*)d_in[8];
    const float* ln2_b = (const float*)d_in[9];
    const float* Wg    = (const float*)d_in[10];
    const float* bg    = (const float*)d_in[11];
    const float* W1    = (const float*)d_in[12];
    const float* b1    = (const float*)d_in[13];
    const float* W2    = (const float*)d_in[14];
    const float* b2    = (const float*)d_in[15];
    float* out = (float*)d_out;

    float *xn1, *qkv, *ao, *x1, *xn2, *hbuf, *eobuf;
    cudaGetSymbolAddress((void**)&xn1,  g_xn1);
    cudaGetSymbolAddress((void**)&qkv,  g_qkv);
    cudaGetSymbolAddress((void**)&ao,   g_ao);
    cudaGetSymbolAddress((void**)&x1,   g_x1);
    cudaGetSymbolAddress((void**)&xn2,  g_xn2);
    cudaGetSymbolAddress((void**)&hbuf, g_h);
    cudaGetSymbolAddress((void**)&eobuf,g_eo);

    init_kernel<<<1, 32>>>();

    // LN1 -> QKV GEMM (tensor cores, tf32)
    ln_kernel<<<Tt, 256>>>(x, ln1_g, ln1_b, xn1);
    mma_gemm<0,0,0,0,0><<<dim3(QKV3/BN, Tt/BM), 256>>>(
        xn1, Wqkv, bqkv, nullptr, qkv, Tt, QKV3, Dm);

    // attention (fp32 flash)
    flash_attn_kernel<<<dim3(Ll/64, Hh, Bb), 64>>>(qkv, mask, ao);

    // output proj + residual
    mma_gemm<0,0,0,1,0><<<dim3(Dm/BN, Tt/BM), 256>>>(
        ao, Wo, bo, x, x1, Tt, Dm, Dm);

    // LN2 -> gate -> routing
    ln_kernel<<<Tt, 256>>>(x1, ln2_g, ln2_b, xn2);
    gate_kernel<<<Tt, 128>>>(xn2, Wg, bg);
    offsets_kernel<<<1, 32>>>();
    scatter_kernel<<<(NASS+255)/256, 256>>>();

    // sparse MoE (tensor cores): up-proj (gather + GELU, NN), down-proj (NN)
    mma_gemm<1,1,1,0,1><<<dim3(HIDm/BN, Tt/BM, Ee), 256>>>(
        xn2, W1, b1, nullptr, hbuf, Tt, HIDm, Dm);
    mma_gemm<0,1,0,0,1><<<dim3(Dm/BN, Tt/BM, Ee), 256>>>(
        hbuf, W2, b2, nullptr, eobuf, Tt, Dm, HIDm);

    // combine + aux loss
    combine_kernel<<<Tt, 256>>>(out);
    mece_kernel<<<Ee, 256>>>();
    loss_kernel<<<1, 32>>>(out, out_size);
}

// round 3
// speedup vs baseline: 4.1197x; 1.8078x over previous
#include <cuda_runtime.h>
#include <math.h>
#include <stdint.h>

// Problem constants
#define Dm    1024
#define Hh    16
#define DHd   64
#define Ee    8
#define HIDm  2048
#define TOPKk 2
#define Bb    2
#define Ll    2048
#define Tt    4096          // B*L
#define QKV3  3072
#define NASS  (Tt*TOPKk)

// ---------------- scratch (static device memory) ---------------------------
__device__ float g_xn1 [Tt*Dm];
__device__ float g_qkv [Tt*QKV3];
__device__ float g_ao  [Tt*Dm];
__device__ float g_x1  [Tt*Dm];
__device__ float g_xn2 [Tt*Dm];
__device__ float g_probs[Tt*Ee];
__device__ int   g_idx [NASS];
__device__ float g_wts [NASS];
__device__ int   g_counts[Ee];
__device__ int   g_offsets[Ee+1];
__device__ int   g_fill[Ee];
__device__ int   g_assign_row[NASS];
__device__ int   g_pos_of[NASS];
__device__ float g_h  [(size_t)NASS*HIDm];
__device__ float g_eo [(size_t)NASS*Dm];
__device__ float g_me [Ee];
__device__ float g_ce [Ee];

// ---------------------------------------------------------------- utilities
__global__ void init_kernel() {
    int i = threadIdx.x;
    if (i < Ee) { g_counts[i] = 0; g_fill[i] = 0; }
}

__global__ __launch_bounds__(256) void ln_kernel(
    const float* __restrict__ x, const float* __restrict__ g,
    const float* __restrict__ b, float* __restrict__ out)
{
    int t = blockIdx.x, tid = threadIdx.x;
    const float* xr = x + (size_t)t*Dm;
    float s = 0.f, s2 = 0.f;
    for (int d = tid; d < Dm; d += 256) { float v = xr[d]; s += v; s2 += v*v; }
    __shared__ float sh1[256], sh2[256];
    sh1[tid] = s; sh2[tid] = s2; __syncthreads();
    for (int st = 128; st > 0; st >>= 1) {
        if (tid < st) { sh1[tid] += sh1[tid+st]; sh2[tid] += sh2[tid+st]; }
        __syncthreads();
    }
    float mu  = sh1[0] * (1.f/Dm);
    float var = sh2[0] * (1.f/Dm) - mu*mu;
    float inv = rsqrtf(var + 1e-5f);
    float* orow = out + (size_t)t*Dm;
    for (int d = tid; d < Dm; d += 256)
        orow[d] = (xr[d]-mu)*inv*g[d] + b[d];
}

// ------------------------------------------------------ tf32 MMA primitives
__device__ __forceinline__ uint32_t f2tf(float x) {
    uint32_t y;
    asm("cvt.rna.tf32.f32 %0, %1;" : "=r"(y) : "f"(x));
    return y;
}
__device__ __forceinline__ void mma_tf32(float* c, const uint32_t* a, const uint32_t* b) {
    asm volatile(
        "mma.sync.aligned.m16n8k8.row.col.f32.tf32.tf32.f32 "
        "{%0,%1,%2,%3}, {%4,%5,%6,%7}, {%8,%9}, {%0,%1,%2,%3};"
        : "+f"(c[0]), "+f"(c[1]), "+f"(c[2]), "+f"(c[3])
        : "r"(a[0]), "r"(a[1]), "r"(a[2]), "r"(a[3]), "r"(b[0]), "r"(b[1]));
}

// ------------------------------------------ tensor-core GEMM (tf32 mma.sync)
#define BM 128
#define BN 128
#define BK 32
#define KST 36

template<int GATHER, int TRANSB, int GELU, int RES, int MOE>
__global__ __launch_bounds__(256) void mma_gemm(
    const float* __restrict__ A, const float* __restrict__ Bmat,
    const float* __restrict__ bias, const float* __restrict__ res,
    float* __restrict__ C, int M, int N, int K)
{
    __shared__ uint32_t As[BM*KST];
    __shared__ uint32_t Bs[BN*KST];
    __shared__ int rowsrc[BM];

    int e = MOE ? blockIdx.z : 0;
    int cnt = M, off = 0;
    if (MOE) {
        cnt = g_counts[e]; off = g_offsets[e];
        if ((int)blockIdx.y * BM >= cnt) return;
    }
    int m0 = blockIdx.y * BM;
    int n0 = blockIdx.x * BN;
    int tid = threadIdx.x;

    const float* Bbase = Bmat + (size_t)e * K * N;
    const float* bi    = bias + (size_t)e * N;

    if (tid < BM) {
        int lr = m0 + tid;
        int r;
        if (MOE) {
            int l = lr < cnt ? lr : cnt - 1;
            r = GATHER ? g_assign_row[off + l] : (off + l);
        } else r = lr;
        rowsrc[tid] = r;
    }
    __syncthreads();

    int lane = tid & 31;
    int wid  = tid >> 5;
    int wm = (wid >> 2) * 64;
    int wn = (wid & 3) * 32;
    int g  = lane >> 2;
    int tg = lane & 3;

    float acc[4][4][4];
    #pragma unroll
    for (int i = 0; i < 4; i++)
        #pragma unroll
        for (int j = 0; j < 4; j++)
            #pragma unroll
            for (int q = 0; q < 4; q++) acc[i][j][q] = 0.f;

    float4 pa[4], pb[4];

    auto loadA = [&](int k0) {
        #pragma unroll
        for (int p = 0; p < 4; p++) {
            int r = p*32 + (tid >> 3);
            int c = (tid & 7) * 4;
            pa[p] = *(const float4*)(A + (size_t)rowsrc[r]*K + k0 + c);
        }
    };
    auto loadB = [&](int k0) {
        if (!TRANSB) {
            #pragma unroll
            for (int p = 0; p < 4; p++) {
                int r = p*32 + (tid >> 3);
                int c = (tid & 7) * 4;
                pb[p] = *(const float4*)(Bbase + (size_t)(n0 + r)*K + k0 + c);
            }
        } else {
            #pragma unroll
            for (int p = 0; p < 4; p++) {
                int n  = tid & 127;
                int kg = p*2 + (tid >> 7);
                const float* s = Bbase + (size_t)(k0 + kg*4)*N + n0 + n;
                pb[p].x = s[0];
                pb[p].y = s[(size_t)N];
                pb[p].z = s[(size_t)2*N];
                pb[p].w = s[(size_t)3*N];
            }
        }
    };
    auto storeA = [&]() {
        #pragma unroll
        for (int p = 0; p < 4; p++) {
            int r = p*32 + (tid >> 3);
            int c = (tid & 7) * 4;
            uint4 u = make_uint4(f2tf(pa[p].x), f2tf(pa[p].y), f2tf(pa[p].z), f2tf(pa[p].w));
            *(uint4*)&As[r*KST + c] = u;
        }
    };
    auto storeB = [&]() {
        if (!TRANSB) {
            #pragma unroll
            for (int p = 0; p < 4; p++) {
                int r = p*32 + (tid >> 3);
                int c = (tid & 7) * 4;
                uint4 u = make_uint4(f2tf(pb[p].x), f2tf(pb[p].y), f2tf(pb[p].z), f2tf(pb[p].w));
                *(uint4*)&Bs[r*KST + c] = u;
            }
        } else {
            #pragma unroll
            for (int p = 0; p < 4; p++) {
                int n  = tid & 127;
                int kg = p*2 + (tid >> 7);
                uint4 u = make_uint4(f2tf(pb[p].x), f2tf(pb[p].y), f2tf(pb[p].z), f2tf(pb[p].w));
                *(uint4*)&Bs[n*KST + kg*4] = u;
            }
        }
    };
    auto compute = [&]() {
        #pragma unroll
        for (int ks = 0; ks < 4; ks++) {
            int k0 = ks * 8;
            uint32_t af[4][4];
            #pragma unroll
            for (int mt = 0; mt < 4; mt++) {
                int r = wm + mt*16 + g;
                af[mt][0] = As[r*KST + k0 + tg];
                af[mt][1] = As[(r+8)*KST + k0 + tg];
                af[mt][2] = As[r*KST + k0 + 4 + tg];
                af[mt][3] = As[(r+8)*KST + k0 + 4 + tg];
            }
            uint32_t bf[4][2];
            #pragma unroll
            for (int nt = 0; nt < 4; nt++) {
                int n = wn + nt*8 + g;
                bf[nt][0] = Bs[n*KST + k0 + tg];
                bf[nt][1] = Bs[n*KST + k0 + 4 + tg];
            }
            #pragma unroll
            for (int mt = 0; mt < 4; mt++)
                #pragma unroll
                for (int nt = 0; nt < 4; nt++)
                    mma_tf32(acc[mt][nt], af[mt], bf[nt]);
        }
    };

    int KT = K / BK;
    loadA(0); loadB(0);
    storeA(); storeB();
    __syncthreads();
    for (int t = 0; t < KT; t++) {
        if (t + 1 < KT) { loadA((t+1)*BK); loadB((t+1)*BK); }
        compute();
        __syncthreads();
        if (t + 1 < KT) {
            storeA(); storeB();
            __syncthreads();
        }
    }

    #pragma unroll
    for (int mt = 0; mt < 4; mt++) {
        #pragma unroll
        for (int h = 0; h < 2; h++) {
            int lr = m0 + wm + mt*16 + g + 8*h;   // local row (MOE) / global row
            if (MOE && lr >= cnt) continue;
            int gr = MOE ? (off + lr) : lr;
            #pragma unroll
            for (int nt = 0; nt < 4; nt++) {
                int cc = n0 + wn + nt*8 + 2*tg;
                float v0 = acc[mt][nt][2*h + 0] + bi[cc];
                float v1 = acc[mt][nt][2*h + 1] + bi[cc + 1];
                if (GELU) {
                    v0 = 0.5f*v0*(1.f + erff(v0*0.70710678118f));
                    v1 = 0.5f*v1*(1.f + erff(v1*0.70710678118f));
                }
                if (RES) {
                    v0 += res[(size_t)gr*N + cc];
                    v1 += res[(size_t)gr*N + cc + 1];
                }
                *(float2*)&C[(size_t)gr*N + cc] = make_float2(v0, v1);
            }
        }
    }
}

// ---------------------------- tensor-core flash attention (tf32 mma.sync) ---
// grid (L/128, H, B), 256 threads = 8 warps; each warp owns 16 Q rows.
// kv tiles of 64. Dynamic smem: Ks[64*68] Vs[64*68] Ps[128*68] (u32) + mask[64].
#define AST 68
#define ATT_SMEM ((2*64*AST + 128*AST)*4 + 64)

__global__ __launch_bounds__(256) void flash_attn_tc(
    const float* __restrict__ qkv, const unsigned char* __restrict__ mask,
    float* __restrict__ ao)
{
    extern __shared__ uint32_t dsm[];
    uint32_t* Ks = dsm;                 // [64][AST]
    uint32_t* Vs = dsm + 64*AST;        // [64][AST]
    uint32_t* Ps = dsm + 2*64*AST;      // [128][AST]  (Q stage, then P per warp)
    unsigned char* smask = (unsigned char*)(dsm + 2*64*AST + 128*AST);

    int b = blockIdx.z, h = blockIdx.y, qt = blockIdx.x;
    int tid = threadIdx.x;
    int lane = tid & 31, wid = tid >> 5;
    int g = lane >> 2, tg = lane & 3;
    int wm = wid * 16;
    int t0 = b*Ll + qt*128;

    // ---- stage Q tile (tf32) into Ps, then load persistent A-fragments
    #pragma unroll
    for (int p = 0; p < 8; p++) {
        int idx = p*256 + tid;
        int r = idx >> 4, c = (idx & 15) * 4;
        const float4 q4 = *(const float4*)&qkv[(size_t)(t0+r)*QKV3 + h*DHd + c];
        *(uint4*)&Ps[r*AST + c] = make_uint4(f2tf(q4.x), f2tf(q4.y), f2tf(q4.z), f2tf(q4.w));
    }
    __syncthreads();
    uint32_t qf[8][4];
    #pragma unroll
    for (int ks = 0; ks < 8; ks++) {
        int k0 = ks*8;
        qf[ks][0] = Ps[(wm+g)*AST + k0 + tg];
        qf[ks][1] = Ps[(wm+g+8)*AST + k0 + tg];
        qf[ks][2] = Ps[(wm+g)*AST + k0 + 4 + tg];
        qf[ks][3] = Ps[(wm+g+8)*AST + k0 + 4 + tg];
    }

    float oacc[8][4];
    #pragma unroll
    for (int nt = 0; nt < 8; nt++)
        #pragma unroll
        for (int q = 0; q < 4; q++) oacc[nt][q] = 0.f;
    float m0 = -1e30f, m1 = -1e30f, l0 = 0.f, l1 = 0.f;

    for (int u0 = 0; u0 < Ll; u0 += 64) {
        __syncthreads();   // protect Ks/Vs (and per-warp Ps already consumed)
        // stage K, V tiles (tf32)
        #pragma unroll
        for (int p = 0; p < 4; p++) {
            int idx = p*256 + tid;
            int r = idx >> 4, c = (idx & 15) * 4;
            size_t base = (size_t)(b*Ll + u0 + r)*QKV3 + h*DHd + c;
            const float4 k4 = *(const float4*)&qkv[base + Dm];
            const float4 v4 = *(const float4*)&qkv[base + 2*Dm];
            *(uint4*)&Ks[r*AST + c] = make_uint4(f2tf(k4.x), f2tf(k4.y), f2tf(k4.z), f2tf(k4.w));
            *(uint4*)&Vs[r*AST + c] = make_uint4(f2tf(v4.x), f2tf(v4.y), f2tf(v4.z), f2tf(v4.w));
        }
        if (tid < 64) smask[tid] = mask[b*Ll + u0 + tid];
        __syncthreads();

        // ---- S = Q K^T (warp: 16 x 64)
        float sacc[8][4];
        #pragma unroll
        for (int nt = 0; nt < 8; nt++)
            #pragma unroll
            for (int q = 0; q < 4; q++) sacc[nt][q] = 0.f;
        #pragma unroll
        for (int ks = 0; ks < 8; ks++) {
            int k0 = ks*8;
            #pragma unroll
            for (int nt = 0; nt < 8; nt++) {
                uint32_t bf[2];
                bf[0] = Ks[(nt*8+g)*AST + k0 + tg];
                bf[1] = Ks[(nt*8+g)*AST + k0 + 4 + tg];
                mma_tf32(sacc[nt], qf[ks], bf);
            }
        }

        // ---- online softmax on fragments
        float mx0 = -1e30f, mx1 = -1e30f;
        #pragma unroll
        for (int nt = 0; nt < 8; nt++) {
            #pragma unroll
            for (int j = 0; j < 2; j++) {
                int c = nt*8 + 2*tg + j;
                bool mk = smask[c] != 0;
                float s0 = mk ? -1e9f : sacc[nt][j]   * 0.125f;
                float s1 = mk ? -1e9f : sacc[nt][2+j] * 0.125f;
                sacc[nt][j] = s0; sacc[nt][2+j] = s1;
                mx0 = fmaxf(mx0, s0); mx1 = fmaxf(mx1, s1);
            }
        }
        mx0 = fmaxf(mx0, __shfl_xor_sync(0xffffffffu, mx0, 1));
        mx0 = fmaxf(mx0, __shfl_xor_sync(0xffffffffu, mx0, 2));
        mx1 = fmaxf(mx1, __shfl_xor_sync(0xffffffffu, mx1, 1));
        mx1 = fmaxf(mx1, __shfl_xor_sync(0xffffffffu, mx1, 2));
        float nm0 = fmaxf(m0, mx0), nm1 = fmaxf(m1, mx1);
        float corr0 = __expf(m0 - nm0), corr1 = __expf(m1 - nm1);
        m0 = nm0; m1 = nm1;
        float ls0 = 0.f, ls1 = 0.f;
        #pragma unroll
        for (int nt = 0; nt < 8; nt++) {
            float p00 = __expf(sacc[nt][0] - m0);
            float p01 = __expf(sacc[nt][1] - m0);
            float p10 = __expf(sacc[nt][2] - m1);
            float p11 = __expf(sacc[nt][3] - m1);
            ls0 += p00 + p01; ls1 += p10 + p11;
            *(uint2*)&Ps[(wm+g)*AST   + nt*8 + 2*tg] = make_uint2(f2tf(p00), f2tf(p01));
            *(uint2*)&Ps[(wm+g+8)*AST + nt*8 + 2*tg] = make_uint2(f2tf(p10), f2tf(p11));
        }
        ls0 += __shfl_xor_sync(0xffffffffu, ls0, 1);
        ls0 += __shfl_xor_sync(0xffffffffu, ls0, 2);
        ls1 += __shfl_xor_sync(0xffffffffu, ls1, 1);
        ls1 += __shfl_xor_sync(0xffffffffu, ls1, 2);
        l0 = l0*corr0 + ls0;
        l1 = l1*corr1 + ls1;
        #pragma unroll
        for (int nt = 0; nt < 8; nt++) {
            oacc[nt][0] *= corr0; oacc[nt][1] *= corr0;
            oacc[nt][2] *= corr1; oacc[nt][3] *= corr1;
        }
        __syncwarp();

        // ---- O += P V (warp reads only its own 16 P rows)
        #pragma unroll
        for (int ks = 0; ks < 8; ks++) {
            int k0 = ks*8;
            uint32_t af[4];
            af[0] = Ps[(wm+g)*AST + k0 + tg];
            af[1] = Ps[(wm+g+8)*AST + k0 + tg];
            af[2] = Ps[(wm+g)*AST + k0 + 4 + tg];
            af[3] = Ps[(wm+g+8)*AST + k0 + 4 + tg];
            #pragma unroll
            for (int nt = 0; nt < 8; nt++) {
                uint32_t bf[2];
                bf[0] = Vs[(k0+tg)*AST   + nt*8 + g];
                bf[1] = Vs[(k0+tg+4)*AST + nt*8 + g];
                mma_tf32(oacc[nt], af, bf);
            }
        }
    }

    float inv0 = 1.f / l0, inv1 = 1.f / l1;
    int r0 = t0 + wm + g, r1 = r0 + 8;
    #pragma unroll
    for (int nt = 0; nt < 8; nt++) {
        int c = nt*8 + 2*tg;
        *(float2*)&ao[(size_t)r0*Dm + h*DHd + c] =
            make_float2(oacc[nt][0]*inv0, oacc[nt][1]*inv0);
        *(float2*)&ao[(size_t)r1*Dm + h*DHd + c] =
            make_float2(oacc[nt][2]*inv1, oacc[nt][3]*inv1);
    }
}

// ------------------------------------------------------------------- gating
__global__ __launch_bounds__(128) void gate_kernel(
    const float* __restrict__ xn2, const float* __restrict__ Wg,
    const float* __restrict__ bg)
{
    int t = blockIdx.x, tid = threadIdx.x;
    const float* xr = xn2 + (size_t)t*Dm;
    float part[Ee] = {};
    for (int d = tid; d < Dm; d += 128) {
        float xv = xr[d];
        const float* wr = Wg + (size_t)d*Ee;
        #pragma unroll
        for (int e = 0; e < Ee; e++) part[e] += xv*wr[e];
    }
    __shared__ float red[128];
    __shared__ float logits[Ee];
    for (int e = 0; e < Ee; e++) {
        red[tid] = part[e]; __syncthreads();
        for (int st = 64; st > 0; st >>= 1) {
            if (tid < st) red[tid] += red[tid+st];
            __syncthreads();
        }
        if (tid == 0) logits[e] = red[0] + bg[e];
        __syncthreads();
    }
    if (tid == 0) {
        float mx = -1e30f;
        #pragma unroll
        for (int e = 0; e < Ee; e++) mx = fmaxf(mx, logits[e]);
        float p[Ee], se = 0.f;
        #pragma unroll
        for (int e = 0; e < Ee; e++) { p[e] = expf(logits[e]-mx); se += p[e]; }
        float isz = 1.f/se;
        #pragma unroll
        for (int e = 0; e < Ee; e++) { p[e] *= isz; g_probs[t*Ee+e] = p[e]; }
        int i0 = 0;
        #pragma unroll
        for (int e = 1; e < Ee; e++) if (p[e] > p[i0]) i0 = e;
        int i1 = (i0 == 0) ? 1 : 0;
        #pragma unroll
        for (int e = 0; e < Ee; e++) if (e != i0 && p[e] > p[i1]) i1 = e;
        float v0 = p[i0], v1 = p[i1], s01 = v0 + v1;
        g_idx[2*t]   = i0; g_idx[2*t+1] = i1;
        g_wts[2*t]   = v0/s01; g_wts[2*t+1] = v1/s01;
        atomicAdd(&g_counts[i0], 1);
        atomicAdd(&g_counts[i1], 1);
    }
}

__global__ void offsets_kernel() {
    if (threadIdx.x == 0) {
        int o = 0;
        for (int e = 0; e < Ee; e++) { g_offsets[e] = o; o += g_counts[e]; }
        g_offsets[Ee] = o;
    }
}

__global__ void scatter_kernel() {
    int a = blockIdx.x*blockDim.x + threadIdx.x;
    if (a < NASS) {
        int e = g_idx[a];
        int pos = g_offsets[e] + atomicAdd(&g_fill[e], 1);
        g_assign_row[pos] = a >> 1;
        g_pos_of[a] = pos;
    }
}

// ------------------------------------------------------ combine + moe loss
__global__ __launch_bounds__(256) void combine_kernel(float* __restrict__ out) {
    int t = blockIdx.x, tid = threadIdx.x;
    int p0 = g_pos_of[2*t], p1 = g_pos_of[2*t+1];
    float w0 = g_wts[2*t], w1 = g_wts[2*t+1];
    const float* e0 = g_eo + (size_t)p0*Dm;
    const float* e1 = g_eo + (size_t)p1*Dm;
    const float* xr = g_x1 + (size_t)t*Dm;
    float* orow = out + (size_t)t*Dm;
    for (int d = tid; d < Dm; d += 256)
        orow[d] = xr[d] + w0*e0[d] + w1*e1[d];
}

__global__ __launch_bounds__(256) void mece_kernel() {
    int e = blockIdx.x, tid = threadIdx.x;
    float s = 0.f, c = 0.f;
    for (int t = tid; t < Tt; t += 256) s += g_probs[t*Ee + e];
    for (int a = tid; a < NASS; a += 256) c += (g_idx[a] == e) ? 1.f : 0.f;
    __shared__ float sh1[256], sh2[256];
    sh1[tid] = s; sh2[tid] = c; __syncthreads();
    for (int st = 128; st > 0; st >>= 1) {
        if (tid < st) { sh1[tid] += sh1[tid+st]; sh2[tid] += sh2[tid+st]; }
        __syncthreads();
    }
    if (tid == 0) { g_me[e] = sh1[0]*(1.f/Tt); g_ce[e] = sh2[0]*(1.f/Tt); }
}

__global__ void loss_kernel(float* __restrict__ out, int out_size) {
    if (threadIdx.x == 0 && out_size > Tt*Dm) {
        float L = 0.f;
        for (int e = 0; e < Ee; e++) L += g_me[e]*g_ce[e];
        out[Tt*Dm] = (float)Ee * L;
    }
}

// ------------------------------------------------------------------ driver
extern "C" void kernel_launch(void* const* d_in, const int* in_sizes, int n_in,
                              void* d_out, int out_size)
{
    const float* x     = (const float*)d_in[0];
    const unsigned char* mask = (const unsigned char*)d_in[1];
    const float* ln1_g = (const float*)d_in[2];
    const float* ln1_b = (const float*)d_in[3];
    const float* Wqkv  = (const float*)d_in[4];
    const float* bqkv  = (const float*)d_in[5];
    const float* Wo    = (const float*)d_in[6];
    const float* bo    = (const float*)d_in[7];
    const float* ln2_g = (const float*)d_in[8];
    const float* ln2_b = (const float*)d_in[9];
    const float* Wg    = (const float*)d_in[10];
    const float* bg    = (const float*)d_in[11];
    const float* W1    = (const float*)d_in[12];
    const float* b1    = (const float*)d_in[13];
    const float* W2    = (const float*)d_in[14];
    const float* b2    = (const float*)d_in[15];
    float* out = (float*)d_out;

    float *xn1, *qkv, *ao, *x1, *xn2, *hbuf, *eobuf;
    cudaGetSymbolAddress((void**)&xn1,  g_xn1);
    cudaGetSymbolAddress((void**)&qkv,  g_qkv);
    cudaGetSymbolAddress((void**)&ao,   g_ao);
    cudaGetSymbolAddress((void**)&x1,   g_x1);
    cudaGetSymbolAddress((void**)&xn2,  g_xn2);
    cudaGetSymbolAddress((void**)&hbuf, g_h);
    cudaGetSymbolAddress((void**)&eobuf,g_eo);

    static bool attr_set = false;
    if (!attr_set) {
        cudaFuncSetAttribute(flash_attn_tc,
                             cudaFuncAttributeMaxDynamicSharedMemorySize, ATT_SMEM);
        attr_set = true;
    }

    init_kernel<<<1, 32>>>();

    // LN1 -> QKV GEMM (tf32 tensor cores)
    ln_kernel<<<Tt, 256>>>(x, ln1_g, ln1_b, xn1);
    mma_gemm<0,0,0,0,0><<<dim3(QKV3/BN, Tt/BM), 256>>>(
        xn1, Wqkv, bqkv, nullptr, qkv, Tt, QKV3, Dm);

    // attention (tf32 tensor-core flash)
    flash_attn_tc<<<dim3(Ll/128, Hh, Bb), 256, ATT_SMEM>>>(qkv, mask, ao);

    // output proj + residual
    mma_gemm<0,0,0,1,0><<<dim3(Dm/BN, Tt/BM), 256>>>(
        ao, Wo, bo, x, x1, Tt, Dm, Dm);

    // LN2 -> gate -> routing
    ln_kernel<<<Tt, 256>>>(x1, ln2_g, ln2_b, xn2);
    gate_kernel<<<Tt, 128>>>(xn2, Wg, bg);
    offsets_kernel<<<1, 32>>>();
    scatter_kernel<<<(NASS+255)/256, 256>>>();

    // sparse MoE (tf32): up-proj (gather + GELU, NN), down-proj (NN)
    mma_gemm<1,1,1,0,1><<<dim3(HIDm/BN, Tt/BM, Ee), 256>>>(
        xn2, W1, b1, nullptr, hbuf, Tt, HIDm, Dm);
    mma_gemm<0,1,0,0,1><<<dim3(Dm/BN, Tt/BM, Ee), 256>>>(
        hbuf, W2, b2, nullptr, eobuf, Tt, Dm, HIDm);

    // combine + aux loss
    combine_kernel<<<Tt, 256>>>(out);
    mece_kernel<<<Ee, 256>>>();
    loss_kernel<<<1, 32>>>(out, out_size);
}

// round 4
// speedup vs baseline: 5.8422x; 1.4181x over previous
#include <cuda_runtime.h>
#include <cuda_bf16.h>
#include <math.h>
#include <stdint.h>

// Problem constants
#define Dm    1024
#define Hh    16
#define DHd   64
#define Ee    8
#define HIDm  2048
#define TOPKk 2
#define Bb    2
#define Ll    2048
#define Tt    4096          // B*L
#define QKV3  3072
#define NASS  (Tt*TOPKk)

// ---------------- scratch (static device memory) ---------------------------
__device__ float g_xn1 [Tt*Dm];
__device__ float g_qkv [Tt*QKV3];
__device__ float g_ao  [Tt*Dm];
__device__ float g_x1  [Tt*Dm];
__device__ float g_xn2 [Tt*Dm];
__device__ float g_probs[Tt*Ee];
__device__ int   g_idx [NASS];
__device__ float g_wts [NASS];
__device__ int   g_counts[Ee];
__device__ int   g_offsets[Ee+1];
__device__ int   g_fill[Ee];
__device__ int   g_assign_row[NASS];
__device__ int   g_pos_of[NASS];
__device__ float g_h  [(size_t)NASS*HIDm];
__device__ float g_eo [(size_t)NASS*Dm];
__device__ float g_me [Ee];
__device__ float g_ce [Ee];

// ---------------------------------------------------------------- utilities
__global__ void init_kernel() {
    int i = threadIdx.x;
    if (i < Ee) { g_counts[i] = 0; g_fill[i] = 0; }
}

__global__ __launch_bounds__(256) void ln_kernel(
    const float* __restrict__ x, const float* __restrict__ g,
    const float* __restrict__ b, float* __restrict__ out)
{
    int t = blockIdx.x, tid = threadIdx.x;
    const float* xr = x + (size_t)t*Dm;
    float s = 0.f, s2 = 0.f;
    for (int d = tid; d < Dm; d += 256) { float v = xr[d]; s += v; s2 += v*v; }
    __shared__ float sh1[256], sh2[256];
    sh1[tid] = s; sh2[tid] = s2; __syncthreads();
    for (int st = 128; st > 0; st >>= 1) {
        if (tid < st) { sh1[tid] += sh1[tid+st]; sh2[tid] += sh2[tid+st]; }
        __syncthreads();
    }
    float mu  = sh1[0] * (1.f/Dm);
    float var = sh2[0] * (1.f/Dm) - mu*mu;
    float inv = rsqrtf(var + 1e-5f);
    float* orow = out + (size_t)t*Dm;
    for (int d = tid; d < Dm; d += 256)
        orow[d] = (xr[d]-mu)*inv*g[d] + b[d];
}

// ---------------------------------------------------- MMA / ldmatrix helpers
__device__ __forceinline__ uint32_t f2tf(float x) {
    uint32_t y;
    asm("cvt.rna.tf32.f32 %0, %1;" : "=r"(y) : "f"(x));
    return y;
}
__device__ __forceinline__ void mma_tf32(float* c, const uint32_t* a, const uint32_t* b) {
    asm volatile(
        "mma.sync.aligned.m16n8k8.row.col.f32.tf32.tf32.f32 "
        "{%0,%1,%2,%3}, {%4,%5,%6,%7}, {%8,%9}, {%0,%1,%2,%3};"
        : "+f"(c[0]), "+f"(c[1]), "+f"(c[2]), "+f"(c[3])
        : "r"(a[0]), "r"(a[1]), "r"(a[2]), "r"(a[3]), "r"(b[0]), "r"(b[1]));
}
__device__ __forceinline__ uint32_t packbf2(float a, float b) {
    __nv_bfloat162 h = __floats2bfloat162_rn(a, b);
    return *reinterpret_cast<uint32_t*>(&h);
}
__device__ __forceinline__ void mma_bf16(float* c, const uint32_t* a, const uint32_t* b) {
    asm volatile(
        "mma.sync.aligned.m16n8k16.row.col.f32.bf16.bf16.f32 "
        "{%0,%1,%2,%3}, {%4,%5,%6,%7}, {%8,%9}, {%0,%1,%2,%3};"
        : "+f"(c[0]), "+f"(c[1]), "+f"(c[2]), "+f"(c[3])
        : "r"(a[0]), "r"(a[1]), "r"(a[2]), "r"(a[3]), "r"(b[0]), "r"(b[1]));
}
__device__ __forceinline__ void ldm_x4(uint32_t* r, uint32_t addr) {
    asm volatile("ldmatrix.sync.aligned.m8n8.x4.shared.b16 {%0,%1,%2,%3}, [%4];"
        : "=r"(r[0]), "=r"(r[1]), "=r"(r[2]), "=r"(r[3]) : "r"(addr));
}

// ----------------------------------- tensor-core GEMM (bf16 m16n8k16 + ldmatrix)
// CTA 128x128x32, 256 threads = 8 warps (2x4), warp tile 64x32.
#define BM 128
#define BN 128
#define BK 32
#define ASTW 20   // smem row stride in 32-bit words (= 40 bf16; ldmatrix conflict-free)

template<int GATHER, int TRANSB, int GELU, int RES, int MOE>
__global__ __launch_bounds__(256) void mma_gemm_bf16(
    const float* __restrict__ A, const float* __restrict__ Bmat,
    const float* __restrict__ bias, const float* __restrict__ res,
    float* __restrict__ C, int M, int N, int K)
{
    __shared__ uint32_t As[BM*ASTW];
    __shared__ uint32_t Bs[BN*ASTW];
    __shared__ int rowsrc[BM];

    int e = MOE ? blockIdx.z : 0;
    int cnt = M, off = 0;
    if (MOE) {
        cnt = g_counts[e]; off = g_offsets[e];
        if ((int)blockIdx.y * BM >= cnt) return;
    }
    int m0 = blockIdx.y * BM;
    int n0 = blockIdx.x * BN;
    int tid = threadIdx.x;

    const float* Bbase = Bmat + (size_t)e * K * N;
    const float* bi    = bias + (size_t)e * N;

    if (tid < BM) {
        int lr = m0 + tid;
        int r;
        if (MOE) {
            int l = lr < cnt ? lr : cnt - 1;
            r = GATHER ? g_assign_row[off + l] : (off + l);
        } else r = lr;
        rowsrc[tid] = r;
    }
    __syncthreads();

    int lane = tid & 31;
    int wid  = tid >> 5;
    int wm = (wid >> 2) * 64;
    int wn = (wid & 3) * 32;
    int g  = lane >> 2;
    int tg = lane & 3;

    uint32_t as_base = (uint32_t)__cvta_generic_to_shared(As);
    uint32_t bs_base = (uint32_t)__cvta_generic_to_shared(Bs);
    // per-lane ldmatrix address components
    int a_row = (lane & 7) + ((lane >> 3) & 1) * 8;   // row within 16-block
    int a_colw = (lane >> 4) * 4;                     // k colblock in words
    int b_nt_sub = (lane >> 4) & 1;                   // which nt of the pair
    int b_row = (lane & 7);
    int b_colw = ((lane >> 3) & 1) * 4;

    float acc[4][4][4];
    #pragma unroll
    for (int i = 0; i < 4; i++)
        #pragma unroll
        for (int j = 0; j < 4; j++)
            #pragma unroll
            for (int q = 0; q < 4; q++) acc[i][j][q] = 0.f;

    float4 pa[4], pb[4];

    auto loadA = [&](int k0) {
        #pragma unroll
        for (int p = 0; p < 4; p++) {
            int r = p*32 + (tid >> 3);
            int c = (tid & 7) * 4;
            pa[p] = *(const float4*)(A + (size_t)rowsrc[r]*K + k0 + c);
        }
    };
    auto loadB = [&](int k0) {
        if (!TRANSB) {
            #pragma unroll
            for (int p = 0; p < 4; p++) {
                int r = p*32 + (tid >> 3);
                int c = (tid & 7) * 4;
                pb[p] = *(const float4*)(Bbase + (size_t)(n0 + r)*K + k0 + c);
            }
        } else {
            #pragma unroll
            for (int p = 0; p < 4; p++) {
                int n  = tid & 127;
                int kg = p*2 + (tid >> 7);
                const float* s = Bbase + (size_t)(k0 + kg*4)*N + n0 + n;
                pb[p].x = s[0];
                pb[p].y = s[(size_t)N];
                pb[p].z = s[(size_t)2*N];
                pb[p].w = s[(size_t)3*N];
            }
        }
    };
    auto storeA = [&]() {
        #pragma unroll
        for (int p = 0; p < 4; p++) {
            int r = p*32 + (tid >> 3);
            int cw = (tid & 7) * 2;   // word offset = c/2
            *(uint2*)&As[r*ASTW + cw] =
                make_uint2(packbf2(pa[p].x, pa[p].y), packbf2(pa[p].z, pa[p].w));
        }
    };
    auto storeB = [&]() {
        if (!TRANSB) {
            #pragma unroll
            for (int p = 0; p < 4; p++) {
                int r = p*32 + (tid >> 3);
                int cw = (tid & 7) * 2;
                *(uint2*)&Bs[r*ASTW + cw] =
                    make_uint2(packbf2(pb[p].x, pb[p].y), packbf2(pb[p].z, pb[p].w));
            }
        } else {
            #pragma unroll
            for (int p = 0; p < 4; p++) {
                int n  = tid & 127;
                int kg = p*2 + (tid >> 7);
                *(uint2*)&Bs[n*ASTW + kg*2] =
                    make_uint2(packbf2(pb[p].x, pb[p].y), packbf2(pb[p].z, pb[p].w));
            }
        }
    };
    auto compute = [&]() {
        #pragma unroll
        for (int ks = 0; ks < 2; ks++) {          // two k16 steps per BK=32
            int k0w = ks * 8;                     // k offset in words
            uint32_t af[4][4];
            #pragma unroll
            for (int mt = 0; mt < 4; mt++) {
                uint32_t addr = as_base +
                    ((wm + mt*16 + a_row)*ASTW + k0w + a_colw) * 4u;
                ldm_x4(af[mt], addr);
            }
            uint32_t bf[2][4];
            #pragma unroll
            for (int ntp = 0; ntp < 2; ntp++) {
                int nrow = wn + (2*ntp + b_nt_sub)*8 + b_row;
                uint32_t addr = bs_base + ((nrow)*ASTW + k0w + b_colw) * 4u;
                ldm_x4(bf[ntp], addr);
            }
            #pragma unroll
            for (int mt = 0; mt < 4; mt++) {
                #pragma unroll
                for (int nt = 0; nt < 4; nt++) {
                    const uint32_t* bb = &bf[nt >> 1][(nt & 1) * 2];
                    mma_bf16(acc[mt][nt], af[mt], bb);
                }
            }
        }
    };

    int KT = K / BK;
    loadA(0); loadB(0);
    storeA(); storeB();
    __syncthreads();
    for (int t = 0; t < KT; t++) {
        if (t + 1 < KT) { loadA((t+1)*BK); loadB((t+1)*BK); }
        compute();
        __syncthreads();
        if (t + 1 < KT) {
            storeA(); storeB();
            __syncthreads();
        }
    }

    #pragma unroll
    for (int mt = 0; mt < 4; mt++) {
        #pragma unroll
        for (int h = 0; h < 2; h++) {
            int lr = m0 + wm + mt*16 + g + 8*h;
            if (MOE && lr >= cnt) continue;
            int gr = MOE ? (off + lr) : lr;
            #pragma unroll
            for (int nt = 0; nt < 4; nt++) {
                int cc = n0 + wn + nt*8 + 2*tg;
                float v0 = acc[mt][nt][2*h + 0] + bi[cc];
                float v1 = acc[mt][nt][2*h + 1] + bi[cc + 1];
                if (GELU) {
                    v0 = 0.5f*v0*(1.f + erff(v0*0.70710678118f));
                    v1 = 0.5f*v1*(1.f + erff(v1*0.70710678118f));
                }
                if (RES) {
                    v0 += res[(size_t)gr*N + cc];
                    v1 += res[(size_t)gr*N + cc + 1];
                }
                *(float2*)&C[(size_t)gr*N + cc] = make_float2(v0, v1);
            }
        }
    }
}

// ---------------------------- tensor-core flash attention (tf32 mma.sync) ---
// grid (L/128, H, B), 256 threads = 8 warps; each warp owns 16 Q rows.
#define AST 68
#define VST 72   // V stride: 72 mod 32 = 8 -> PV B-fragment loads conflict-free
#define ATT_SMEM ((64*AST + 64*VST + 128*AST)*4 + 64)

__global__ __launch_bounds__(256) void flash_attn_tc(
    const float* __restrict__ qkv, const unsigned char* __restrict__ mask,
    float* __restrict__ ao)
{
    extern __shared__ uint32_t dsm[];
    uint32_t* Ks = dsm;                       // [64][AST]
    uint32_t* Vs = dsm + 64*AST;              // [64][VST]
    uint32_t* Ps = dsm + 64*AST + 64*VST;     // [128][AST]
    unsigned char* smask = (unsigned char*)(dsm + 64*AST + 64*VST + 128*AST);

    int b = blockIdx.z, h = blockIdx.y, qt = blockIdx.x;
    int tid = threadIdx.x;
    int lane = tid & 31, wid = tid >> 5;
    int g = lane >> 2, tg = lane & 3;
    int wm = wid * 16;
    int t0 = b*Ll + qt*128;

    #pragma unroll
    for (int p = 0; p < 8; p++) {
        int idx = p*256 + tid;
        int r = idx >> 4, c = (idx & 15) * 4;
        const float4 q4 = *(const float4*)&qkv[(size_t)(t0+r)*QKV3 + h*DHd + c];
        *(uint4*)&Ps[r*AST + c] = make_uint4(f2tf(q4.x), f2tf(q4.y), f2tf(q4.z), f2tf(q4.w));
    }
    __syncthreads();
    uint32_t qf[8][4];
    #pragma unroll
    for (int ks = 0; ks < 8; ks++) {
        int k0 = ks*8;
        qf[ks][0] = Ps[(wm+g)*AST + k0 + tg];
        qf[ks][1] = Ps[(wm+g+8)*AST + k0 + tg];
        qf[ks][2] = Ps[(wm+g)*AST + k0 + 4 + tg];
        qf[ks][3] = Ps[(wm+g+8)*AST + k0 + 4 + tg];
    }

    float oacc[8][4];
    #pragma unroll
    for (int nt = 0; nt < 8; nt++)
        #pragma unroll
        for (int q = 0; q < 4; q++) oacc[nt][q] = 0.f;
    float m0 = -1e30f, m1 = -1e30f, l0 = 0.f, l1 = 0.f;

    for (int u0 = 0; u0 < Ll; u0 += 64) {
        __syncthreads();
        #pragma unroll
        for (int p = 0; p < 4; p++) {
            int idx = p*256 + tid;
            int r = idx >> 4, c = (idx & 15) * 4;
            size_t base = (size_t)(b*Ll + u0 + r)*QKV3 + h*DHd + c;
            const float4 k4 = *(const float4*)&qkv[base + Dm];
            const float4 v4 = *(const float4*)&qkv[base + 2*Dm];
            *(uint4*)&Ks[r*AST + c] = make_uint4(f2tf(k4.x), f2tf(k4.y), f2tf(k4.z), f2tf(k4.w));
            *(uint4*)&Vs[r*VST + c] = make_uint4(f2tf(v4.x), f2tf(v4.y), f2tf(v4.z), f2tf(v4.w));
        }
        if (tid < 64) smask[tid] = mask[b*Ll + u0 + tid];
        __syncthreads();

        float sacc[8][4];
        #pragma unroll
        for (int nt = 0; nt < 8; nt++)
            #pragma unroll
            for (int q = 0; q < 4; q++) sacc[nt][q] = 0.f;
        #pragma unroll
        for (int ks = 0; ks < 8; ks++) {
            int k0 = ks*8;
            #pragma unroll
            for (int nt = 0; nt < 8; nt++) {
                uint32_t bf[2];
                bf[0] = Ks[(nt*8+g)*AST + k0 + tg];
                bf[1] = Ks[(nt*8+g)*AST + k0 + 4 + tg];
                mma_tf32(sacc[nt], qf[ks], bf);
            }
        }

        float mx0 = -1e30f, mx1 = -1e30f;
        #pragma unroll
        for (int nt = 0; nt < 8; nt++) {
            #pragma unroll
            for (int j = 0; j < 2; j++) {
                int c = nt*8 + 2*tg + j;
                bool mk = smask[c] != 0;
                float s0 = mk ? -1e9f : sacc[nt][j]   * 0.125f;
                float s1 = mk ? -1e9f : sacc[nt][2+j] * 0.125f;
                sacc[nt][j] = s0; sacc[nt][2+j] = s1;
                mx0 = fmaxf(mx0, s0); mx1 = fmaxf(mx1, s1);
            }
        }
        mx0 = fmaxf(mx0, __shfl_xor_sync(0xffffffffu, mx0, 1));
        mx0 = fmaxf(mx0, __shfl_xor_sync(0xffffffffu, mx0, 2));
        mx1 = fmaxf(mx1, __shfl_xor_sync(0xffffffffu, mx1, 1));
        mx1 = fmaxf(mx1, __shfl_xor_sync(0xffffffffu, mx1, 2));
        float nm0 = fmaxf(m0, mx0), nm1 = fmaxf(m1, mx1);
        float corr0 = __expf(m0 - nm0), corr1 = __expf(m1 - nm1);
        m0 = nm0; m1 = nm1;
        float ls0 = 0.f, ls1 = 0.f;
        #pragma unroll
        for (int nt = 0; nt < 8; nt++) {
            float p00 = __expf(sacc[nt][0] - m0);
            float p01 = __expf(sacc[nt][1] - m0);
            float p10 = __expf(sacc[nt][2] - m1);
            float p11 = __expf(sacc[nt][3] - m1);
            ls0 += p00 + p01; ls1 += p10 + p11;
            *(uint2*)&Ps[(wm+g)*AST   + nt*8 + 2*tg] = make_uint2(f2tf(p00), f2tf(p01));
            *(uint2*)&Ps[(wm+g+8)*AST + nt*8 + 2*tg] = make_uint2(f2tf(p10), f2tf(p11));
        }
        ls0 += __shfl_xor_sync(0xffffffffu, ls0, 1);
        ls0 += __shfl_xor_sync(0xffffffffu, ls0, 2);
        ls1 += __shfl_xor_sync(0xffffffffu, ls1, 1);
        ls1 += __shfl_xor_sync(0xffffffffu, ls1, 2);
        l0 = l0*corr0 + ls0;
        l1 = l1*corr1 + ls1;
        #pragma unroll
        for (int nt = 0; nt < 8; nt++) {
            oacc[nt][0] *= corr0; oacc[nt][1] *= corr0;
            oacc[nt][2] *= corr1; oacc[nt][3] *= corr1;
        }
        __syncwarp();

        #pragma unroll
        for (int ks = 0; ks < 8; ks++) {
            int k0 = ks*8;
            uint32_t af[4];
            af[0] = Ps[(wm+g)*AST + k0 + tg];
            af[1] = Ps[(wm+g+8)*AST + k0 + tg];
            af[2] = Ps[(wm+g)*AST + k0 + 4 + tg];
            af[3] = Ps[(wm+g+8)*AST + k0 + 4 + tg];
            #pragma unroll
            for (int nt = 0; nt < 8; nt++) {
                uint32_t bf[2];
                bf[0] = Vs[(k0+tg)*VST   + nt*8 + g];
                bf[1] = Vs[(k0+tg+4)*VST + nt*8 + g];
                mma_tf32(oacc[nt], af, bf);
            }
        }
    }

    float inv0 = 1.f / l0, inv1 = 1.f / l1;
    int r0 = t0 + wm + g, r1 = r0 + 8;
    #pragma unroll
    for (int nt = 0; nt < 8; nt++) {
        int c = nt*8 + 2*tg;
        *(float2*)&ao[(size_t)r0*Dm + h*DHd + c] =
            make_float2(oacc[nt][0]*inv0, oacc[nt][1]*inv0);
        *(float2*)&ao[(size_t)r1*Dm + h*DHd + c] =
            make_float2(oacc[nt][2]*inv1, oacc[nt][3]*inv1);
    }
}

// ------------------------------------------------------------------- gating
__global__ __launch_bounds__(128) void gate_kernel(
    const float* __restrict__ xn2, const float* __restrict__ Wg,
    const float* __restrict__ bg)
{
    int t = blockIdx.x, tid = threadIdx.x;
    const float* xr = xn2 + (size_t)t*Dm;
    float part[Ee] = {};
    for (int d = tid; d < Dm; d += 128) {
        float xv = xr[d];
        const float* wr = Wg + (size_t)d*Ee;
        #pragma unroll
        for (int e = 0; e < Ee; e++) part[e] += xv*wr[e];
    }
    __shared__ float red[128];
    __shared__ float logits[Ee];
    for (int e = 0; e < Ee; e++) {
        red[tid] = part[e]; __syncthreads();
        for (int st = 64; st > 0; st >>= 1) {
            if (tid < st) red[tid] += red[tid+st];
            __syncthreads();
        }
        if (tid == 0) logits[e] = red[0] + bg[e];
        __syncthreads();
    }
    if (tid == 0) {
        float mx = -1e30f;
        #pragma unroll
        for (int e = 0; e < Ee; e++) mx = fmaxf(mx, logits[e]);
        float p[Ee], se = 0.f;
        #pragma unroll
        for (int e = 0; e < Ee; e++) { p[e] = expf(logits[e]-mx); se += p[e]; }
        float isz = 1.f/se;
        #pragma unroll
        for (int e = 0; e < Ee; e++) { p[e] *= isz; g_probs[t*Ee+e] = p[e]; }
        int i0 = 0;
        #pragma unroll
        for (int e = 1; e < Ee; e++) if (p[e] > p[i0]) i0 = e;
        int i1 = (i0 == 0) ? 1 : 0;
        #pragma unroll
        for (int e = 0; e < Ee; e++) if (e != i0 && p[e] > p[i1]) i1 = e;
        float v0 = p[i0], v1 = p[i1], s01 = v0 + v1;
        g_idx[2*t]   = i0; g_idx[2*t+1] = i1;
        g_wts[2*t]   = v0/s01; g_wts[2*t+1] = v1/s01;
        atomicAdd(&g_counts[i0], 1);
        atomicAdd(&g_counts[i1], 1);
    }
}

__global__ void offsets_kernel() {
    if (threadIdx.x == 0) {
        int o = 0;
        for (int e = 0; e < Ee; e++) { g_offsets[e] = o; o += g_counts[e]; }
        g_offsets[Ee] = o;
    }
}

__global__ void scatter_kernel() {
    int a = blockIdx.x*blockDim.x + threadIdx.x;
    if (a < NASS) {
        int e = g_idx[a];
        int pos = g_offsets[e] + atomicAdd(&g_fill[e], 1);
        g_assign_row[pos] = a >> 1;
        g_pos_of[a] = pos;
    }
}

// ------------------------------------------------------ combine + moe loss
__global__ __launch_bounds__(256) void combine_kernel(float* __restrict__ out) {
    int t = blockIdx.x, tid = threadIdx.x;
    int p0 = g_pos_of[2*t], p1 = g_pos_of[2*t+1];
    float w0 = g_wts[2*t], w1 = g_wts[2*t+1];
    const float* e0 = g_eo + (size_t)p0*Dm;
    const float* e1 = g_eo + (size_t)p1*Dm;
    const float* xr = g_x1 + (size_t)t*Dm;
    float* orow = out + (size_t)t*Dm;
    for (int d = tid; d < Dm; d += 256)
        orow[d] = xr[d] + w0*e0[d] + w1*e1[d];
}

__global__ __launch_bounds__(256) void mece_kernel() {
    int e = blockIdx.x, tid = threadIdx.x;
    float s = 0.f, c = 0.f;
    for (int t = tid; t < Tt; t += 256) s += g_probs[t*Ee + e];
    for (int a = tid; a < NASS; a += 256) c += (g_idx[a] == e) ? 1.f : 0.f;
    __shared__ float sh1[256], sh2[256];
    sh1[tid] = s; sh2[tid] = c; __syncthreads();
    for (int st = 128; st > 0; st >>= 1) {
        if (tid < st) { sh1[tid] += sh1[tid+st]; sh2[tid] += sh2[tid+st]; }
        __syncthreads();
    }
    if (tid == 0) { g_me[e] = sh1[0]*(1.f/Tt); g_ce[e] = sh2[0]*(1.f/Tt); }
}

__global__ void loss_kernel(float* __restrict__ out, int out_size) {
    if (threadIdx.x == 0 && out_size > Tt*Dm) {
        float L = 0.f;
        for (int e = 0; e < Ee; e++) L += g_me[e]*g_ce[e];
        out[Tt*Dm] = (float)Ee * L;
    }
}

// ------------------------------------------------------------------ driver
extern "C" void kernel_launch(void* const* d_in, const int* in_sizes, int n_in,
                              void* d_out, int out_size)
{
    const float* x     = (const float*)d_in[0];
    const unsigned char* mask = (const unsigned char*)d_in[1];
    const float* ln1_g = (const float*)d_in[2];
    const float* ln1_b = (const float*)d_in[3];
    const float* Wqkv  = (const float*)d_in[4];
    const float* bqkv  = (const float*)d_in[5];
    const float* Wo    = (const float*)d_in[6];
    const float* bo    = (const float*)d_in[7];
    const float* ln2_g = (const float*)d_in[8];
    const float* ln2_b = (const float*)d_in[9];
    const float* Wg    = (const float*)d_in[10];
    const float* bg    = (const float*)d_in[11];
    const float* W1    = (const float*)d_in[12];
    const float* b1    = (const float*)d_in[13];
    const float* W2    = (const float*)d_in[14];
    const float* b2    = (const float*)d_in[15];
    float* out = (float*)d_out;

    float *xn1, *qkv, *ao, *x1, *xn2, *hbuf, *eobuf;
    cudaGetSymbolAddress((void**)&xn1,  g_xn1);
    cudaGetSymbolAddress((void**)&qkv,  g_qkv);
    cudaGetSymbolAddress((void**)&ao,   g_ao);
    cudaGetSymbolAddress((void**)&x1,   g_x1);
    cudaGetSymbolAddress((void**)&xn2,  g_xn2);
    cudaGetSymbolAddress((void**)&hbuf, g_h);
    cudaGetSymbolAddress((void**)&eobuf,g_eo);

    static bool attr_set = false;
    if (!attr_set) {
        cudaFuncSetAttribute(flash_attn_tc,
                             cudaFuncAttributeMaxDynamicSharedMemorySize, ATT_SMEM);
        attr_set = true;
    }

    init_kernel<<<1, 32>>>();

    // LN1 -> QKV GEMM (bf16 tensor cores)
    ln_kernel<<<Tt, 256>>>(x, ln1_g, ln1_b, xn1);
    mma_gemm_bf16<0,0,0,0,0><<<dim3(QKV3/BN, Tt/BM), 256>>>(
        xn1, Wqkv, bqkv, nullptr, qkv, Tt, QKV3, Dm);

    // attention (tf32 tensor-core flash)
    flash_attn_tc<<<dim3(Ll/128, Hh, Bb), 256, ATT_SMEM>>>(qkv, mask, ao);

    // output proj + residual
    mma_gemm_bf16<0,0,0,1,0><<<dim3(Dm/BN, Tt/BM), 256>>>(
        ao, Wo, bo, x, x1, Tt, Dm, Dm);

    // LN2 -> gate -> routing
    ln_kernel<<<Tt, 256>>>(x1, ln2_g, ln2_b, xn2);
    gate_kernel<<<Tt, 128>>>(xn2, Wg, bg);
    offsets_kernel<<<1, 32>>>();
    scatter_kernel<<<(NASS+255)/256, 256>>>();

    // sparse MoE (bf16): up-proj (gather + GELU, NN), down-proj (NN)
    mma_gemm_bf16<1,1,1,0,1><<<dim3(HIDm/BN, Tt/BM, Ee), 256>>>(
        xn2, W1, b1, nullptr, hbuf, Tt, HIDm, Dm);
    mma_gemm_bf16<0,1,0,0,1><<<dim3(Dm/BN, Tt/BM, Ee), 256>>>(
        hbuf, W2, b2, nullptr, eobuf, Tt, Dm, HIDm);

    // combine + aux loss
    combine_kernel<<<Tt, 256>>>(out);
    mece_kernel<<<Ee, 256>>>();
    loss_kernel<<<1, 32>>>(out, out_size);
}

// round 5
// speedup vs baseline: 6.4316x; 1.1009x over previous
#include <cuda_runtime.h>
#include <cuda_bf16.h>
#include <math.h>
#include <stdint.h>

// Problem constants
#define Dm    1024
#define Hh    16
#define DHd   64
#define Ee    8
#define HIDm  2048
#define TOPKk 2
#define Bb    2
#define Ll    2048
#define Tt    4096          // B*L
#define QKV3  3072
#define NASS  (Tt*TOPKk)

// ---------------- scratch (static device memory) ---------------------------
__device__ float g_xn1 [Tt*Dm];
__device__ float g_qkv [Tt*QKV3];
__device__ float g_ao  [Tt*Dm];
__device__ float g_x1  [Tt*Dm];
__device__ float g_xn2 [Tt*Dm];
__device__ float g_probs[Tt*Ee];
__device__ int   g_idx [NASS];
__device__ float g_wts [NASS];
__device__ int   g_counts[Ee];
__device__ int   g_offsets[Ee+1];
__device__ int   g_fill[Ee];
__device__ int   g_assign_row[NASS];
__device__ int   g_pos_of[NASS];
__device__ float g_h  [(size_t)NASS*HIDm];
__device__ float g_eo [(size_t)NASS*Dm];
__device__ float g_me [Ee];
__device__ float g_ce [Ee];

// ---------------------------------------------------------------- utilities
__global__ void init_kernel() {
    int i = threadIdx.x;
    if (i < Ee) { g_counts[i] = 0; g_fill[i] = 0; }
}

__global__ __launch_bounds__(256) void ln_kernel(
    const float* __restrict__ x, const float* __restrict__ g,
    const float* __restrict__ b, float* __restrict__ out)
{
    int t = blockIdx.x, tid = threadIdx.x;
    const float* xr = x + (size_t)t*Dm;
    float s = 0.f, s2 = 0.f;
    for (int d = tid; d < Dm; d += 256) { float v = xr[d]; s += v; s2 += v*v; }
    __shared__ float sh1[256], sh2[256];
    sh1[tid] = s; sh2[tid] = s2; __syncthreads();
    for (int st = 128; st > 0; st >>= 1) {
        if (tid < st) { sh1[tid] += sh1[tid+st]; sh2[tid] += sh2[tid+st]; }
        __syncthreads();
    }
    float mu  = sh1[0] * (1.f/Dm);
    float var = sh2[0] * (1.f/Dm) - mu*mu;
    float inv = rsqrtf(var + 1e-5f);
    float* orow = out + (size_t)t*Dm;
    for (int d = tid; d < Dm; d += 256)
        orow[d] = (xr[d]-mu)*inv*g[d] + b[d];
}

// ---------------------------------------------------- MMA / async primitives
__device__ __forceinline__ void mma_tf32(float* c, const uint32_t* a, const uint32_t* b) {
    asm volatile(
        "mma.sync.aligned.m16n8k8.row.col.f32.tf32.tf32.f32 "
        "{%0,%1,%2,%3}, {%4,%5,%6,%7}, {%8,%9}, {%0,%1,%2,%3};"
        : "+f"(c[0]), "+f"(c[1]), "+f"(c[2]), "+f"(c[3])
        : "r"(a[0]), "r"(a[1]), "r"(a[2]), "r"(a[3]), "r"(b[0]), "r"(b[1]));
}
__device__ __forceinline__ uint32_t packbf2(float a, float b) {
    __nv_bfloat162 h = __floats2bfloat162_rn(a, b);
    return *reinterpret_cast<uint32_t*>(&h);
}
__device__ __forceinline__ void mma_bf16(float* c, const uint32_t* a, const uint32_t* b) {
    asm volatile(
        "mma.sync.aligned.m16n8k16.row.col.f32.bf16.bf16.f32 "
        "{%0,%1,%2,%3}, {%4,%5,%6,%7}, {%8,%9}, {%0,%1,%2,%3};"
        : "+f"(c[0]), "+f"(c[1]), "+f"(c[2]), "+f"(c[3])
        : "r"(a[0]), "r"(a[1]), "r"(a[2]), "r"(a[3]), "r"(b[0]), "r"(b[1]));
}
__device__ __forceinline__ void ldm_x4(uint32_t* r, uint32_t addr) {
    asm volatile("ldmatrix.sync.aligned.m8n8.x4.shared.b16 {%0,%1,%2,%3}, [%4];"
        : "=r"(r[0]), "=r"(r[1]), "=r"(r[2]), "=r"(r[3]) : "r"(addr));
}
__device__ __forceinline__ void cpasync16(uint32_t dst, const void* src) {
    asm volatile("cp.async.cg.shared.global [%0], [%1], 16;" :: "r"(dst), "l"(src));
}
__device__ __forceinline__ void cpcommit() {
    asm volatile("cp.async.commit_group;");
}
template<int N> __device__ __forceinline__ void cpwait() {
    asm volatile("cp.async.wait_group %0;" :: "n"(N));
}

// ----------------------------------- tensor-core GEMM (bf16 m16n8k16 + ldmatrix)
// CTA 128x128x32, 256 threads = 8 warps (2x4), warp tile 64x32. 2-stage smem.
#define BM 128
#define BN 128
#define BK 32
#define ASTW 20   // smem row stride in 32-bit words (= 40 bf16; ldmatrix conflict-free)

template<int GATHER, int TRANSB, int GELU, int RES, int MOE>
__global__ __launch_bounds__(256) void mma_gemm_bf16(
    const float* __restrict__ A, const float* __restrict__ Bmat,
    const float* __restrict__ bias, const float* __restrict__ res,
    float* __restrict__ C, int M, int N, int K)
{
    __shared__ uint32_t As[2*BM*ASTW];
    __shared__ uint32_t Bs[2*BN*ASTW];
    __shared__ int rowsrc[BM];

    int e = MOE ? blockIdx.z : 0;
    int cnt = M, off = 0;
    if (MOE) {
        cnt = g_counts[e]; off = g_offsets[e];
        if ((int)blockIdx.y * BM >= cnt) return;
    }
    int m0 = blockIdx.y * BM;
    int n0 = blockIdx.x * BN;
    int tid = threadIdx.x;

    const float* Bbase = Bmat + (size_t)e * K * N;
    const float* bi    = bias + (size_t)e * N;

    if (tid < BM) {
        int lr = m0 + tid;
        int r;
        if (MOE) {
            int l = lr < cnt ? lr : cnt - 1;
            r = GATHER ? g_assign_row[off + l] : (off + l);
        } else r = lr;
        rowsrc[tid] = r;
    }
    __syncthreads();

    int lane = tid & 31;
    int wid  = tid >> 5;
    int wm = (wid >> 2) * 64;
    int wn = (wid & 3) * 32;
    int g  = lane >> 2;
    int tg = lane & 3;

    uint32_t as_base = (uint32_t)__cvta_generic_to_shared(As);
    uint32_t bs_base = (uint32_t)__cvta_generic_to_shared(Bs);
    int a_row = (lane & 7) + ((lane >> 3) & 1) * 8;
    int a_colw = (lane >> 4) * 4;
    int b_nt_sub = (lane >> 4) & 1;
    int b_row = (lane & 7);
    int b_colw = ((lane >> 3) & 1) * 4;

    float acc[4][4][4];
    #pragma unroll
    for (int i = 0; i < 4; i++)
        #pragma unroll
        for (int j = 0; j < 4; j++)
            #pragma unroll
            for (int q = 0; q < 4; q++) acc[i][j][q] = 0.f;

    float4 pa[4], pb[4];

    auto loadA = [&](int k0) {
        #pragma unroll
        for (int p = 0; p < 4; p++) {
            int r = p*32 + (tid >> 3);
            int c = (tid & 7) * 4;
            pa[p] = *(const float4*)(A + (size_t)rowsrc[r]*K + k0 + c);
        }
    };
    auto loadB = [&](int k0) {
        if (!TRANSB) {
            #pragma unroll
            for (int p = 0; p < 4; p++) {
                int r = p*32 + (tid >> 3);
                int c = (tid & 7) * 4;
                pb[p] = *(const float4*)(Bbase + (size_t)(n0 + r)*K + k0 + c);
            }
        } else {
            #pragma unroll
            for (int p = 0; p < 4; p++) {
                int n  = tid & 127;
                int kg = p*2 + (tid >> 7);
                const float* s = Bbase + (size_t)(k0 + kg*4)*N + n0 + n;
                pb[p].x = s[0];
                pb[p].y = s[(size_t)N];
                pb[p].z = s[(size_t)2*N];
                pb[p].w = s[(size_t)3*N];
            }
        }
    };
    auto storeA = [&](int s) {
        #pragma unroll
        for (int p = 0; p < 4; p++) {
            int r = p*32 + (tid >> 3);
            int cw = (tid & 7) * 2;
            *(uint2*)&As[(s*BM + r)*ASTW + cw] =
                make_uint2(packbf2(pa[p].x, pa[p].y), packbf2(pa[p].z, pa[p].w));
        }
    };
    auto storeB = [&](int s) {
        if (!TRANSB) {
            #pragma unroll
            for (int p = 0; p < 4; p++) {
                int r = p*32 + (tid >> 3);
                int cw = (tid & 7) * 2;
                *(uint2*)&Bs[(s*BN + r)*ASTW + cw] =
                    make_uint2(packbf2(pb[p].x, pb[p].y), packbf2(pb[p].z, pb[p].w));
            }
        } else {
            #pragma unroll
            for (int p = 0; p < 4; p++) {
                int n  = tid & 127;
                int kg = p*2 + (tid >> 7);
                *(uint2*)&Bs[(s*BN + n)*ASTW + kg*2] =
                    make_uint2(packbf2(pb[p].x, pb[p].y), packbf2(pb[p].z, pb[p].w));
            }
        }
    };
    auto compute = [&](int s) {
        #pragma unroll
        for (int ks = 0; ks < 2; ks++) {
            int k0w = ks * 8;
            uint32_t af[4][4];
            #pragma unroll
            for (int mt = 0; mt < 4; mt++) {
                uint32_t addr = as_base +
                    ((s*BM + wm + mt*16 + a_row)*ASTW + k0w + a_colw) * 4u;
                ldm_x4(af[mt], addr);
            }
            uint32_t bf[2][4];
            #pragma unroll
            for (int ntp = 0; ntp < 2; ntp++) {
                int nrow = wn + (2*ntp + b_nt_sub)*8 + b_row;
                uint32_t addr = bs_base + ((s*BN + nrow)*ASTW + k0w + b_colw) * 4u;
                ldm_x4(bf[ntp], addr);
            }
            #pragma unroll
            for (int mt = 0; mt < 4; mt++) {
                #pragma unroll
                for (int nt = 0; nt < 4; nt++) {
                    const uint32_t* bb = &bf[nt >> 1][(nt & 1) * 2];
                    mma_bf16(acc[mt][nt], af[mt], bb);
                }
            }
        }
    };

    int KT = K / BK;
    loadA(0); loadB(0);
    storeA(0); storeB(0);
    if (KT > 1) { loadA(BK); loadB(BK); }
    __syncthreads();
    for (int t = 0; t < KT; t++) {
        compute(t & 1);
        if (t + 1 < KT) { storeA((t+1) & 1); storeB((t+1) & 1); }
        if (t + 2 < KT) { loadA((t+2)*BK); loadB((t+2)*BK); }
        __syncthreads();
    }

    #pragma unroll
    for (int mt = 0; mt < 4; mt++) {
        #pragma unroll
        for (int h = 0; h < 2; h++) {
            int lr = m0 + wm + mt*16 + g + 8*h;
            if (MOE && lr >= cnt) continue;
            int gr = MOE ? (off + lr) : lr;
            #pragma unroll
            for (int nt = 0; nt < 4; nt++) {
                int cc = n0 + wn + nt*8 + 2*tg;
                float v0 = acc[mt][nt][2*h + 0] + bi[cc];
                float v1 = acc[mt][nt][2*h + 1] + bi[cc + 1];
                if (GELU) {
                    v0 = 0.5f*v0*(1.f + erff(v0*0.70710678118f));
                    v1 = 0.5f*v1*(1.f + erff(v1*0.70710678118f));
                }
                if (RES) {
                    v0 += res[(size_t)gr*N + cc];
                    v1 += res[(size_t)gr*N + cc + 1];
                }
                *(float2*)&C[(size_t)gr*N + cc] = make_float2(v0, v1);
            }
        }
    }
}

// -------------- tensor-core flash attention (tf32, cp.async double-buffer) --
// grid (L/64, H, B), 128 threads = 4 warps; each warp owns 16 Q rows.
// fp32 bits fed directly as tf32 operands (HW ignores low 13 mantissa bits).
#define AST 68
#define VST 72
#define NTILES (Ll/64)
#define ATT_SMEM ((2*64*AST + 2*64*VST + 64*AST)*4 + 160)

__global__ __launch_bounds__(128) void flash_attn_tc(
    const float* __restrict__ qkv, const unsigned char* __restrict__ mask,
    float* __restrict__ ao)
{
    extern __shared__ uint32_t dsm[];
    uint32_t* Ks = dsm;                        // [2][64][AST]
    uint32_t* Vs = dsm + 2*64*AST;             // [2][64][VST]
    uint32_t* Ps = dsm + 2*64*AST + 2*64*VST;  // [64][AST] (Q stage, then P)
    unsigned char* smask = (unsigned char*)(Ps + 64*AST);  // [2][64]

    int b = blockIdx.z, h = blockIdx.y, qt = blockIdx.x;
    int tid = threadIdx.x;
    int lane = tid & 31, wid = tid >> 5;
    int g = lane >> 2, tg = lane & 3;
    int wm = wid * 16;
    int t0 = b*Ll + qt*64;

    uint32_t sbase = (uint32_t)__cvta_generic_to_shared(dsm);
    uint32_t ks_b = sbase;
    uint32_t vs_b = sbase + 2*64*AST*4;
    uint32_t ps_b = sbase + (2*64*AST + 2*64*VST)*4;
    uint32_t mk_b = ps_b + 64*AST*4;

    // stage Q via cp.async (group 0)
    #pragma unroll
    for (int p = 0; p < 8; p++) {
        int idx = p*128 + tid;
        int r = idx >> 4, c = (idx & 15) * 4;
        cpasync16(ps_b + (r*AST + c)*4u, &qkv[(size_t)(t0+r)*QKV3 + h*DHd + c]);
    }
    cpcommit();

    auto stageKV = [&](int u, int s) {
        int base_t = b*Ll + u*64;
        #pragma unroll
        for (int p = 0; p < 8; p++) {
            int idx = p*128 + tid;
            int r = idx >> 4, c = (idx & 15) * 4;
            size_t gb = (size_t)(base_t + r)*QKV3 + h*DHd + c;
            cpasync16(ks_b + (((s*64) + r)*AST + c)*4u, &qkv[gb + Dm]);
            cpasync16(vs_b + (((s*64) + r)*VST + c)*4u, &qkv[gb + 2*Dm]);
        }
        if (tid < 4)
            cpasync16(mk_b + (uint32_t)(s*64 + tid*16), &mask[base_t + tid*16]);
        cpcommit();
    };
    stageKV(0, 0);
    stageKV(1, 1);

    // Q fragments (needs group 0 complete; KV0/KV1 may still be in flight)
    cpwait<2>();
    __syncthreads();
    uint32_t qf[8][4];
    #pragma unroll
    for (int ks = 0; ks < 8; ks++) {
        int k0 = ks*8;
        qf[ks][0] = Ps[(wm+g)*AST + k0 + tg];
        qf[ks][1] = Ps[(wm+g+8)*AST + k0 + tg];
        qf[ks][2] = Ps[(wm+g)*AST + k0 + 4 + tg];
        qf[ks][3] = Ps[(wm+g+8)*AST + k0 + 4 + tg];
    }

    float oacc[8][4];
    #pragma unroll
    for (int nt = 0; nt < 8; nt++)
        #pragma unroll
        for (int q = 0; q < 4; q++) oacc[nt][q] = 0.f;
    float m0 = -1e30f, m1 = -1e30f, l0 = 0.f, l1 = 0.f;

    for (int u = 0; u < NTILES; u++) {
        int s = u & 1;
        cpwait<1>();        // KV(u) complete; KV(u+1) may pend
        __syncthreads();

        // ---- S = Q K^T
        float sacc[8][4];
        #pragma unroll
        for (int nt = 0; nt < 8; nt++)
            #pragma unroll
            for (int q = 0; q < 4; q++) sacc[nt][q] = 0.f;
        #pragma unroll
        for (int ks = 0; ks < 8; ks++) {
            int k0 = ks*8;
            #pragma unroll
            for (int nt = 0; nt < 8; nt++) {
                uint32_t bf[2];
                bf[0] = Ks[(s*64 + nt*8+g)*AST + k0 + tg];
                bf[1] = Ks[(s*64 + nt*8+g)*AST + k0 + 4 + tg];
                mma_tf32(sacc[nt], qf[ks], bf);
            }
        }

        // ---- online softmax
        float mx0 = -1e30f, mx1 = -1e30f;
        #pragma unroll
        for (int nt = 0; nt < 8; nt++) {
            #pragma unroll
            for (int j = 0; j < 2; j++) {
                int c = nt*8 + 2*tg + j;
                bool mk = smask[s*64 + c] != 0;
                float s0 = mk ? -1e9f : sacc[nt][j]   * 0.125f;
                float s1 = mk ? -1e9f : sacc[nt][2+j] * 0.125f;
                sacc[nt][j] = s0; sacc[nt][2+j] = s1;
                mx0 = fmaxf(mx0, s0); mx1 = fmaxf(mx1, s1);
            }
        }
        mx0 = fmaxf(mx0, __shfl_xor_sync(0xffffffffu, mx0, 1));
        mx0 = fmaxf(mx0, __shfl_xor_sync(0xffffffffu, mx0, 2));
        mx1 = fmaxf(mx1, __shfl_xor_sync(0xffffffffu, mx1, 1));
        mx1 = fmaxf(mx1, __shfl_xor_sync(0xffffffffu, mx1, 2));
        float nm0 = fmaxf(m0, mx0), nm1 = fmaxf(m1, mx1);
        float corr0 = __expf(m0 - nm0), corr1 = __expf(m1 - nm1);
        m0 = nm0; m1 = nm1;
        float ls0 = 0.f, ls1 = 0.f;
        #pragma unroll
        for (int nt = 0; nt < 8; nt++) {
            float p00 = __expf(sacc[nt][0] - m0);
            float p01 = __expf(sacc[nt][1] - m0);
            float p10 = __expf(sacc[nt][2] - m1);
            float p11 = __expf(sacc[nt][3] - m1);
            ls0 += p00 + p01; ls1 += p10 + p11;
            *(uint2*)&Ps[(wm+g)*AST   + nt*8 + 2*tg] =
                make_uint2(__float_as_uint(p00), __float_as_uint(p01));
            *(uint2*)&Ps[(wm+g+8)*AST + nt*8 + 2*tg] =
                make_uint2(__float_as_uint(p10), __float_as_uint(p11));
        }
        ls0 += __shfl_xor_sync(0xffffffffu, ls0, 1);
        ls0 += __shfl_xor_sync(0xffffffffu, ls0, 2);
        ls1 += __shfl_xor_sync(0xffffffffu, ls1, 1);
        ls1 += __shfl_xor_sync(0xffffffffu, ls1, 2);
        l0 = l0*corr0 + ls0;
        l1 = l1*corr1 + ls1;
        #pragma unroll
        for (int nt = 0; nt < 8; nt++) {
            oacc[nt][0] *= corr0; oacc[nt][1] *= corr0;
            oacc[nt][2] *= corr1; oacc[nt][3] *= corr1;
        }
        __syncwarp();

        // ---- O += P V
        #pragma unroll
        for (int ks = 0; ks < 8; ks++) {
            int k0 = ks*8;
            uint32_t af[4];
            af[0] = Ps[(wm+g)*AST + k0 + tg];
            af[1] = Ps[(wm+g+8)*AST + k0 + tg];
            af[2] = Ps[(wm+g)*AST + k0 + 4 + tg];
            af[3] = Ps[(wm+g+8)*AST + k0 + 4 + tg];
            #pragma unroll
            for (int nt = 0; nt < 8; nt++) {
                uint32_t bf[2];
                bf[0] = Vs[(s*64 + k0+tg)*VST   + nt*8 + g];
                bf[1] = Vs[(s*64 + k0+tg+4)*VST + nt*8 + g];
                mma_tf32(oacc[nt], af, bf);
            }
        }
        __syncthreads();                       // all warps done with stage s
        if (u + 2 < NTILES) stageKV(u + 2, s); // refill freed stage
    }

    float inv0 = 1.f / l0, inv1 = 1.f / l1;
    int r0 = t0 + wm + g, r1 = r0 + 8;
    #pragma unroll
    for (int nt = 0; nt < 8; nt++) {
        int c = nt*8 + 2*tg;
        *(float2*)&ao[(size_t)r0*Dm + h*DHd + c] =
            make_float2(oacc[nt][0]*inv0, oacc[nt][1]*inv0);
        *(float2*)&ao[(size_t)r1*Dm + h*DHd + c] =
            make_float2(oacc[nt][2]*inv1, oacc[nt][3]*inv1);
    }
}

// ------------------------------------------------------------------- gating
// warp per token; 8 tokens per block.
__global__ __launch_bounds__(256) void gate_kernel(
    const float* __restrict__ xn2, const float* __restrict__ Wg,
    const float* __restrict__ bg)
{
    int t = blockIdx.x*8 + (threadIdx.x >> 5);
    int lane = threadIdx.x & 31;
    const float* xr = xn2 + (size_t)t*Dm;
    float part[Ee] = {};
    for (int d = lane; d < Dm; d += 32) {
        float xv = xr[d];
        const float4* wr = (const float4*)(Wg + (size_t)d*Ee);
        float4 w0 = wr[0], w1 = wr[1];
        part[0] += xv*w0.x; part[1] += xv*w0.y;
        part[2] += xv*w0.z; part[3] += xv*w0.w;
        part[4] += xv*w1.x; part[5] += xv*w1.y;
        part[6] += xv*w1.z; part[7] += xv*w1.w;
    }
    #pragma unroll
    for (int e = 0; e < Ee; e++) {
        part[e] += __shfl_xor_sync(0xffffffffu, part[e], 16);
        part[e] += __shfl_xor_sync(0xffffffffu, part[e], 8);
        part[e] += __shfl_xor_sync(0xffffffffu, part[e], 4);
        part[e] += __shfl_xor_sync(0xffffffffu, part[e], 2);
        part[e] += __shfl_xor_sync(0xffffffffu, part[e], 1);
    }
    if (lane == 0) {
        float logits[Ee];
        #pragma unroll
        for (int e = 0; e < Ee; e++) logits[e] = part[e] + bg[e];
        float mx = -1e30f;
        #pragma unroll
        for (int e = 0; e < Ee; e++) mx = fmaxf(mx, logits[e]);
        float p[Ee], se = 0.f;
        #pragma unroll
        for (int e = 0; e < Ee; e++) { p[e] = expf(logits[e]-mx); se += p[e]; }
        float isz = 1.f/se;
        #pragma unroll
        for (int e = 0; e < Ee; e++) { p[e] *= isz; g_probs[t*Ee+e] = p[e]; }
        int i0 = 0;
        #pragma unroll
        for (int e = 1; e < Ee; e++) if (p[e] > p[i0]) i0 = e;
        int i1 = (i0 == 0) ? 1 : 0;
        #pragma unroll
        for (int e = 0; e < Ee; e++) if (e != i0 && p[e] > p[i1]) i1 = e;
        float v0 = p[i0], v1 = p[i1], s01 = v0 + v1;
        g_idx[2*t]   = i0; g_idx[2*t+1] = i1;
        g_wts[2*t]   = v0/s01; g_wts[2*t+1] = v1/s01;
        atomicAdd(&g_counts[i0], 1);
        atomicAdd(&g_counts[i1], 1);
    }
}

__global__ void offsets_kernel() {
    if (threadIdx.x == 0) {
        int o = 0;
        for (int e = 0; e < Ee; e++) { g_offsets[e] = o; o += g_counts[e]; }
        g_offsets[Ee] = o;
    }
}

__global__ void scatter_kernel() {
    int a = blockIdx.x*blockDim.x + threadIdx.x;
    if (a < NASS) {
        int e = g_idx[a];
        int pos = g_offsets[e] + atomicAdd(&g_fill[e], 1);
        g_assign_row[pos] = a >> 1;
        g_pos_of[a] = pos;
    }
}

// ------------------------------------------------------ combine + moe loss
__global__ __launch_bounds__(256) void combine_kernel(float* __restrict__ out) {
    int t = blockIdx.x, tid = threadIdx.x;
    int p0 = g_pos_of[2*t], p1 = g_pos_of[2*t+1];
    float w0 = g_wts[2*t], w1 = g_wts[2*t+1];
    const float* e0 = g_eo + (size_t)p0*Dm;
    const float* e1 = g_eo + (size_t)p1*Dm;
    const float* xr = g_x1 + (size_t)t*Dm;
    float* orow = out + (size_t)t*Dm;
    for (int d = tid; d < Dm; d += 256)
        orow[d] = xr[d] + w0*e0[d] + w1*e1[d];
}

__global__ __launch_bounds__(256) void mece_kernel() {
    int e = blockIdx.x, tid = threadIdx.x;
    float s = 0.f, c = 0.f;
    for (int t = tid; t < Tt; t += 256) s += g_probs[t*Ee + e];
    for (int a = tid; a < NASS; a += 256) c += (g_idx[a] == e) ? 1.f : 0.f;
    __shared__ float sh1[256], sh2[256];
    sh1[tid] = s; sh2[tid] = c; __syncthreads();
    for (int st = 128; st > 0; st >>= 1) {
        if (tid < st) { sh1[tid] += sh1[tid+st]; sh2[tid] += sh2[tid+st]; }
        __syncthreads();
    }
    if (tid == 0) { g_me[e] = sh1[0]*(1.f/Tt); g_ce[e] = sh2[0]*(1.f/Tt); }
}

__global__ void loss_kernel(float* __restrict__ out, int out_size) {
    if (threadIdx.x == 0 && out_size > Tt*Dm) {
        float L = 0.f;
        for (int e = 0; e < Ee; e++) L += g_me[e]*g_ce[e];
        out[Tt*Dm] = (float)Ee * L;
    }
}

// ------------------------------------------------------------------ driver
extern "C" void kernel_launch(void* const* d_in, const int* in_sizes, int n_in,
                              void* d_out, int out_size)
{
    const float* x     = (const float*)d_in[0];
    const unsigned char* mask = (const unsigned char*)d_in[1];
    const float* ln1_g = (const float*)d_in[2];
    const float* ln1_b = (const float*)d_in[3];
    const float* Wqkv  = (const float*)d_in[4];
    const float* bqkv  = (const float*)d_in[5];
    const float* Wo    = (const float*)d_in[6];
    const float* bo    = (const float*)d_in[7];
    const float* ln2_g = (const float*)d_in[8];
    const float* ln2_b = (const float*)d_in[9];
    const float* Wg    = (const float*)d_in[10];
    const float* bg    = (const float*)d_in[11];
    const float* W1    = (const float*)d_in[12];
    const float* b1    = (const float*)d_in[13];
    const float* W2    = (const float*)d_in[14];
    const float* b2    = (const float*)d_in[15];
    float* out = (float*)d_out;

    float *xn1, *qkv, *ao, *x1, *xn2, *hbuf, *eobuf;
    cudaGetSymbolAddress((void**)&xn1,  g_xn1);
    cudaGetSymbolAddress((void**)&qkv,  g_qkv);
    cudaGetSymbolAddress((void**)&ao,   g_ao);
    cudaGetSymbolAddress((void**)&x1,   g_x1);
    cudaGetSymbolAddress((void**)&xn2,  g_xn2);
    cudaGetSymbolAddress((void**)&hbuf, g_h);
    cudaGetSymbolAddress((void**)&eobuf,g_eo);

    static bool attr_set = false;
    if (!attr_set) {
        cudaFuncSetAttribute(flash_attn_tc,
                             cudaFuncAttributeMaxDynamicSharedMemorySize, ATT_SMEM);
        attr_set = true;
    }

    init_kernel<<<1, 32>>>();

    // LN1 -> QKV GEMM (bf16 tensor cores)
    ln_kernel<<<Tt, 256>>>(x, ln1_g, ln1_b, xn1);
    mma_gemm_bf16<0,0,0,0,0><<<dim3(QKV3/BN, Tt/BM), 256>>>(
        xn1, Wqkv, bqkv, nullptr, qkv, Tt, QKV3, Dm);

    // attention (tf32 tensor-core flash, cp.async pipelined)
    flash_attn_tc<<<dim3(Ll/64, Hh, Bb), 128, ATT_SMEM>>>(qkv, mask, ao);

    // output proj + residual
    mma_gemm_bf16<0,0,0,1,0><<<dim3(Dm/BN, Tt/BM), 256>>>(
        ao, Wo, bo, x, x1, Tt, Dm, Dm);

    // LN2 -> gate -> routing
    ln_kernel<<<Tt, 256>>>(x1, ln2_g, ln2_b, xn2);
    gate_kernel<<<Tt/8, 256>>>(xn2, Wg, bg);
    offsets_kernel<<<1, 32>>>();
    scatter_kernel<<<(NASS+255)/256, 256>>>();

    // sparse MoE (bf16): up-proj (gather + GELU, NN), down-proj (NN)
    mma_gemm_bf16<1,1,1,0,1><<<dim3(HIDm/BN, NASS/BM, Ee), 256>>>(
        xn2, W1, b1, nullptr, hbuf, Tt, HIDm, Dm);
    mma_gemm_bf16<0,1,0,0,1><<<dim3(Dm/BN, NASS/BM, Ee), 256>>>(
        hbuf, W2, b2, nullptr, eobuf, Tt, Dm, HIDm);

    // combine + aux loss
    combine_kernel<<<Tt, 256>>>(out);
    mece_kernel<<<Ee, 256>>>();
    loss_kernel<<<1, 32>>>(out, out_size);
}

// round 6
// speedup vs baseline: 7.1391x; 1.1100x over previous
#include <cuda_runtime.h>
#include <cuda_bf16.h>
#include <math.h>
#include <stdint.h>

// Problem constants
#define Dm    1024
#define Hh    16
#define DHd   64
#define Ee    8
#define HIDm  2048
#define TOPKk 2
#define Bb    2
#define Ll    2048
#define Tt    4096          // B*L
#define QKV3  3072
#define NASS  (Tt*TOPKk)

typedef __nv_bfloat16 bf16;

// ---------------- scratch (static device memory) ---------------------------
__device__ float g_qkv [Tt*QKV3];
__device__ float g_x1  [Tt*Dm];
__device__ float g_xn2 [Tt*Dm];
__device__ float g_probs[Tt*Ee];
__device__ int   g_idx [NASS];
__device__ float g_wts [NASS];
__device__ int   g_counts[Ee];
__device__ int   g_offsets[Ee+1];
__device__ int   g_fill[Ee];
__device__ int   g_assign_row[NASS];
__device__ int   g_pos_of[NASS];
__device__ float g_eo [(size_t)NASS*Dm];
__device__ float g_me [Ee];
__device__ float g_ce [Ee];
// bf16 operand buffers
__device__ bf16  g_wqkv_bf[QKV3*Dm];
__device__ bf16  g_wo_bf  [Dm*Dm];
__device__ bf16  g_w1_bf  [(size_t)Ee*Dm*HIDm];
__device__ bf16  g_w2_bf  [(size_t)Ee*HIDm*Dm];
__device__ bf16  g_xn1b   [Tt*Dm];
__device__ bf16  g_xn2b   [Tt*Dm];
__device__ bf16  g_aob    [Tt*Dm];
__device__ bf16  g_hb     [(size_t)NASS*HIDm];

// ---------------------------------------------------------------- helpers
__device__ __forceinline__ uint32_t packbf2(float a, float b) {
    __nv_bfloat162 h = __floats2bfloat162_rn(a, b);
    return *reinterpret_cast<uint32_t*>(&h);
}
__device__ __forceinline__ void mma_tf32(float* c, const uint32_t* a, const uint32_t* b) {
    asm volatile(
        "mma.sync.aligned.m16n8k8.row.col.f32.tf32.tf32.f32 "
        "{%0,%1,%2,%3}, {%4,%5,%6,%7}, {%8,%9}, {%0,%1,%2,%3};"
        : "+f"(c[0]), "+f"(c[1]), "+f"(c[2]), "+f"(c[3])
        : "r"(a[0]), "r"(a[1]), "r"(a[2]), "r"(a[3]), "r"(b[0]), "r"(b[1]));
}
__device__ __forceinline__ void mma_bf16(float* c, const uint32_t* a, const uint32_t* b) {
    asm volatile(
        "mma.sync.aligned.m16n8k16.row.col.f32.bf16.bf16.f32 "
        "{%0,%1,%2,%3}, {%4,%5,%6,%7}, {%8,%9}, {%0,%1,%2,%3};"
        : "+f"(c[0]), "+f"(c[1]), "+f"(c[2]), "+f"(c[3])
        : "r"(a[0]), "r"(a[1]), "r"(a[2]), "r"(a[3]), "r"(b[0]), "r"(b[1]));
}
__device__ __forceinline__ void ldm_x4(uint32_t* r, uint32_t addr) {
    asm volatile("ldmatrix.sync.aligned.m8n8.x4.shared.b16 {%0,%1,%2,%3}, [%4];"
        : "=r"(r[0]), "=r"(r[1]), "=r"(r[2]), "=r"(r[3]) : "r"(addr));
}
__device__ __forceinline__ void ldm_x4_t(uint32_t* r, uint32_t addr) {
    asm volatile("ldmatrix.sync.aligned.m8n8.x4.trans.shared.b16 {%0,%1,%2,%3}, [%4];"
        : "=r"(r[0]), "=r"(r[1]), "=r"(r[2]), "=r"(r[3]) : "r"(addr));
}
__device__ __forceinline__ void cpasync16(uint32_t dst, const void* src) {
    asm volatile("cp.async.cg.shared.global [%0], [%1], 16;" :: "r"(dst), "l"(src));
}
__device__ __forceinline__ void cpcommit() {
    asm volatile("cp.async.commit_group;");
}
template<int N> __device__ __forceinline__ void cpwait() {
    asm volatile("cp.async.wait_group %0;" :: "n"(N));
}

// ---------------------------------------------------------------- utilities
__global__ void init_kernel() {
    int i = threadIdx.x;
    if (i < Ee) { g_counts[i] = 0; g_fill[i] = 0; }
}

__global__ __launch_bounds__(256) void f2bf_kernel(
    const float* __restrict__ in, bf16* __restrict__ out)
{
    int i = (blockIdx.x*256 + threadIdx.x)*8;
    float4 a = *(const float4*)(in+i);
    float4 b = *(const float4*)(in+i+4);
    uint4 u;
    u.x = packbf2(a.x,a.y); u.y = packbf2(a.z,a.w);
    u.z = packbf2(b.x,b.y); u.w = packbf2(b.z,b.w);
    *(uint4*)&out[i] = u;
}

// LayerNorm: writes bf16 (always) and optional fp32 copy
template<int WF32>
__global__ __launch_bounds__(256) void ln_kernel(
    const float* __restrict__ x, const float* __restrict__ g,
    const float* __restrict__ b, bf16* __restrict__ outb,
    float* __restrict__ outf)
{
    int t = blockIdx.x, tid = threadIdx.x;
    const float* xr = x + (size_t)t*Dm;
    float s = 0.f, s2 = 0.f;
    for (int d = tid; d < Dm; d += 256) { float v = xr[d]; s += v; s2 += v*v; }
    __shared__ float sh1[256], sh2[256];
    sh1[tid] = s; sh2[tid] = s2; __syncthreads();
    for (int st = 128; st > 0; st >>= 1) {
        if (tid < st) { sh1[tid] += sh1[tid+st]; sh2[tid] += sh2[tid+st]; }
        __syncthreads();
    }
    float mu  = sh1[0] * (1.f/Dm);
    float var = sh2[0] * (1.f/Dm) - mu*mu;
    float inv = rsqrtf(var + 1e-5f);
    for (int d = tid*2; d < Dm; d += 512) {
        float v0 = (xr[d]-mu)*inv*g[d] + b[d];
        float v1 = (xr[d+1]-mu)*inv*g[d+1] + b[d+1];
        *(uint32_t*)&outb[(size_t)t*Dm + d] = packbf2(v0, v1);
        if (WF32) *(float2*)&outf[(size_t)t*Dm + d] = make_float2(v0, v1);
    }
}

// -------------------- tensor-core GEMM (bf16 gmem operands, cp.async staged)
// CTA 128x128x32, 256 threads = 8 warps (2x4), warp tile 64x32. 2-stage.
#define BM 128
#define BN 128
#define BK 32
#define ASTW 20   // A / NT-B row stride in words (32 bf16 + pad)
#define BSTW 68   // NN-B row stride in words (128 bf16 + pad)

template<int GATHER, int TRANSB, int GELU, int RES, int MOE, int OUTBF>
__global__ __launch_bounds__(256) void mma_gemm_bf16(
    const bf16* __restrict__ A, const bf16* __restrict__ Bmat,
    const float* __restrict__ bias, const float* __restrict__ res,
    void* __restrict__ Cv, int M, int N, int K)
{
    __shared__ uint32_t As[2*BM*ASTW];
    __shared__ uint32_t Bs[2*BM*ASTW];   // covers NT (2*128*20) and NN (2*32*68)
    __shared__ int rowsrc[BM];

    int e = MOE ? blockIdx.z : 0;
    int cnt = M, off = 0;
    if (MOE) {
        cnt = g_counts[e]; off = g_offsets[e];
        if ((int)blockIdx.y * BM >= cnt) return;
    }
    int m0 = blockIdx.y * BM;
    int n0 = blockIdx.x * BN;
    int tid = threadIdx.x;

    const bf16* Bbase = Bmat + (size_t)e * K * N;
    const float* bi   = bias + (size_t)e * N;

    if (tid < BM) {
        int lr = m0 + tid;
        int r;
        if (MOE) {
            int l = lr < cnt ? lr : cnt - 1;
            r = GATHER ? g_assign_row[off + l] : (off + l);
        } else r = lr;
        rowsrc[tid] = r;
    }
    __syncthreads();

    int lane = tid & 31;
    int wid  = tid >> 5;
    int wm = (wid >> 2) * 64;
    int wn = (wid & 3) * 32;
    int g  = lane >> 2;
    int tg = lane & 3;

    uint32_t as_base = (uint32_t)__cvta_generic_to_shared(As);
    uint32_t bs_base = (uint32_t)__cvta_generic_to_shared(Bs);
    int a_row  = (lane & 7) + ((lane >> 3) & 1) * 8;
    int a_colw = (lane >> 4) * 4;
    int b_nt_sub = (lane >> 4) & 1;
    int b_row  = (lane & 7);
    int b_colw = ((lane >> 3) & 1) * 4;
    // NN trans-ldmatrix lane mapping
    int jj = lane >> 3;
    int nn_krow = (lane & 7) + 8*(jj & 1);
    int nn_ncol = 8*(jj >> 1);

    float acc[4][4][4];
    #pragma unroll
    for (int i = 0; i < 4; i++)
        #pragma unroll
        for (int j = 0; j < 4; j++)
            #pragma unroll
            for (int q = 0; q < 4; q++) acc[i][j][q] = 0.f;

    auto stageAB = [&](int k0, int s) {
        // A: 128 rows x 32 bf16 (64B = 4 chunks)
        #pragma unroll
        for (int p = 0; p < 2; p++) {
            int idx = p*256 + tid;
            int r = idx >> 2, c = idx & 3;
            const bf16* src = A + (size_t)rowsrc[r]*K + k0 + c*8;
            cpasync16(as_base + (((s*BM + r)*ASTW) + c*4)*4u, src);
        }
        if (!TRANSB) {
            #pragma unroll
            for (int p = 0; p < 2; p++) {
                int idx = p*256 + tid;
                int r = idx >> 2, c = idx & 3;
                const bf16* src = Bbase + (size_t)(n0 + r)*K + k0 + c*8;
                cpasync16(bs_base + (((s*BM + r)*ASTW) + c*4)*4u, src);
            }
        } else {
            // B: 32 k-rows x 128 n bf16 (256B = 16 chunks)
            #pragma unroll
            for (int p = 0; p < 2; p++) {
                int idx = p*256 + tid;
                int kr = idx >> 4, c = idx & 15;
                const bf16* src = Bbase + (size_t)(k0 + kr)*N + n0 + c*8;
                cpasync16(bs_base + (((s*32 + kr)*BSTW) + c*4)*4u, src);
            }
        }
    };

    auto compute = [&](int s) {
        #pragma unroll
        for (int ks = 0; ks < 2; ks++) {
            int k0w = ks * 8;
            uint32_t af[4][4];
            #pragma unroll
            for (int mt = 0; mt < 4; mt++) {
                uint32_t addr = as_base +
                    ((s*BM + wm + mt*16 + a_row)*ASTW + k0w + a_colw) * 4u;
                ldm_x4(af[mt], addr);
            }
            uint32_t bf[2][4];
            if (!TRANSB) {
                #pragma unroll
                for (int ntp = 0; ntp < 2; ntp++) {
                    int nrow = wn + (2*ntp + b_nt_sub)*8 + b_row;
                    uint32_t addr = bs_base + ((s*BN + nrow)*ASTW + k0w + b_colw) * 4u;
                    ldm_x4(bf[ntp], addr);
                }
            } else {
                int krow = s*32 + ks*16 + nn_krow;
                #pragma unroll
                for (int ntp = 0; ntp < 2; ntp++) {
                    uint32_t addr = bs_base + (uint32_t)(krow*BSTW)*4u
                                  + (uint32_t)(wn + ntp*16 + nn_ncol)*2u;
                    ldm_x4_t(bf[ntp], addr);
                }
            }
            #pragma unroll
            for (int mt = 0; mt < 4; mt++) {
                #pragma unroll
                for (int nt = 0; nt < 4; nt++) {
                    const uint32_t* bb = &bf[nt >> 1][(nt & 1) * 2];
                    mma_bf16(acc[mt][nt], af[mt], bb);
                }
            }
        }
    };

    int KT = K / BK;
    stageAB(0, 0); cpcommit();
    stageAB(BK, 1); cpcommit();
    for (int t = 0; t < KT; t++) {
        cpwait<1>();
        __syncthreads();
        compute(t & 1);
        __syncthreads();
        if (t + 2 < KT) stageAB((t+2)*BK, t & 1);
        cpcommit();
    }

    #pragma unroll
    for (int mt = 0; mt < 4; mt++) {
        #pragma unroll
        for (int h = 0; h < 2; h++) {
            int lr = m0 + wm + mt*16 + g + 8*h;
            if (MOE && lr >= cnt) continue;
            int gr = MOE ? (off + lr) : lr;
            #pragma unroll
            for (int nt = 0; nt < 4; nt++) {
                int cc = n0 + wn + nt*8 + 2*tg;
                float v0 = acc[mt][nt][2*h + 0] + bi[cc];
                float v1 = acc[mt][nt][2*h + 1] + bi[cc + 1];
                if (GELU) {
                    v0 = 0.5f*v0*(1.f + erff(v0*0.70710678118f));
                    v1 = 0.5f*v1*(1.f + erff(v1*0.70710678118f));
                }
                if (RES) {
                    v0 += res[(size_t)gr*N + cc];
                    v1 += res[(size_t)gr*N + cc + 1];
                }
                if (OUTBF)
                    *(uint32_t*)&((bf16*)Cv)[(size_t)gr*N + cc] = packbf2(v0, v1);
                else
                    *(float2*)&((float*)Cv)[(size_t)gr*N + cc] = make_float2(v0, v1);
            }
        }
    }
}

// -------------- tensor-core flash attention (tf32, cp.async double-buffer) --
// grid (L/64, H, B), 128 threads = 4 warps; each warp owns 16 Q rows.
#define AST 68
#define VST 72
#define NTILES (Ll/64)
#define ATT_SMEM ((2*64*AST + 2*64*VST + 64*AST)*4 + 160)

__global__ __launch_bounds__(128) void flash_attn_tc(
    const float* __restrict__ qkv, const unsigned char* __restrict__ mask,
    bf16* __restrict__ ao)
{
    extern __shared__ uint32_t dsm[];
    uint32_t* Ks = dsm;                        // [2][64][AST]
    uint32_t* Vs = dsm + 2*64*AST;             // [2][64][VST]
    uint32_t* Ps = dsm + 2*64*AST + 2*64*VST;  // [64][AST] (Q stage, then P)
    unsigned char* smask = (unsigned char*)(Ps + 64*AST);  // [2][64]

    int b = blockIdx.z, h = blockIdx.y, qt = blockIdx.x;
    int tid = threadIdx.x;
    int lane = tid & 31, wid = tid >> 5;
    int g = lane >> 2, tg = lane & 3;
    int wm = wid * 16;
    int t0 = b*Ll + qt*64;

    uint32_t sbase = (uint32_t)__cvta_generic_to_shared(dsm);
    uint32_t ks_b = sbase;
    uint32_t vs_b = sbase + 2*64*AST*4;
    uint32_t ps_b = sbase + (2*64*AST + 2*64*VST)*4;
    uint32_t mk_b = ps_b + 64*AST*4;

    #pragma unroll
    for (int p = 0; p < 8; p++) {
        int idx = p*128 + tid;
        int r = idx >> 4, c = (idx & 15) * 4;
        cpasync16(ps_b + (r*AST + c)*4u, &qkv[(size_t)(t0+r)*QKV3 + h*DHd + c]);
    }
    cpcommit();

    auto stageKV = [&](int u, int s) {
        int base_t = b*Ll + u*64;
        #pragma unroll
        for (int p = 0; p < 8; p++) {
            int idx = p*128 + tid;
            int r = idx >> 4, c = (idx & 15) * 4;
            size_t gb = (size_t)(base_t + r)*QKV3 + h*DHd + c;
            cpasync16(ks_b + (((s*64) + r)*AST + c)*4u, &qkv[gb + Dm]);
            cpasync16(vs_b + (((s*64) + r)*VST + c)*4u, &qkv[gb + 2*Dm]);
        }
        if (tid < 4)
            cpasync16(mk_b + (uint32_t)(s*64 + tid*16), &mask[base_t + tid*16]);
        cpcommit();
    };
    stageKV(0, 0);
    stageKV(1, 1);

    cpwait<2>();
    __syncthreads();
    uint32_t qf[8][4];
    #pragma unroll
    for (int ks = 0; ks < 8; ks++) {
        int k0 = ks*8;
        qf[ks][0] = Ps[(wm+g)*AST + k0 + tg];
        qf[ks][1] = Ps[(wm+g+8)*AST + k0 + tg];
        qf[ks][2] = Ps[(wm+g)*AST + k0 + 4 + tg];
        qf[ks][3] = Ps[(wm+g+8)*AST + k0 + 4 + tg];
    }

    float oacc[8][4];
    #pragma unroll
    for (int nt = 0; nt < 8; nt++)
        #pragma unroll
        for (int q = 0; q < 4; q++) oacc[nt][q] = 0.f;
    float m0 = -1e30f, m1 = -1e30f, l0 = 0.f, l1 = 0.f;

    for (int u = 0; u < NTILES; u++) {
        int s = u & 1;
        cpwait<1>();
        __syncthreads();

        float sacc[8][4];
        #pragma unroll
        for (int nt = 0; nt < 8; nt++)
            #pragma unroll
            for (int q = 0; q < 4; q++) sacc[nt][q] = 0.f;
        #pragma unroll
        for (int ks = 0; ks < 8; ks++) {
            int k0 = ks*8;
            #pragma unroll
            for (int nt = 0; nt < 8; nt++) {
                uint32_t bf[2];
                bf[0] = Ks[(s*64 + nt*8+g)*AST + k0 + tg];
                bf[1] = Ks[(s*64 + nt*8+g)*AST + k0 + 4 + tg];
                mma_tf32(sacc[nt], qf[ks], bf);
            }
        }

        float mx0 = -1e30f, mx1 = -1e30f;
        #pragma unroll
        for (int nt = 0; nt < 8; nt++) {
            #pragma unroll
            for (int j = 0; j < 2; j++) {
                int c = nt*8 + 2*tg + j;
                bool mk = smask[s*64 + c] != 0;
                float s0 = mk ? -1e9f : sacc[nt][j]   * 0.125f;
                float s1 = mk ? -1e9f : sacc[nt][2+j] * 0.125f;
                sacc[nt][j] = s0; sacc[nt][2+j] = s1;
                mx0 = fmaxf(mx0, s0); mx1 = fmaxf(mx1, s1);
            }
        }
        mx0 = fmaxf(mx0, __shfl_xor_sync(0xffffffffu, mx0, 1));
        mx0 = fmaxf(mx0, __shfl_xor_sync(0xffffffffu, mx0, 2));
        mx1 = fmaxf(mx1, __shfl_xor_sync(0xffffffffu, mx1, 1));
        mx1 = fmaxf(mx1, __shfl_xor_sync(0xffffffffu, mx1, 2));
        float nm0 = fmaxf(m0, mx0), nm1 = fmaxf(m1, mx1);
        float corr0 = __expf(m0 - nm0), corr1 = __expf(m1 - nm1);
        m0 = nm0; m1 = nm1;
        float ls0 = 0.f, ls1 = 0.f;
        #pragma unroll
        for (int nt = 0; nt < 8; nt++) {
            float p00 = __expf(sacc[nt][0] - m0);
            float p01 = __expf(sacc[nt][1] - m0);
            float p10 = __expf(sacc[nt][2] - m1);
            float p11 = __expf(sacc[nt][3] - m1);
            ls0 += p00 + p01; ls1 += p10 + p11;
            *(uint2*)&Ps[(wm+g)*AST   + nt*8 + 2*tg] =
                make_uint2(__float_as_uint(p00), __float_as_uint(p01));
            *(uint2*)&Ps[(wm+g+8)*AST + nt*8 + 2*tg] =
                make_uint2(__float_as_uint(p10), __float_as_uint(p11));
        }
        ls0 += __shfl_xor_sync(0xffffffffu, ls0, 1);
        ls0 += __shfl_xor_sync(0xffffffffu, ls0, 2);
        ls1 += __shfl_xor_sync(0xffffffffu, ls1, 1);
        ls1 += __shfl_xor_sync(0xffffffffu, ls1, 2);
        l0 = l0*corr0 + ls0;
        l1 = l1*corr1 + ls1;
        #pragma unroll
        for (int nt = 0; nt < 8; nt++) {
            oacc[nt][0] *= corr0; oacc[nt][1] *= corr0;
            oacc[nt][2] *= corr1; oacc[nt][3] *= corr1;
        }
        __syncwarp();

        #pragma unroll
        for (int ks = 0; ks < 8; ks++) {
            int k0 = ks*8;
            uint32_t af[4];
            af[0] = Ps[(wm+g)*AST + k0 + tg];
            af[1] = Ps[(wm+g+8)*AST + k0 + tg];
            af[2] = Ps[(wm+g)*AST + k0 + 4 + tg];
            af[3] = Ps[(wm+g+8)*AST + k0 + 4 + tg];
            #pragma unroll
            for (int nt = 0; nt < 8; nt++) {
                uint32_t bf[2];
                bf[0] = Vs[(s*64 + k0+tg)*VST   + nt*8 + g];
                bf[1] = Vs[(s*64 + k0+tg+4)*VST + nt*8 + g];
                mma_tf32(oacc[nt], af, bf);
            }
        }
        __syncthreads();
        if (u + 2 < NTILES) stageKV(u + 2, s);
    }

    float inv0 = 1.f / l0, inv1 = 1.f / l1;
    int r0 = t0 + wm + g, r1 = r0 + 8;
    #pragma unroll
    for (int nt = 0; nt < 8; nt++) {
        int c = nt*8 + 2*tg;
        *(uint32_t*)&ao[(size_t)r0*Dm + h*DHd + c] =
            packbf2(oacc[nt][0]*inv0, oacc[nt][1]*inv0);
        *(uint32_t*)&ao[(size_t)r1*Dm + h*DHd + c] =
            packbf2(oacc[nt][2]*inv1, oacc[nt][3]*inv1);
    }
}

// ------------------------------------------------------------------- gating
__global__ __launch_bounds__(256) void gate_kernel(
    const float* __restrict__ xn2, const float* __restrict__ Wg,
    const float* __restrict__ bg)
{
    int t = blockIdx.x*8 + (threadIdx.x >> 5);
    int lane = threadIdx.x & 31;
    const float* xr = xn2 + (size_t)t*Dm;
    float part[Ee] = {};
    for (int d = lane; d < Dm; d += 32) {
        float xv = xr[d];
        const float4* wr = (const float4*)(Wg + (size_t)d*Ee);
        float4 w0 = wr[0], w1 = wr[1];
        part[0] += xv*w0.x; part[1] += xv*w0.y;
        part[2] += xv*w0.z; part[3] += xv*w0.w;
        part[4] += xv*w1.x; part[5] += xv*w1.y;
        part[6] += xv*w1.z; part[7] += xv*w1.w;
    }
    #pragma unroll
    for (int e = 0; e < Ee; e++) {
        part[e] += __shfl_xor_sync(0xffffffffu, part[e], 16);
        part[e] += __shfl_xor_sync(0xffffffffu, part[e], 8);
        part[e] += __shfl_xor_sync(0xffffffffu, part[e], 4);
        part[e] += __shfl_xor_sync(0xffffffffu, part[e], 2);
        part[e] += __shfl_xor_sync(0xffffffffu, part[e], 1);
    }
    if (lane == 0) {
        float logits[Ee];
        #pragma unroll
        for (int e = 0; e < Ee; e++) logits[e] = part[e] + bg[e];
        float mx = -1e30f;
        #pragma unroll
        for (int e = 0; e < Ee; e++) mx = fmaxf(mx, logits[e]);
        float p[Ee], se = 0.f;
        #pragma unroll
        for (int e = 0; e < Ee; e++) { p[e] = expf(logits[e]-mx); se += p[e]; }
        float isz = 1.f/se;
        #pragma unroll
        for (int e = 0; e < Ee; e++) { p[e] *= isz; g_probs[t*Ee+e] = p[e]; }
        int i0 = 0;
        #pragma unroll
        for (int e = 1; e < Ee; e++) if (p[e] > p[i0]) i0 = e;
        int i1 = (i0 == 0) ? 1 : 0;
        #pragma unroll
        for (int e = 0; e < Ee; e++) if (e != i0 && p[e] > p[i1]) i1 = e;
        float v0 = p[i0], v1 = p[i1], s01 = v0 + v1;
        g_idx[2*t]   = i0; g_idx[2*t+1] = i1;
        g_wts[2*t]   = v0/s01; g_wts[2*t+1] = v1/s01;
        atomicAdd(&g_counts[i0], 1);
        atomicAdd(&g_counts[i1], 1);
    }
}

__global__ void offsets_kernel() {
    if (threadIdx.x == 0) {
        int o = 0;
        for (int e = 0; e < Ee; e++) { g_offsets[e] = o; o += g_counts[e]; }
        g_offsets[Ee] = o;
    }
}

__global__ void scatter_kernel() {
    int a = blockIdx.x*blockDim.x + threadIdx.x;
    if (a < NASS) {
        int e = g_idx[a];
        int pos = g_offsets[e] + atomicAdd(&g_fill[e], 1);
        g_assign_row[pos] = a >> 1;
        g_pos_of[a] = pos;
    }
}

// ------------------------------------------------------ combine + moe loss
__global__ __launch_bounds__(256) void combine_kernel(float* __restrict__ out) {
    int t = blockIdx.x, tid = threadIdx.x;
    int p0 = g_pos_of[2*t], p1 = g_pos_of[2*t+1];
    float w0 = g_wts[2*t], w1 = g_wts[2*t+1];
    const float* e0 = g_eo + (size_t)p0*Dm;
    const float* e1 = g_eo + (size_t)p1*Dm;
    const float* xr = g_x1 + (size_t)t*Dm;
    float* orow = out + (size_t)t*Dm;
    for (int d = tid; d < Dm; d += 256)
        orow[d] = xr[d] + w0*e0[d] + w1*e1[d];
}

__global__ __launch_bounds__(256) void mece_kernel() {
    int e = blockIdx.x, tid = threadIdx.x;
    float s = 0.f, c = 0.f;
    for (int t = tid; t < Tt; t += 256) s += g_probs[t*Ee + e];
    for (int a = tid; a < NASS; a += 256) c += (g_idx[a] == e) ? 1.f : 0.f;
    __shared__ float sh1[256], sh2[256];
    sh1[tid] = s; sh2[tid] = c; __syncthreads();
    for (int st = 128; st > 0; st >>= 1) {
        if (tid < st) { sh1[tid] += sh1[tid+st]; sh2[tid] += sh2[tid+st]; }
        __syncthreads();
    }
    if (tid == 0) { g_me[e] = sh1[0]*(1.f/Tt); g_ce[e] = sh2[0]*(1.f/Tt); }
}

__global__ void loss_kernel(float* __restrict__ out, int out_size) {
    if (threadIdx.x == 0 && out_size > Tt*Dm) {
        float L = 0.f;
        for (int e = 0; e < Ee; e++) L += g_me[e]*g_ce[e];
        out[Tt*Dm] = (float)Ee * L;
    }
}

// ------------------------------------------------------------------ driver
extern "C" void kernel_launch(void* const* d_in, const int* in_sizes, int n_in,
                              void* d_out, int out_size)
{
    const float* x     = (const float*)d_in[0];
    const unsigned char* mask = (const unsigned char*)d_in[1];
    const float* ln1_g = (const float*)d_in[2];
    const float* ln1_b = (const float*)d_in[3];
    const float* Wqkv  = (const float*)d_in[4];
    const float* bqkv  = (const float*)d_in[5];
    const float* Wo    = (const float*)d_in[6];
    const float* bo    = (const float*)d_in[7];
    const float* ln2_g = (const float*)d_in[8];
    const float* ln2_b = (const float*)d_in[9];
    const float* Wg    = (const float*)d_in[10];
    const float* bg    = (const float*)d_in[11];
    const float* W1    = (const float*)d_in[12];
    const float* b1    = (const float*)d_in[13];
    const float* W2    = (const float*)d_in[14];
    const float* b2    = (const float*)d_in[15];
    float* out = (float*)d_out;

    float *qkv, *x1, *xn2, *eobuf;
    bf16 *wqkvb, *wob, *w1b, *w2b, *xn1b, *xn2b, *aob, *hb;
    cudaGetSymbolAddress((void**)&qkv,   g_qkv);
    cudaGetSymbolAddress((void**)&x1,    g_x1);
    cudaGetSymbolAddress((void**)&xn2,   g_xn2);
    cudaGetSymbolAddress((void**)&eobuf, g_eo);
    cudaGetSymbolAddress((void**)&wqkvb, g_wqkv_bf);
    cudaGetSymbolAddress((void**)&wob,   g_wo_bf);
    cudaGetSymbolAddress((void**)&w1b,   g_w1_bf);
    cudaGetSymbolAddress((void**)&w2b,   g_w2_bf);
    cudaGetSymbolAddress((void**)&xn1b,  g_xn1b);
    cudaGetSymbolAddress((void**)&xn2b,  g_xn2b);
    cudaGetSymbolAddress((void**)&aob,   g_aob);
    cudaGetSymbolAddress((void**)&hb,    g_hb);

    static bool attr_set = false;
    if (!attr_set) {
        cudaFuncSetAttribute(flash_attn_tc,
                             cudaFuncAttributeMaxDynamicSharedMemorySize, ATT_SMEM);
        attr_set = true;
    }

    init_kernel<<<1, 32>>>();

    // weight conversions (per launch; deterministic)
    f2bf_kernel<<<(QKV3*Dm)/2048, 256>>>(Wqkv, wqkvb);
    f2bf_kernel<<<(Dm*Dm)/2048, 256>>>(Wo, wob);
    f2bf_kernel<<<(Ee*Dm*HIDm)/2048, 256>>>(W1, w1b);
    f2bf_kernel<<<(Ee*HIDm*Dm)/2048, 256>>>(W2, w2b);

    // LN1 -> QKV GEMM
    ln_kernel<0><<<Tt, 256>>>(x, ln1_g, ln1_b, xn1b, nullptr);
    mma_gemm_bf16<0,0,0,0,0,0><<<dim3(QKV3/BN, Tt/BM), 256>>>(
        xn1b, wqkvb, bqkv, nullptr, qkv, Tt, QKV3, Dm);

    // attention (tf32 tensor-core flash) -> bf16 ao
    flash_attn_tc<<<dim3(Ll/64, Hh, Bb), 128, ATT_SMEM>>>(qkv, mask, aob);

    // output proj + residual (fp32 out)
    mma_gemm_bf16<0,0,0,1,0,0><<<dim3(Dm/BN, Tt/BM), 256>>>(
        aob, wob, bo, x, x1, Tt, Dm, Dm);

    // LN2 (fp32 for gate + bf16 for MoE) -> gate -> routing
    ln_kernel<1><<<Tt, 256>>>(x1, ln2_g, ln2_b, xn2b, xn2);
    gate_kernel<<<Tt/8, 256>>>(xn2, Wg, bg);
    offsets_kernel<<<1, 32>>>();
    scatter_kernel<<<(NASS+255)/256, 256>>>();

    // sparse MoE: up (gather + GELU, NN, bf16 out), down (NN, fp32 out)
    mma_gemm_bf16<1,1,1,0,1,1><<<dim3(HIDm/BN, NASS/BM, Ee), 256>>>(
        xn2b, w1b, b1, nullptr, hb, Tt, HIDm, Dm);
    mma_gemm_bf16<0,1,0,0,1,0><<<dim3(Dm/BN, NASS/BM, Ee), 256>>>(
        hb, w2b, b2, nullptr, eobuf, Tt, Dm, HIDm);

    // combine + aux loss
    combine_kernel<<<Tt, 256>>>(out);
    mece_kernel<<<Ee, 256>>>();
    loss_kernel<<<1, 32>>>(out, out_size);
}

// round 7
// speedup vs baseline: 7.5408x; 1.0563x over previous
#include <cuda_runtime.h>
#include <cuda_bf16.h>
#include <math.h>
#include <stdint.h>

// Problem constants
#define Dm    1024
#define Hh    16
#define DHd   64
#define Ee    8
#define HIDm  2048
#define TOPKk 2
#define Bb    2
#define Ll    2048
#define Tt    4096          // B*L
#define QKV3  3072
#define NASS  (Tt*TOPKk)

typedef __nv_bfloat16 bf16;

// ---------------- scratch (static device memory) ---------------------------
__device__ float g_qkv [Tt*QKV3];
__device__ float g_x1  [Tt*Dm];
__device__ float g_xn2 [Tt*Dm];
__device__ float g_probs[Tt*Ee];
__device__ int   g_idx [NASS];
__device__ float g_wts [NASS];
__device__ int   g_counts[Ee];
__device__ int   g_offsets[Ee+1];
__device__ int   g_fill[Ee];
__device__ int   g_assign_row[NASS];
__device__ int   g_pos_of[NASS];
__device__ float g_eo [(size_t)NASS*Dm];
__device__ float g_me [Ee];
__device__ float g_ce [Ee];
// bf16 operand buffers
__device__ bf16  g_wqkv_bf[QKV3*Dm];
__device__ bf16  g_wo_bf  [Dm*Dm];
__device__ bf16  g_w1_bf  [(size_t)Ee*Dm*HIDm];
__device__ bf16  g_w2_bf  [(size_t)Ee*HIDm*Dm];
__device__ bf16  g_xn1b   [Tt*Dm];
__device__ bf16  g_xn2b   [Tt*Dm];
__device__ bf16  g_aob    [Tt*Dm];
__device__ bf16  g_hb     [(size_t)NASS*HIDm];

// ---------------------------------------------------------------- helpers
__device__ __forceinline__ uint32_t packbf2(float a, float b) {
    __nv_bfloat162 h = __floats2bfloat162_rn(a, b);
    return *reinterpret_cast<uint32_t*>(&h);
}
__device__ __forceinline__ void mma_tf32(float* c, const uint32_t* a, const uint32_t* b) {
    asm volatile(
        "mma.sync.aligned.m16n8k8.row.col.f32.tf32.tf32.f32 "
        "{%0,%1,%2,%3}, {%4,%5,%6,%7}, {%8,%9}, {%0,%1,%2,%3};"
        : "+f"(c[0]), "+f"(c[1]), "+f"(c[2]), "+f"(c[3])
        : "r"(a[0]), "r"(a[1]), "r"(a[2]), "r"(a[3]), "r"(b[0]), "r"(b[1]));
}
__device__ __forceinline__ void mma_bf16(float* c, const uint32_t* a, const uint32_t* b) {
    asm volatile(
        "mma.sync.aligned.m16n8k16.row.col.f32.bf16.bf16.f32 "
        "{%0,%1,%2,%3}, {%4,%5,%6,%7}, {%8,%9}, {%0,%1,%2,%3};"
        : "+f"(c[0]), "+f"(c[1]), "+f"(c[2]), "+f"(c[3])
        : "r"(a[0]), "r"(a[1]), "r"(a[2]), "r"(a[3]), "r"(b[0]), "r"(b[1]));
}
__device__ __forceinline__ void ldm_x4(uint32_t* r, uint32_t addr) {
    asm volatile("ldmatrix.sync.aligned.m8n8.x4.shared.b16 {%0,%1,%2,%3}, [%4];"
        : "=r"(r[0]), "=r"(r[1]), "=r"(r[2]), "=r"(r[3]) : "r"(addr));
}
__device__ __forceinline__ void ldm_x4_t(uint32_t* r, uint32_t addr) {
    asm volatile("ldmatrix.sync.aligned.m8n8.x4.trans.shared.b16 {%0,%1,%2,%3}, [%4];"
        : "=r"(r[0]), "=r"(r[1]), "=r"(r[2]), "=r"(r[3]) : "r"(addr));
}
__device__ __forceinline__ void cpasync16(uint32_t dst, const void* src) {
    asm volatile("cp.async.cg.shared.global [%0], [%1], 16;" :: "r"(dst), "l"(src));
}
__device__ __forceinline__ void cpcommit() {
    asm volatile("cp.async.commit_group;");
}
template<int N> __device__ __forceinline__ void cpwait() {
    asm volatile("cp.async.wait_group %0;" :: "n"(N));
}

// ---------------------------------------------------------------- utilities
__global__ void init_kernel() {
    int i = threadIdx.x;
    if (i < Ee) { g_counts[i] = 0; g_fill[i] = 0; }
}

__global__ __launch_bounds__(256) void f2bf_kernel(
    const float* __restrict__ in, bf16* __restrict__ out)
{
    int i = (blockIdx.x*256 + threadIdx.x)*8;
    float4 a = *(const float4*)(in+i);
    float4 b = *(const float4*)(in+i+4);
    uint4 u;
    u.x = packbf2(a.x,a.y); u.y = packbf2(a.z,a.w);
    u.z = packbf2(b.x,b.y); u.w = packbf2(b.z,b.w);
    *(uint4*)&out[i] = u;
}

template<int WF32>
__global__ __launch_bounds__(256) void ln_kernel(
    const float* __restrict__ x, const float* __restrict__ g,
    const float* __restrict__ b, bf16* __restrict__ outb,
    float* __restrict__ outf)
{
    int t = blockIdx.x, tid = threadIdx.x;
    const float* xr = x + (size_t)t*Dm;
    float s = 0.f, s2 = 0.f;
    for (int d = tid; d < Dm; d += 256) { float v = xr[d]; s += v; s2 += v*v; }
    __shared__ float sh1[256], sh2[256];
    sh1[tid] = s; sh2[tid] = s2; __syncthreads();
    for (int st = 128; st > 0; st >>= 1) {
        if (tid < st) { sh1[tid] += sh1[tid+st]; sh2[tid] += sh2[tid+st]; }
        __syncthreads();
    }
    float mu  = sh1[0] * (1.f/Dm);
    float var = sh2[0] * (1.f/Dm) - mu*mu;
    float inv = rsqrtf(var + 1e-5f);
    for (int d = tid*2; d < Dm; d += 512) {
        float v0 = (xr[d]-mu)*inv*g[d] + b[d];
        float v1 = (xr[d+1]-mu)*inv*g[d+1] + b[d+1];
        *(uint32_t*)&outb[(size_t)t*Dm + d] = packbf2(v0, v1);
        if (WF32) *(float2*)&outf[(size_t)t*Dm + d] = make_float2(v0, v1);
    }
}

// -------------------- tensor-core GEMM (bf16, 4-stage cp.async, 1 bar/iter)
#define BM 128
#define BN 128
#define BK 32
#define ASTW 20      // A / NT-B row stride (words)
#define BSTW 68      // NN-B row stride (words)
#define GST  4       // stages
#define A_STG (BM*ASTW)     // 2560 words
#define B_STG (BM*ASTW)     // 2560 words (covers NT 128x20 and NN 32x68=2176)
#define GEMM_SMEM ((GST*(A_STG + B_STG))*4)

template<int GATHER, int TRANSB, int GELU, int RES, int MOE, int OUTBF>
__global__ __launch_bounds__(256) void mma_gemm_bf16(
    const bf16* __restrict__ A, const bf16* __restrict__ Bmat,
    const float* __restrict__ bias, const float* __restrict__ res,
    void* __restrict__ Cv, int M, int N, int K)
{
    extern __shared__ uint32_t gsm[];
    __shared__ int rowsrc[BM];

    int e = MOE ? blockIdx.z : 0;
    int cnt = M, off = 0;
    if (MOE) {
        cnt = g_counts[e]; off = g_offsets[e];
        if ((int)blockIdx.y * BM >= cnt) return;
    }
    int m0 = blockIdx.y * BM;
    int n0 = blockIdx.x * BN;
    int tid = threadIdx.x;

    const bf16* Bbase = Bmat + (size_t)e * K * N;
    const float* bi   = bias + (size_t)e * N;

    if (tid < BM) {
        int lr = m0 + tid;
        int r;
        if (MOE) {
            int l = lr < cnt ? lr : cnt - 1;
            r = GATHER ? g_assign_row[off + l] : (off + l);
        } else r = lr;
        rowsrc[tid] = r;
    }
    __syncthreads();

    int lane = tid & 31;
    int wid  = tid >> 5;
    int wm = (wid >> 2) * 64;
    int wn = (wid & 3) * 32;
    int g  = lane >> 2;
    int tg = lane & 3;

    uint32_t as_base = (uint32_t)__cvta_generic_to_shared(gsm);
    uint32_t bs_base = as_base + GST*A_STG*4u;
    int a_row  = (lane & 7) + ((lane >> 3) & 1) * 8;
    int a_colw = (lane >> 4) * 4;
    int b_nt_sub = (lane >> 4) & 1;
    int b_row  = (lane & 7);
    int b_colw = ((lane >> 3) & 1) * 4;
    int jj = lane >> 3;
    int nn_krow = (lane & 7) + 8*(jj & 1);
    int nn_ncol = 8*(jj >> 1);

    float acc[4][4][4];
    #pragma unroll
    for (int i = 0; i < 4; i++)
        #pragma unroll
        for (int j = 0; j < 4; j++)
            #pragma unroll
            for (int q = 0; q < 4; q++) acc[i][j][q] = 0.f;

    auto stageAB = [&](int k0, int s) {
        #pragma unroll
        for (int p = 0; p < 2; p++) {
            int idx = p*256 + tid;
            int r = idx >> 2, c = idx & 3;
            const bf16* src = A + (size_t)rowsrc[r]*K + k0 + c*8;
            cpasync16(as_base + (((s*BM + r)*ASTW) + c*4)*4u, src);
        }
        if (!TRANSB) {
            #pragma unroll
            for (int p = 0; p < 2; p++) {
                int idx = p*256 + tid;
                int r = idx >> 2, c = idx & 3;
                const bf16* src = Bbase + (size_t)(n0 + r)*K + k0 + c*8;
                cpasync16(bs_base + (((s*BM + r)*ASTW) + c*4)*4u, src);
            }
        } else {
            #pragma unroll
            for (int p = 0; p < 2; p++) {
                int idx = p*256 + tid;
                int kr = idx >> 4, c = idx & 15;
                const bf16* src = Bbase + (size_t)(k0 + kr)*N + n0 + c*8;
                cpasync16(bs_base + (((s*32 + kr)*BSTW) + c*4)*4u, src);
            }
        }
    };

    auto compute = [&](int s) {
        #pragma unroll
        for (int ks = 0; ks < 2; ks++) {
            int k0w = ks * 8;
            uint32_t af[4][4];
            #pragma unroll
            for (int mt = 0; mt < 4; mt++) {
                uint32_t addr = as_base +
                    ((s*BM + wm + mt*16 + a_row)*ASTW + k0w + a_colw) * 4u;
                ldm_x4(af[mt], addr);
            }
            uint32_t bf[2][4];
            if (!TRANSB) {
                #pragma unroll
                for (int ntp = 0; ntp < 2; ntp++) {
                    int nrow = wn + (2*ntp + b_nt_sub)*8 + b_row;
                    uint32_t addr = bs_base + ((s*BN + nrow)*ASTW + k0w + b_colw) * 4u;
                    ldm_x4(bf[ntp], addr);
                }
            } else {
                int krow = s*32 + ks*16 + nn_krow;
                #pragma unroll
                for (int ntp = 0; ntp < 2; ntp++) {
                    uint32_t addr = bs_base + (uint32_t)(krow*BSTW)*4u
                                  + (uint32_t)(wn + ntp*16 + nn_ncol)*2u;
                    ldm_x4_t(bf[ntp], addr);
                }
            }
            #pragma unroll
            for (int mt = 0; mt < 4; mt++) {
                #pragma unroll
                for (int nt = 0; nt < 4; nt++) {
                    const uint32_t* bb = &bf[nt >> 1][(nt & 1) * 2];
                    mma_bf16(acc[mt][nt], af[mt], bb);
                }
            }
        }
    };

    int KT = K / BK;
    stageAB(0, 0);      cpcommit();
    stageAB(BK, 1);     cpcommit();
    stageAB(2*BK, 2);   cpcommit();
    for (int t = 0; t < KT; t++) {
        cpwait<2>();
        __syncthreads();
        if (t + 3 < KT) stageAB((t+3)*BK, (t+3) & 3);
        cpcommit();
        compute(t & 3);
    }

    #pragma unroll
    for (int mt = 0; mt < 4; mt++) {
        #pragma unroll
        for (int h = 0; h < 2; h++) {
            int lr = m0 + wm + mt*16 + g + 8*h;
            if (MOE && lr >= cnt) continue;
            int gr = MOE ? (off + lr) : lr;
            #pragma unroll
            for (int nt = 0; nt < 4; nt++) {
                int cc = n0 + wn + nt*8 + 2*tg;
                float v0 = acc[mt][nt][2*h + 0] + bi[cc];
                float v1 = acc[mt][nt][2*h + 1] + bi[cc + 1];
                if (GELU) {
                    v0 = 0.5f*v0*(1.f + erff(v0*0.70710678118f));
                    v1 = 0.5f*v1*(1.f + erff(v1*0.70710678118f));
                }
                if (RES) {
                    v0 += res[(size_t)gr*N + cc];
                    v1 += res[(size_t)gr*N + cc + 1];
                }
                if (OUTBF)
                    *(uint32_t*)&((bf16*)Cv)[(size_t)gr*N + cc] = packbf2(v0, v1);
                else
                    *(float2*)&((float*)Cv)[(size_t)gr*N + cc] = make_float2(v0, v1);
            }
        }
    }
}

// -------- tensor-core flash attention (tf32, 3-stage x 32-row KV tiles) ----
// grid (L/64, H, B), 128 threads = 4 warps; each warp owns 16 Q rows.
#define AST 68
#define VST 72
#define KVT 32
#define NT3 (Ll/KVT)   // 64 tiles
#define ATT_SMEM ((3*KVT*AST + 3*KVT*VST + 64*AST)*4 + 128)

__global__ __launch_bounds__(128) void flash_attn_tc(
    const float* __restrict__ qkv, const unsigned char* __restrict__ mask,
    bf16* __restrict__ ao)
{
    extern __shared__ uint32_t dsm[];
    uint32_t* Ks = dsm;                          // [3][32][AST]
    uint32_t* Vs = dsm + 3*KVT*AST;              // [3][32][VST]
    uint32_t* Ps = dsm + 3*KVT*AST + 3*KVT*VST;  // [64][AST] (Q stage, then P)
    unsigned char* smask = (unsigned char*)(Ps + 64*AST);   // [3][32]

    int b = blockIdx.z, h = blockIdx.y, qt = blockIdx.x;
    int tid = threadIdx.x;
    int lane = tid & 31, wid = tid >> 5;
    int g = lane >> 2, tg = lane & 3;
    int wm = wid * 16;
    int t0 = b*Ll + qt*64;

    uint32_t sbase = (uint32_t)__cvta_generic_to_shared(dsm);
    uint32_t ks_b = sbase;
    uint32_t vs_b = sbase + 3*KVT*AST*4;
    uint32_t ps_b = sbase + (3*KVT*AST + 3*KVT*VST)*4;
    uint32_t mk_b = ps_b + 64*AST*4;

    auto stageKV = [&](int u, int s) {
        int base_t = b*Ll + u*KVT;
        #pragma unroll
        for (int p = 0; p < 4; p++) {
            int idx = p*128 + tid;
            int r = idx >> 4, c = (idx & 15) * 4;
            size_t gb = (size_t)(base_t + r)*QKV3 + h*DHd + c;
            cpasync16(ks_b + (((s*KVT) + r)*AST + c)*4u, &qkv[gb + Dm]);
            cpasync16(vs_b + (((s*KVT) + r)*VST + c)*4u, &qkv[gb + 2*Dm]);
        }
        if (tid < 2)
            cpasync16(mk_b + (uint32_t)(s*KVT + tid*16), &mask[base_t + tid*16]);
        cpcommit();
    };

    // group 0 = Q stage + KV tile 0; group 1 = KV tile 1
    #pragma unroll
    for (int p = 0; p < 8; p++) {
        int idx = p*128 + tid;
        int r = idx >> 4, c = (idx & 15) * 4;
        cpasync16(ps_b + (r*AST + c)*4u, &qkv[(size_t)(t0+r)*QKV3 + h*DHd + c]);
    }
    stageKV(0, 0);
    stageKV(1, 1);

    uint32_t qf[8][4];
    float oacc[8][4];
    #pragma unroll
    for (int nt = 0; nt < 8; nt++)
        #pragma unroll
        for (int q = 0; q < 4; q++) oacc[nt][q] = 0.f;
    float m0 = -1e30f, m1 = -1e30f, l0 = 0.f, l1 = 0.f;

    for (int u = 0; u < NT3; u++) {
        int s = u % 3;
        cpwait<1>();           // KV tile u complete; tile u+1 may pend
        __syncthreads();       // also: all warps done with buffer (u-1)%3
        if (u + 2 < NT3) stageKV(u + 2, (u + 2) % 3);
        else cpcommit();       // keep group counting aligned

        if (u == 0) {
            #pragma unroll
            for (int ks = 0; ks < 8; ks++) {
                int k0 = ks*8;
                qf[ks][0] = Ps[(wm+g)*AST + k0 + tg];
                qf[ks][1] = Ps[(wm+g+8)*AST + k0 + tg];
                qf[ks][2] = Ps[(wm+g)*AST + k0 + 4 + tg];
                qf[ks][3] = Ps[(wm+g+8)*AST + k0 + 4 + tg];
            }
            __syncwarp();
        }

        // ---- S = Q K^T   (16 x 32 per warp)
        float sacc[4][4];
        #pragma unroll
        for (int nt = 0; nt < 4; nt++)
            #pragma unroll
            for (int q = 0; q < 4; q++) sacc[nt][q] = 0.f;
        #pragma unroll
        for (int ks = 0; ks < 8; ks++) {
            int k0 = ks*8;
            #pragma unroll
            for (int nt = 0; nt < 4; nt++) {
                uint32_t bf[2];
                bf[0] = Ks[(s*KVT + nt*8+g)*AST + k0 + tg];
                bf[1] = Ks[(s*KVT + nt*8+g)*AST + k0 + 4 + tg];
                mma_tf32(sacc[nt], qf[ks], bf);
            }
        }

        // ---- online softmax
        float mx0 = -1e30f, mx1 = -1e30f;
        #pragma unroll
        for (int nt = 0; nt < 4; nt++) {
            #pragma unroll
            for (int j = 0; j < 2; j++) {
                int c = nt*8 + 2*tg + j;
                bool mk = smask[s*KVT + c] != 0;
                float s0 = mk ? -1e9f : sacc[nt][j]   * 0.125f;
                float s1 = mk ? -1e9f : sacc[nt][2+j] * 0.125f;
                sacc[nt][j] = s0; sacc[nt][2+j] = s1;
                mx0 = fmaxf(mx0, s0); mx1 = fmaxf(mx1, s1);
            }
        }
        mx0 = fmaxf(mx0, __shfl_xor_sync(0xffffffffu, mx0, 1));
        mx0 = fmaxf(mx0, __shfl_xor_sync(0xffffffffu, mx0, 2));
        mx1 = fmaxf(mx1, __shfl_xor_sync(0xffffffffu, mx1, 1));
        mx1 = fmaxf(mx1, __shfl_xor_sync(0xffffffffu, mx1, 2));
        float nm0 = fmaxf(m0, mx0), nm1 = fmaxf(m1, mx1);
        float corr0 = __expf(m0 - nm0), corr1 = __expf(m1 - nm1);
        m0 = nm0; m1 = nm1;
        float ls0 = 0.f, ls1 = 0.f;
        #pragma unroll
        for (int nt = 0; nt < 4; nt++) {
            float p00 = __expf(sacc[nt][0] - m0);
            float p01 = __expf(sacc[nt][1] - m0);
            float p10 = __expf(sacc[nt][2] - m1);
            float p11 = __expf(sacc[nt][3] - m1);
            ls0 += p00 + p01; ls1 += p10 + p11;
            *(uint2*)&Ps[(wm+g)*AST   + nt*8 + 2*tg] =
                make_uint2(__float_as_uint(p00), __float_as_uint(p01));
            *(uint2*)&Ps[(wm+g+8)*AST + nt*8 + 2*tg] =
                make_uint2(__float_as_uint(p10), __float_as_uint(p11));
        }
        ls0 += __shfl_xor_sync(0xffffffffu, ls0, 1);
        ls0 += __shfl_xor_sync(0xffffffffu, ls0, 2);
        ls1 += __shfl_xor_sync(0xffffffffu, ls1, 1);
        ls1 += __shfl_xor_sync(0xffffffffu, ls1, 2);
        l0 = l0*corr0 + ls0;
        l1 = l1*corr1 + ls1;
        #pragma unroll
        for (int nt = 0; nt < 8; nt++) {
            oacc[nt][0] *= corr0; oacc[nt][1] *= corr0;
            oacc[nt][2] *= corr1; oacc[nt][3] *= corr1;
        }
        __syncwarp();

        // ---- O += P V   (P: 16x32, V: 32x64)
        #pragma unroll
        for (int ks = 0; ks < 4; ks++) {
            int k0 = ks*8;
            uint32_t af[4];
            af[0] = Ps[(wm+g)*AST + k0 + tg];
            af[1] = Ps[(wm+g+8)*AST + k0 + tg];
            af[2] = Ps[(wm+g)*AST + k0 + 4 + tg];
            af[3] = Ps[(wm+g+8)*AST + k0 + 4 + tg];
            #pragma unroll
            for (int nt = 0; nt < 8; nt++) {
                uint32_t bf[2];
                bf[0] = Vs[(s*KVT + k0+tg)*VST   + nt*8 + g];
                bf[1] = Vs[(s*KVT + k0+tg+4)*VST + nt*8 + g];
                mma_tf32(oacc[nt], af, bf);
            }
        }
    }

    float inv0 = 1.f / l0, inv1 = 1.f / l1;
    int r0 = t0 + wm + g, r1 = r0 + 8;
    #pragma unroll
    for (int nt = 0; nt < 8; nt++) {
        int c = nt*8 + 2*tg;
        *(uint32_t*)&ao[(size_t)r0*Dm + h*DHd + c] =
            packbf2(oacc[nt][0]*inv0, oacc[nt][1]*inv0);
        *(uint32_t*)&ao[(size_t)r1*Dm + h*DHd + c] =
            packbf2(oacc[nt][2]*inv1, oacc[nt][3]*inv1);
    }
}

// ------------------------------------------------------------------- gating
__global__ __launch_bounds__(256) void gate_kernel(
    const float* __restrict__ xn2, const float* __restrict__ Wg,
    const float* __restrict__ bg)
{
    int t = blockIdx.x*8 + (threadIdx.x >> 5);
    int lane = threadIdx.x & 31;
    const float* xr = xn2 + (size_t)t*Dm;
    float part[Ee] = {};
    for (int d = lane; d < Dm; d += 32) {
        float xv = xr[d];
        const float4* wr = (const float4*)(Wg + (size_t)d*Ee);
        float4 w0 = wr[0], w1 = wr[1];
        part[0] += xv*w0.x; part[1] += xv*w0.y;
        part[2] += xv*w0.z; part[3] += xv*w0.w;
        part[4] += xv*w1.x; part[5] += xv*w1.y;
        part[6] += xv*w1.z; part[7] += xv*w1.w;
    }
    #pragma unroll
    for (int e = 0; e < Ee; e++) {
        part[e] += __shfl_xor_sync(0xffffffffu, part[e], 16);
        part[e] += __shfl_xor_sync(0xffffffffu, part[e], 8);
        part[e] += __shfl_xor_sync(0xffffffffu, part[e], 4);
        part[e] += __shfl_xor_sync(0xffffffffu, part[e], 2);
        part[e] += __shfl_xor_sync(0xffffffffu, part[e], 1);
    }
    if (lane == 0) {
        float logits[Ee];
        #pragma unroll
        for (int e = 0; e < Ee; e++) logits[e] = part[e] + bg[e];
        float mx = -1e30f;
        #pragma unroll
        for (int e = 0; e < Ee; e++) mx = fmaxf(mx, logits[e]);
        float p[Ee], se = 0.f;
        #pragma unroll
        for (int e = 0; e < Ee; e++) { p[e] = expf(logits[e]-mx); se += p[e]; }
        float isz = 1.f/se;
        #pragma unroll
        for (int e = 0; e < Ee; e++) { p[e] *= isz; g_probs[t*Ee+e] = p[e]; }
        int i0 = 0;
        #pragma unroll
        for (int e = 1; e < Ee; e++) if (p[e] > p[i0]) i0 = e;
        int i1 = (i0 == 0) ? 1 : 0;
        #pragma unroll
        for (int e = 0; e < Ee; e++) if (e != i0 && p[e] > p[i1]) i1 = e;
        float v0 = p[i0], v1 = p[i1], s01 = v0 + v1;
        g_idx[2*t]   = i0; g_idx[2*t+1] = i1;
        g_wts[2*t]   = v0/s01; g_wts[2*t+1] = v1/s01;
        atomicAdd(&g_counts[i0], 1);
        atomicAdd(&g_counts[i1], 1);
    }
}

__global__ void offsets_kernel() {
    if (threadIdx.x == 0) {
        int o = 0;
        for (int e = 0; e < Ee; e++) { g_offsets[e] = o; o += g_counts[e]; }
        g_offsets[Ee] = o;
    }
}

__global__ void scatter_kernel() {
    int a = blockIdx.x*blockDim.x + threadIdx.x;
    if (a < NASS) {
        int e = g_idx[a];
        int pos = g_offsets[e] + atomicAdd(&g_fill[e], 1);
        g_assign_row[pos] = a >> 1;
        g_pos_of[a] = pos;
    }
}

// ------------------------------------------------------ combine + moe loss
__global__ __launch_bounds__(256) void combine_kernel(float* __restrict__ out) {
    int t = blockIdx.x, tid = threadIdx.x;
    int p0 = g_pos_of[2*t], p1 = g_pos_of[2*t+1];
    float w0 = g_wts[2*t], w1 = g_wts[2*t+1];
    const float* e0 = g_eo + (size_t)p0*Dm;
    const float* e1 = g_eo + (size_t)p1*Dm;
    const float* xr = g_x1 + (size_t)t*Dm;
    float* orow = out + (size_t)t*Dm;
    for (int d = tid; d < Dm; d += 256)
        orow[d] = xr[d] + w0*e0[d] + w1*e1[d];
}

__global__ __launch_bounds__(256) void mece_kernel() {
    int e = blockIdx.x, tid = threadIdx.x;
    float s = 0.f, c = 0.f;
    for (int t = tid; t < Tt; t += 256) s += g_probs[t*Ee + e];
    for (int a = tid; a < NASS; a += 256) c += (g_idx[a] == e) ? 1.f : 0.f;
    __shared__ float sh1[256], sh2[256];
    sh1[tid] = s; sh2[tid] = c; __syncthreads();
    for (int st = 128; st > 0; st >>= 1) {
        if (tid < st) { sh1[tid] += sh1[tid+st]; sh2[tid] += sh2[tid+st]; }
        __syncthreads();
    }
    if (tid == 0) { g_me[e] = sh1[0]*(1.f/Tt); g_ce[e] = sh2[0]*(1.f/Tt); }
}

__global__ void loss_kernel(float* __restrict__ out, int out_size) {
    if (threadIdx.x == 0 && out_size > Tt*Dm) {
        float L = 0.f;
        for (int e = 0; e < Ee; e++) L += g_me[e]*g_ce[e];
        out[Tt*Dm] = (float)Ee * L;
    }
}

// ------------------------------------------------------------------ driver
extern "C" void kernel_launch(void* const* d_in, const int* in_sizes, int n_in,
                              void* d_out, int out_size)
{
    const float* x     = (const float*)d_in[0];
    const unsigned char* mask = (const unsigned char*)d_in[1];
    const float* ln1_g = (const float*)d_in[2];
    const float* ln1_b = (const float*)d_in[3];
    const float* Wqkv  = (const float*)d_in[4];
    const float* bqkv  = (const float*)d_in[5];
    const float* Wo    = (const float*)d_in[6];
    const float* bo    = (const float*)d_in[7];
    const float* ln2_g = (const float*)d_in[8];
    const float* ln2_b = (const float*)d_in[9];
    const float* Wg    = (const float*)d_in[10];
    const float* bg    = (const float*)d_in[11];
    const float* W1    = (const float*)d_in[12];
    const float* b1    = (const float*)d_in[13];
    const float* W2    = (const float*)d_in[14];
    const float* b2    = (const float*)d_in[15];
    float* out = (float*)d_out;

    float *qkv, *x1, *xn2, *eobuf;
    bf16 *wqkvb, *wob, *w1b, *w2b, *xn1b, *xn2b, *aob, *hb;
    cudaGetSymbolAddress((void**)&qkv,   g_qkv);
    cudaGetSymbolAddress((void**)&x1,    g_x1);
    cudaGetSymbolAddress((void**)&xn2,   g_xn2);
    cudaGetSymbolAddress((void**)&eobuf, g_eo);
    cudaGetSymbolAddress((void**)&wqkvb, g_wqkv_bf);
    cudaGetSymbolAddress((void**)&wob,   g_wo_bf);
    cudaGetSymbolAddress((void**)&w1b,   g_w1_bf);
    cudaGetSymbolAddress((void**)&w2b,   g_w2_bf);
    cudaGetSymbolAddress((void**)&xn1b,  g_xn1b);
    cudaGetSymbolAddress((void**)&xn2b,  g_xn2b);
    cudaGetSymbolAddress((void**)&aob,   g_aob);
    cudaGetSymbolAddress((void**)&hb,    g_hb);

    static bool attr_set = false;
    if (!attr_set) {
        cudaFuncSetAttribute(flash_attn_tc,
                             cudaFuncAttributeMaxDynamicSharedMemorySize, ATT_SMEM);
        cudaFuncSetAttribute(mma_gemm_bf16<0,0,0,0,0,0>,
                             cudaFuncAttributeMaxDynamicSharedMemorySize, GEMM_SMEM);
        cudaFuncSetAttribute(mma_gemm_bf16<0,0,0,1,0,0>,
                             cudaFuncAttributeMaxDynamicSharedMemorySize, GEMM_SMEM);
        cudaFuncSetAttribute(mma_gemm_bf16<1,1,1,0,1,1>,
                             cudaFuncAttributeMaxDynamicSharedMemorySize, GEMM_SMEM);
        cudaFuncSetAttribute(mma_gemm_bf16<0,1,0,0,1,0>,
                             cudaFuncAttributeMaxDynamicSharedMemorySize, GEMM_SMEM);
        attr_set = true;
    }

    init_kernel<<<1, 32>>>();

    // weight conversions (per launch; deterministic)
    f2bf_kernel<<<(QKV3*Dm)/2048, 256>>>(Wqkv, wqkvb);
    f2bf_kernel<<<(Dm*Dm)/2048, 256>>>(Wo, wob);
    f2bf_kernel<<<(Ee*Dm*HIDm)/2048, 256>>>(W1, w1b);
    f2bf_kernel<<<(Ee*HIDm*Dm)/2048, 256>>>(W2, w2b);

    // LN1 -> QKV GEMM
    ln_kernel<0><<<Tt, 256>>>(x, ln1_g, ln1_b, xn1b, nullptr);
    mma_gemm_bf16<0,0,0,0,0,0><<<dim3(QKV3/BN, Tt/BM), 256, GEMM_SMEM>>>(
        xn1b, wqkvb, bqkv, nullptr, qkv, Tt, QKV3, Dm);

    // attention (tf32 tensor-core flash) -> bf16 ao
    flash_attn_tc<<<dim3(Ll/64, Hh, Bb), 128, ATT_SMEM>>>(qkv, mask, aob);

    // output proj + residual (fp32 out)
    mma_gemm_bf16<0,0,0,1,0,0><<<dim3(Dm/BN, Tt/BM), 256, GEMM_SMEM>>>(
        aob, wob, bo, x, x1, Tt, Dm, Dm);

    // LN2 (fp32 for gate + bf16 for MoE) -> gate -> routing
    ln_kernel<1><<<Tt, 256>>>(x1, ln2_g, ln2_b, xn2b, xn2);
    gate_kernel<<<Tt/8, 256>>>(xn2, Wg, bg);
    offsets_kernel<<<1, 32>>>();
    scatter_kernel<<<(NASS+255)/256, 256>>>();

    // sparse MoE: up (gather + GELU, NN, bf16 out), down (NN, fp32 out)
    mma_gemm_bf16<1,1,1,0,1,1><<<dim3(HIDm/BN, NASS/BM, Ee), 256, GEMM_SMEM>>>(
        xn2b, w1b, b1, nullptr, hb, Tt, HIDm, Dm);
    mma_gemm_bf16<0,1,0,0,1,0><<<dim3(Dm/BN, NASS/BM, Ee), 256, GEMM_SMEM>>>(
        hb, w2b, b2, nullptr, eobuf, Tt, Dm, HIDm);

    // combine + aux loss
    combine_kernel<<<Tt, 256>>>(out);
    mece_kernel<<<Ee, 256>>>();
    loss_kernel<<<1, 32>>>(out, out_size);
}

// round 8
// speedup vs baseline: 7.6750x; 1.0178x over previous
#include <cuda_runtime.h>
#include <cuda_bf16.h>
#include <math.h>
#include <stdint.h>

// Problem constants
#define Dm    1024
#define Hh    16
#define DHd   64
#define Ee    8
#define HIDm  2048
#define TOPKk 2
#define Bb    2
#define Ll    2048
#define Tt    4096          // B*L
#define QKV3  3072
#define NASS  (Tt*TOPKk)

typedef __nv_bfloat16 bf16;

// ---------------- scratch (static device memory) ---------------------------
__device__ float g_qkv [Tt*QKV3];
__device__ float g_x1  [Tt*Dm];
__device__ float g_xn2 [Tt*Dm];
__device__ float g_probs[Tt*Ee];
__device__ int   g_idx [NASS];
__device__ float g_wts [NASS];
__device__ int   g_counts[Ee];
__device__ int   g_offsets[Ee+1];
__device__ int   g_fill[Ee];
__device__ int   g_assign_row[NASS];
__device__ int   g_pos_of[NASS];
__device__ float g_eo [(size_t)NASS*Dm];
__device__ float g_me [Ee];
__device__ float g_ce [Ee];
// bf16 operand buffers
__device__ bf16  g_wqkv_bf[QKV3*Dm];
__device__ bf16  g_wo_bf  [Dm*Dm];
__device__ bf16  g_w1_bf  [(size_t)Ee*Dm*HIDm];
__device__ bf16  g_w2_bf  [(size_t)Ee*HIDm*Dm];
__device__ bf16  g_xn1b   [Tt*Dm];
__device__ bf16  g_xn2b   [Tt*Dm];
__device__ bf16  g_aob    [Tt*Dm];
__device__ bf16  g_hb     [(size_t)NASS*HIDm];

// ---------------------------------------------------------------- helpers
__device__ __forceinline__ uint32_t packbf2(float a, float b) {
    __nv_bfloat162 h = __floats2bfloat162_rn(a, b);
    return *reinterpret_cast<uint32_t*>(&h);
}
__device__ __forceinline__ void mma_tf32(float* c, const uint32_t* a, const uint32_t* b) {
    asm volatile(
        "mma.sync.aligned.m16n8k8.row.col.f32.tf32.tf32.f32 "
        "{%0,%1,%2,%3}, {%4,%5,%6,%7}, {%8,%9}, {%0,%1,%2,%3};"
        : "+f"(c[0]), "+f"(c[1]), "+f"(c[2]), "+f"(c[3])
        : "r"(a[0]), "r"(a[1]), "r"(a[2]), "r"(a[3]), "r"(b[0]), "r"(b[1]));
}
__device__ __forceinline__ void mma_bf16(float* c, const uint32_t* a, const uint32_t* b) {
    asm volatile(
        "mma.sync.aligned.m16n8k16.row.col.f32.bf16.bf16.f32 "
        "{%0,%1,%2,%3}, {%4,%5,%6,%7}, {%8,%9}, {%0,%1,%2,%3};"
        : "+f"(c[0]), "+f"(c[1]), "+f"(c[2]), "+f"(c[3])
        : "r"(a[0]), "r"(a[1]), "r"(a[2]), "r"(a[3]), "r"(b[0]), "r"(b[1]));
}
__device__ __forceinline__ void ldm_x4(uint32_t* r, uint32_t addr) {
    asm volatile("ldmatrix.sync.aligned.m8n8.x4.shared.b16 {%0,%1,%2,%3}, [%4];"
        : "=r"(r[0]), "=r"(r[1]), "=r"(r[2]), "=r"(r[3]) : "r"(addr));
}
__device__ __forceinline__ void ldm_x4_t(uint32_t* r, uint32_t addr) {
    asm volatile("ldmatrix.sync.aligned.m8n8.x4.trans.shared.b16 {%0,%1,%2,%3}, [%4];"
        : "=r"(r[0]), "=r"(r[1]), "=r"(r[2]), "=r"(r[3]) : "r"(addr));
}
__device__ __forceinline__ void cpasync16(uint32_t dst, const void* src) {
    asm volatile("cp.async.cg.shared.global [%0], [%1], 16;" :: "r"(dst), "l"(src));
}
__device__ __forceinline__ void cpcommit() {
    asm volatile("cp.async.commit_group;");
}
template<int N> __device__ __forceinline__ void cpwait() {
    asm volatile("cp.async.wait_group %0;" :: "n"(N));
}

// ---------------------------------------------------------------- utilities
__global__ void init_kernel() {
    int i = threadIdx.x;
    if (i < Ee) { g_counts[i] = 0; g_fill[i] = 0; }
}

__global__ __launch_bounds__(256) void f2bf_kernel(
    const float* __restrict__ in, bf16* __restrict__ out)
{
    int i = (blockIdx.x*256 + threadIdx.x)*8;
    float4 a = *(const float4*)(in+i);
    float4 b = *(const float4*)(in+i+4);
    uint4 u;
    u.x = packbf2(a.x,a.y); u.y = packbf2(a.z,a.w);
    u.z = packbf2(b.x,b.y); u.w = packbf2(b.z,b.w);
    *(uint4*)&out[i] = u;
}

template<int WF32>
__global__ __launch_bounds__(256) void ln_kernel(
    const float* __restrict__ x, const float* __restrict__ g,
    const float* __restrict__ b, bf16* __restrict__ outb,
    float* __restrict__ outf)
{
    int t = blockIdx.x, tid = threadIdx.x;
    const float* xr = x + (size_t)t*Dm;
    float s = 0.f, s2 = 0.f;
    for (int d = tid; d < Dm; d += 256) { float v = xr[d]; s += v; s2 += v*v; }
    __shared__ float sh1[256], sh2[256];
    sh1[tid] = s; sh2[tid] = s2; __syncthreads();
    for (int st = 128; st > 0; st >>= 1) {
        if (tid < st) { sh1[tid] += sh1[tid+st]; sh2[tid] += sh2[tid+st]; }
        __syncthreads();
    }
    float mu  = sh1[0] * (1.f/Dm);
    float var = sh2[0] * (1.f/Dm) - mu*mu;
    float inv = rsqrtf(var + 1e-5f);
    for (int d = tid*2; d < Dm; d += 512) {
        float v0 = (xr[d]-mu)*inv*g[d] + b[d];
        float v1 = (xr[d+1]-mu)*inv*g[d+1] + b[d+1];
        *(uint32_t*)&outb[(size_t)t*Dm + d] = packbf2(v0, v1);
        if (WF32) *(float2*)&outf[(size_t)t*Dm + d] = make_float2(v0, v1);
    }
}

// -------------------- tensor-core GEMM (bf16, 4-stage cp.async, 1 bar/iter)
#define BM 128
#define BN 128
#define BK 32
#define ASTW 20
#define BSTW 68
#define GST  4
#define A_STG (BM*ASTW)
#define B_STG (BM*ASTW)
#define GEMM_SMEM ((GST*(A_STG + B_STG))*4)

template<int GATHER, int TRANSB, int GELU, int RES, int MOE, int OUTBF>
__global__ __launch_bounds__(256) void mma_gemm_bf16(
    const bf16* __restrict__ A, const bf16* __restrict__ Bmat,
    const float* __restrict__ bias, const float* __restrict__ res,
    void* __restrict__ Cv, int M, int N, int K)
{
    extern __shared__ uint32_t gsm[];
    __shared__ int rowsrc[BM];

    int e = MOE ? blockIdx.z : 0;
    int cnt = M, off = 0;
    if (MOE) {
        cnt = g_counts[e]; off = g_offsets[e];
        if ((int)blockIdx.y * BM >= cnt) return;
    }
    int m0 = blockIdx.y * BM;
    int n0 = blockIdx.x * BN;
    int tid = threadIdx.x;

    const bf16* Bbase = Bmat + (size_t)e * K * N;
    const float* bi   = bias + (size_t)e * N;

    if (tid < BM) {
        int lr = m0 + tid;
        int r;
        if (MOE) {
            int l = lr < cnt ? lr : cnt - 1;
            r = GATHER ? g_assign_row[off + l] : (off + l);
        } else r = lr;
        rowsrc[tid] = r;
    }
    __syncthreads();

    int lane = tid & 31;
    int wid  = tid >> 5;
    int wm = (wid >> 2) * 64;
    int wn = (wid & 3) * 32;
    int g  = lane >> 2;
    int tg = lane & 3;

    uint32_t as_base = (uint32_t)__cvta_generic_to_shared(gsm);
    uint32_t bs_base = as_base + GST*A_STG*4u;
    int a_row  = (lane & 7) + ((lane >> 3) & 1) * 8;
    int a_colw = (lane >> 4) * 4;
    int b_nt_sub = (lane >> 4) & 1;
    int b_row  = (lane & 7);
    int b_colw = ((lane >> 3) & 1) * 4;
    int jj = lane >> 3;
    int nn_krow = (lane & 7) + 8*(jj & 1);
    int nn_ncol = 8*(jj >> 1);

    float acc[4][4][4];
    #pragma unroll
    for (int i = 0; i < 4; i++)
        #pragma unroll
        for (int j = 0; j < 4; j++)
            #pragma unroll
            for (int q = 0; q < 4; q++) acc[i][j][q] = 0.f;

    auto stageAB = [&](int k0, int s) {
        #pragma unroll
        for (int p = 0; p < 2; p++) {
            int idx = p*256 + tid;
            int r = idx >> 2, c = idx & 3;
            const bf16* src = A + (size_t)rowsrc[r]*K + k0 + c*8;
            cpasync16(as_base + (((s*BM + r)*ASTW) + c*4)*4u, src);
        }
        if (!TRANSB) {
            #pragma unroll
            for (int p = 0; p < 2; p++) {
                int idx = p*256 + tid;
                int r = idx >> 2, c = idx & 3;
                const bf16* src = Bbase + (size_t)(n0 + r)*K + k0 + c*8;
                cpasync16(bs_base + (((s*BM + r)*ASTW) + c*4)*4u, src);
            }
        } else {
            #pragma unroll
            for (int p = 0; p < 2; p++) {
                int idx = p*256 + tid;
                int kr = idx >> 4, c = idx & 15;
                const bf16* src = Bbase + (size_t)(k0 + kr)*N + n0 + c*8;
                cpasync16(bs_base + (((s*32 + kr)*BSTW) + c*4)*4u, src);
            }
        }
    };

    auto compute = [&](int s) {
        #pragma unroll
        for (int ks = 0; ks < 2; ks++) {
            int k0w = ks * 8;
            uint32_t af[4][4];
            #pragma unroll
            for (int mt = 0; mt < 4; mt++) {
                uint32_t addr = as_base +
                    ((s*BM + wm + mt*16 + a_row)*ASTW + k0w + a_colw) * 4u;
                ldm_x4(af[mt], addr);
            }
            uint32_t bf[2][4];
            if (!TRANSB) {
                #pragma unroll
                for (int ntp = 0; ntp < 2; ntp++) {
                    int nrow = wn + (2*ntp + b_nt_sub)*8 + b_row;
                    uint32_t addr = bs_base + ((s*BN + nrow)*ASTW + k0w + b_colw) * 4u;
                    ldm_x4(bf[ntp], addr);
                }
            } else {
                int krow = s*32 + ks*16 + nn_krow;
                #pragma unroll
                for (int ntp = 0; ntp < 2; ntp++) {
                    uint32_t addr = bs_base + (uint32_t)(krow*BSTW)*4u
                                  + (uint32_t)(wn + ntp*16 + nn_ncol)*2u;
                    ldm_x4_t(bf[ntp], addr);
                }
            }
            #pragma unroll
            for (int mt = 0; mt < 4; mt++) {
                #pragma unroll
                for (int nt = 0; nt < 4; nt++) {
                    const uint32_t* bb = &bf[nt >> 1][(nt & 1) * 2];
                    mma_bf16(acc[mt][nt], af[mt], bb);
                }
            }
        }
    };

    int KT = K / BK;
    stageAB(0, 0);      cpcommit();
    stageAB(BK, 1);     cpcommit();
    stageAB(2*BK, 2);   cpcommit();
    for (int t = 0; t < KT; t++) {
        cpwait<2>();
        __syncthreads();
        if (t + 3 < KT) stageAB((t+3)*BK, (t+3) & 3);
        cpcommit();
        compute(t & 3);
    }

    #pragma unroll
    for (int mt = 0; mt < 4; mt++) {
        #pragma unroll
        for (int h = 0; h < 2; h++) {
            int lr = m0 + wm + mt*16 + g + 8*h;
            if (MOE && lr >= cnt) continue;
            int gr = MOE ? (off + lr) : lr;
            #pragma unroll
            for (int nt = 0; nt < 4; nt++) {
                int cc = n0 + wn + nt*8 + 2*tg;
                float v0 = acc[mt][nt][2*h + 0] + bi[cc];
                float v1 = acc[mt][nt][2*h + 1] + bi[cc + 1];
                if (GELU) {
                    v0 = 0.5f*v0*(1.f + erff(v0*0.70710678118f));
                    v1 = 0.5f*v1*(1.f + erff(v1*0.70710678118f));
                }
                if (RES) {
                    v0 += res[(size_t)gr*N + cc];
                    v1 += res[(size_t)gr*N + cc + 1];
                }
                if (OUTBF)
                    *(uint32_t*)&((bf16*)Cv)[(size_t)gr*N + cc] = packbf2(v0, v1);
                else
                    *(float2*)&((float*)Cv)[(size_t)gr*N + cc] = make_float2(v0, v1);
            }
        }
    }
}

// ------ tensor-core flash attention (tf32, 128 Q rows, 3-stage 32-row KV) --
// grid (L/128, H, B), 256 threads = 8 warps; each warp owns 16 Q rows.
#define AST 68
#define VST 72
#define PST 36
#define KVT 32
#define NT3 (Ll/KVT)   // 64 tiles
#define ATT_SMEM ((3*KVT*AST + 3*KVT*VST + 128*PST)*4 + 128)

__global__ __launch_bounds__(256, 2) void flash_attn_tc(
    const float* __restrict__ qkv, const unsigned char* __restrict__ mask,
    bf16* __restrict__ ao)
{
    extern __shared__ uint32_t dsm[];
    uint32_t* Ks = dsm;                          // [3][32][AST]
    uint32_t* Vs = dsm + 3*KVT*AST;              // [3][32][VST]
    uint32_t* Ps = dsm + 3*KVT*AST + 3*KVT*VST;  // [128][PST]
    unsigned char* smask = (unsigned char*)(Ps + 128*PST);  // [3][32]

    int b = blockIdx.z, h = blockIdx.y, qt = blockIdx.x;
    int tid = threadIdx.x;
    int lane = tid & 31, wid = tid >> 5;
    int g = lane >> 2, tg = lane & 3;
    int wm = wid * 16;
    int t0 = b*Ll + qt*128;

    uint32_t sbase = (uint32_t)__cvta_generic_to_shared(dsm);
    uint32_t ks_b = sbase;
    uint32_t vs_b = sbase + 3*KVT*AST*4;
    uint32_t ps_b = vs_b + 3*KVT*VST*4;
    uint32_t mk_b = ps_b + 128*PST*4;

    auto stageKV = [&](int u, int s) {
        int base_t = b*Ll + u*KVT;
        #pragma unroll
        for (int p = 0; p < 2; p++) {
            int idx = p*256 + tid;
            int r = idx >> 4, c = (idx & 15) * 4;
            size_t gb = (size_t)(base_t + r)*QKV3 + h*DHd + c;
            cpasync16(ks_b + (((s*KVT) + r)*AST + c)*4u, &qkv[gb + Dm]);
            cpasync16(vs_b + (((s*KVT) + r)*VST + c)*4u, &qkv[gb + 2*Dm]);
        }
        if (tid < 2)
            cpasync16(mk_b + (uint32_t)(s*KVT + tid*16), &mask[base_t + tid*16]);
        cpcommit();
    };

    stageKV(0, 0);
    stageKV(1, 1);

    // Q fragments: raw fp32 bits straight from gmem (tf32 truncation in HW)
    const uint32_t* qbits = (const uint32_t*)qkv;
    uint32_t qf[8][4];
    {
        size_t r0q = (size_t)(t0+wm+g)*QKV3 + h*DHd;
        size_t r1q = (size_t)(t0+wm+g+8)*QKV3 + h*DHd;
        #pragma unroll
        for (int ks = 0; ks < 8; ks++) {
            int k0 = ks*8;
            qf[ks][0] = qbits[r0q + k0 + tg];
            qf[ks][1] = qbits[r1q + k0 + tg];
            qf[ks][2] = qbits[r0q + k0 + 4 + tg];
            qf[ks][3] = qbits[r1q + k0 + 4 + tg];
        }
    }

    float oacc[8][4];
    #pragma unroll
    for (int nt = 0; nt < 8; nt++)
        #pragma unroll
        for (int q = 0; q < 4; q++) oacc[nt][q] = 0.f;
    float m0 = -1e30f, m1 = -1e30f, l0 = 0.f, l1 = 0.f;

    for (int u = 0; u < NT3; u++) {
        int s = u % 3;
        cpwait<1>();
        __syncthreads();
        if (u + 2 < NT3) stageKV(u + 2, (u + 2) % 3);
        else cpcommit();

        // ---- S = Q K^T  (16 x 32 per warp)
        float sacc[4][4];
        #pragma unroll
        for (int nt = 0; nt < 4; nt++)
            #pragma unroll
            for (int q = 0; q < 4; q++) sacc[nt][q] = 0.f;
        #pragma unroll
        for (int ks = 0; ks < 8; ks++) {
            int k0 = ks*8;
            #pragma unroll
            for (int nt = 0; nt < 4; nt++) {
                uint32_t bf[2];
                bf[0] = Ks[(s*KVT + nt*8+g)*AST + k0 + tg];
                bf[1] = Ks[(s*KVT + nt*8+g)*AST + k0 + 4 + tg];
                mma_tf32(sacc[nt], qf[ks], bf);
            }
        }

        // ---- online softmax
        float mx0 = -1e30f, mx1 = -1e30f;
        #pragma unroll
        for (int nt = 0; nt < 4; nt++) {
            #pragma unroll
            for (int j = 0; j < 2; j++) {
                int c = nt*8 + 2*tg + j;
                bool mk = smask[s*KVT + c] != 0;
                float s0 = mk ? -1e9f : sacc[nt][j]   * 0.125f;
                float s1 = mk ? -1e9f : sacc[nt][2+j] * 0.125f;
                sacc[nt][j] = s0; sacc[nt][2+j] = s1;
                mx0 = fmaxf(mx0, s0); mx1 = fmaxf(mx1, s1);
            }
        }
        mx0 = fmaxf(mx0, __shfl_xor_sync(0xffffffffu, mx0, 1));
        mx0 = fmaxf(mx0, __shfl_xor_sync(0xffffffffu, mx0, 2));
        mx1 = fmaxf(mx1, __shfl_xor_sync(0xffffffffu, mx1, 1));
        mx1 = fmaxf(mx1, __shfl_xor_sync(0xffffffffu, mx1, 2));
        float nm0 = fmaxf(m0, mx0), nm1 = fmaxf(m1, mx1);
        float corr0 = __expf(m0 - nm0), corr1 = __expf(m1 - nm1);
        m0 = nm0; m1 = nm1;
        float ls0 = 0.f, ls1 = 0.f;
        #pragma unroll
        for (int nt = 0; nt < 4; nt++) {
            float p00 = __expf(sacc[nt][0] - m0);
            float p01 = __expf(sacc[nt][1] - m0);
            float p10 = __expf(sacc[nt][2] - m1);
            float p11 = __expf(sacc[nt][3] - m1);
            ls0 += p00 + p01; ls1 += p10 + p11;
            *(uint2*)&Ps[(wm+g)*PST   + nt*8 + 2*tg] =
                make_uint2(__float_as_uint(p00), __float_as_uint(p01));
            *(uint2*)&Ps[(wm+g+8)*PST + nt*8 + 2*tg] =
                make_uint2(__float_as_uint(p10), __float_as_uint(p11));
        }
        ls0 += __shfl_xor_sync(0xffffffffu, ls0, 1);
        ls0 += __shfl_xor_sync(0xffffffffu, ls0, 2);
        ls1 += __shfl_xor_sync(0xffffffffu, ls1, 1);
        ls1 += __shfl_xor_sync(0xffffffffu, ls1, 2);
        l0 = l0*corr0 + ls0;
        l1 = l1*corr1 + ls1;
        #pragma unroll
        for (int nt = 0; nt < 8; nt++) {
            oacc[nt][0] *= corr0; oacc[nt][1] *= corr0;
            oacc[nt][2] *= corr1; oacc[nt][3] *= corr1;
        }
        __syncwarp();

        // ---- O += P V  (P: 16x32 per warp, V: 32x64)
        #pragma unroll
        for (int ks = 0; ks < 4; ks++) {
            int k0 = ks*8;
            uint32_t af[4];
            af[0] = Ps[(wm+g)*PST + k0 + tg];
            af[1] = Ps[(wm+g+8)*PST + k0 + tg];
            af[2] = Ps[(wm+g)*PST + k0 + 4 + tg];
            af[3] = Ps[(wm+g+8)*PST + k0 + 4 + tg];
            #pragma unroll
            for (int nt = 0; nt < 8; nt++) {
                uint32_t bf[2];
                bf[0] = Vs[(s*KVT + k0+tg)*VST   + nt*8 + g];
                bf[1] = Vs[(s*KVT + k0+tg+4)*VST + nt*8 + g];
                mma_tf32(oacc[nt], af, bf);
            }
        }
    }

    float inv0 = 1.f / l0, inv1 = 1.f / l1;
    int r0 = t0 + wm + g, r1 = r0 + 8;
    #pragma unroll
    for (int nt = 0; nt < 8; nt++) {
        int c = nt*8 + 2*tg;
        *(uint32_t*)&ao[(size_t)r0*Dm + h*DHd + c] =
            packbf2(oacc[nt][0]*inv0, oacc[nt][1]*inv0);
        *(uint32_t*)&ao[(size_t)r1*Dm + h*DHd + c] =
            packbf2(oacc[nt][2]*inv1, oacc[nt][3]*inv1);
    }
}

// ------------------------------------------------------------------- gating
__global__ __launch_bounds__(256) void gate_kernel(
    const float* __restrict__ xn2, const float* __restrict__ Wg,
    const float* __restrict__ bg)
{
    int t = blockIdx.x*8 + (threadIdx.x >> 5);
    int lane = threadIdx.x & 31;
    const float* xr = xn2 + (size_t)t*Dm;
    float part[Ee] = {};
    for (int d = lane; d < Dm; d += 32) {
        float xv = xr[d];
        const float4* wr = (const float4*)(Wg + (size_t)d*Ee);
        float4 w0 = wr[0], w1 = wr[1];
        part[0] += xv*w0.x; part[1] += xv*w0.y;
        part[2] += xv*w0.z; part[3] += xv*w0.w;
        part[4] += xv*w1.x; part[5] += xv*w1.y;
        part[6] += xv*w1.z; part[7] += xv*w1.w;
    }
    #pragma unroll
    for (int e = 0; e < Ee; e++) {
        part[e] += __shfl_xor_sync(0xffffffffu, part[e], 16);
        part[e] += __shfl_xor_sync(0xffffffffu, part[e], 8);
        part[e] += __shfl_xor_sync(0xffffffffu, part[e], 4);
        part[e] += __shfl_xor_sync(0xffffffffu, part[e], 2);
        part[e] += __shfl_xor_sync(0xffffffffu, part[e], 1);
    }
    if (lane == 0) {
        float logits[Ee];
        #pragma unroll
        for (int e = 0; e < Ee; e++) logits[e] = part[e] + bg[e];
        float mx = -1e30f;
        #pragma unroll
        for (int e = 0; e < Ee; e++) mx = fmaxf(mx, logits[e]);
        float p[Ee], se = 0.f;
        #pragma unroll
        for (int e = 0; e < Ee; e++) { p[e] = expf(logits[e]-mx); se += p[e]; }
        float isz = 1.f/se;
        #pragma unroll
        for (int e = 0; e < Ee; e++) { p[e] *= isz; g_probs[t*Ee+e] = p[e]; }
        int i0 = 0;
        #pragma unroll
        for (int e = 1; e < Ee; e++) if (p[e] > p[i0]) i0 = e;
        int i1 = (i0 == 0) ? 1 : 0;
        #pragma unroll
        for (int e = 0; e < Ee; e++) if (e != i0 && p[e] > p[i1]) i1 = e;
        float v0 = p[i0], v1 = p[i1], s01 = v0 + v1;
        g_idx[2*t]   = i0; g_idx[2*t+1] = i1;
        g_wts[2*t]   = v0/s01; g_wts[2*t+1] = v1/s01;
        atomicAdd(&g_counts[i0], 1);
        atomicAdd(&g_counts[i1], 1);
    }
}

__global__ void offsets_kernel() {
    if (threadIdx.x == 0) {
        int o = 0;
        for (int e = 0; e < Ee; e++) { g_offsets[e] = o; o += g_counts[e]; }
        g_offsets[Ee] = o;
    }
}

__global__ void scatter_kernel() {
    int a = blockIdx.x*blockDim.x + threadIdx.x;
    if (a < NASS) {
        int e = g_idx[a];
        int pos = g_offsets[e] + atomicAdd(&g_fill[e], 1);
        g_assign_row[pos] = a >> 1;
        g_pos_of[a] = pos;
    }
}

// ------------------------------------------------------ combine + moe loss
__global__ __launch_bounds__(256) void combine_kernel(float* __restrict__ out) {
    int t = blockIdx.x, tid = threadIdx.x;
    int p0 = g_pos_of[2*t], p1 = g_pos_of[2*t+1];
    float w0 = g_wts[2*t], w1 = g_wts[2*t+1];
    const float* e0 = g_eo + (size_t)p0*Dm;
    const float* e1 = g_eo + (size_t)p1*Dm;
    const float* xr = g_x1 + (size_t)t*Dm;
    float* orow = out + (size_t)t*Dm;
    for (int d = tid; d < Dm; d += 256)
        orow[d] = xr[d] + w0*e0[d] + w1*e1[d];
}

__global__ __launch_bounds__(256) void mece_kernel() {
    int e = blockIdx.x, tid = threadIdx.x;
    float s = 0.f, c = 0.f;
    for (int t = tid; t < Tt; t += 256) s += g_probs[t*Ee + e];
    for (int a = tid; a < NASS; a += 256) c += (g_idx[a] == e) ? 1.f : 0.f;
    __shared__ float sh1[256], sh2[256];
    sh1[tid] = s; sh2[tid] = c; __syncthreads();
    for (int st = 128; st > 0; st >>= 1) {
        if (tid < st) { sh1[tid] += sh1[tid+st]; sh2[tid] += sh2[tid+st]; }
        __syncthreads();
    }
    if (tid == 0) { g_me[e] = sh1[0]*(1.f/Tt); g_ce[e] = sh2[0]*(1.f/Tt); }
}

__global__ void loss_kernel(float* __restrict__ out, int out_size) {
    if (threadIdx.x == 0 && out_size > Tt*Dm) {
        float L = 0.f;
        for (int e = 0; e < Ee; e++) L += g_me[e]*g_ce[e];
        out[Tt*Dm] = (float)Ee * L;
    }
}

// ------------------------------------------------------------------ driver
extern "C" void kernel_launch(void* const* d_in, const int* in_sizes, int n_in,
                              void* d_out, int out_size)
{
    const float* x     = (const float*)d_in[0];
    const unsigned char* mask = (const unsigned char*)d_in[1];
    const float* ln1_g = (const float*)d_in[2];
    const float* ln1_b = (const float*)d_in[3];
    const float* Wqkv  = (const float*)d_in[4];
    const float* bqkv  = (const float*)d_in[5];
    const float* Wo    = (const float*)d_in[6];
    const float* bo    = (const float*)d_in[7];
    const float* ln2_g = (const float*)d_in[8];
    const float* ln2_b = (const float*)d_in[9];
    const float* Wg    = (const float*)d_in[10];
    const float* bg    = (const float*)d_in[11];
    const float* W1    = (const float*)d_in[12];
    const float* b1    = (const float*)d_in[13];
    const float* W2    = (const float*)d_in[14];
    const float* b2    = (const float*)d_in[15];
    float* out = (float*)d_out;

    float *qkv, *x1, *xn2, *eobuf;
    bf16 *wqkvb, *wob, *w1b, *w2b, *xn1b, *xn2b, *aob, *hb;
    cudaGetSymbolAddress((void**)&qkv,   g_qkv);
    cudaGetSymbolAddress((void**)&x1,    g_x1);
    cudaGetSymbolAddress((void**)&xn2,   g_xn2);
    cudaGetSymbolAddress((void**)&eobuf, g_eo);
    cudaGetSymbolAddress((void**)&wqkvb, g_wqkv_bf);
    cudaGetSymbolAddress((void**)&wob,   g_wo_bf);
    cudaGetSymbolAddress((void**)&w1b,   g_w1_bf);
    cudaGetSymbolAddress((void**)&w2b,   g_w2_bf);
    cudaGetSymbolAddress((void**)&xn1b,  g_xn1b);
    cudaGetSymbolAddress((void**)&xn2b,  g_xn2b);
    cudaGetSymbolAddress((void**)&aob,   g_aob);
    cudaGetSymbolAddress((void**)&hb,    g_hb);

    static bool attr_set = false;
    static cudaStream_t s2;
    static cudaEvent_t evF, evJ;
    if (!attr_set) {
        cudaFuncSetAttribute(flash_attn_tc,
                             cudaFuncAttributeMaxDynamicSharedMemorySize, ATT_SMEM);
        cudaFuncSetAttribute(mma_gemm_bf16<0,0,0,0,0,0>,
                             cudaFuncAttributeMaxDynamicSharedMemorySize, GEMM_SMEM);
        cudaFuncSetAttribute(mma_gemm_bf16<0,0,0,1,0,0>,
                             cudaFuncAttributeMaxDynamicSharedMemorySize, GEMM_SMEM);
        cudaFuncSetAttribute(mma_gemm_bf16<1,1,1,0,1,1>,
                             cudaFuncAttributeMaxDynamicSharedMemorySize, GEMM_SMEM);
        cudaFuncSetAttribute(mma_gemm_bf16<0,1,0,0,1,0>,
                             cudaFuncAttributeMaxDynamicSharedMemorySize, GEMM_SMEM);
        cudaStreamCreateWithFlags(&s2, cudaStreamNonBlocking);
        cudaEventCreateWithFlags(&evF, cudaEventDisableTiming);
        cudaEventCreateWithFlags(&evJ, cudaEventDisableTiming);
        attr_set = true;
    }

    init_kernel<<<1, 32>>>();

    // QKV weights converted on the main stream (needed immediately)
    f2bf_kernel<<<(QKV3*Dm)/2048, 256>>>(Wqkv, wqkvb);

    // fork: Wo/W1/W2 conversions overlap with LN1 -> QKV -> attention
    cudaEventRecord(evF, 0);
    cudaStreamWaitEvent(s2, evF, 0);
    f2bf_kernel<<<(Dm*Dm)/2048, 256, 0, s2>>>(Wo, wob);
    f2bf_kernel<<<(Ee*Dm*HIDm)/2048, 256, 0, s2>>>(W1, w1b);
    f2bf_kernel<<<(Ee*HIDm*Dm)/2048, 256, 0, s2>>>(W2, w2b);
    cudaEventRecord(evJ, s2);

    // LN1 -> QKV GEMM
    ln_kernel<0><<<Tt, 256>>>(x, ln1_g, ln1_b, xn1b, nullptr);
    mma_gemm_bf16<0,0,0,0,0,0><<<dim3(QKV3/BN, Tt/BM), 256, GEMM_SMEM>>>(
        xn1b, wqkvb, bqkv, nullptr, qkv, Tt, QKV3, Dm);

    // attention (tf32 tensor-core flash, 128-row Q tiles) -> bf16 ao
    flash_attn_tc<<<dim3(Ll/128, Hh, Bb), 256, ATT_SMEM>>>(qkv, mask, aob);

    // join: Wo/W1/W2 conversions must be done before Wo GEMM
    cudaStreamWaitEvent(0, evJ, 0);

    // output proj + residual (fp32 out)
    mma_gemm_bf16<0,0,0,1,0,0><<<dim3(Dm/BN, Tt/BM), 256, GEMM_SMEM>>>(
        aob, wob, bo, x, x1, Tt, Dm, Dm);

    // LN2 (fp32 for gate + bf16 for MoE) -> gate -> routing
    ln_kernel<1><<<Tt, 256>>>(x1, ln2_g, ln2_b, xn2b, xn2);
    gate_kernel<<<Tt/8, 256>>>(xn2, Wg, bg);
    offsets_kernel<<<1, 32>>>();
    scatter_kernel<<<(NASS+255)/256, 256>>>();

    // sparse MoE: up (gather + GELU, NN, bf16 out), down (NN, fp32 out)
    mma_gemm_bf16<1,1,1,0,1,1><<<dim3(HIDm/BN, NASS/BM, Ee), 256, GEMM_SMEM>>>(
        xn2b, w1b, b1, nullptr, hb, Tt, HIDm, Dm);
    mma_gemm_bf16<0,1,0,0,1,0><<<dim3(Dm/BN, NASS/BM, Ee), 256, GEMM_SMEM>>>(
        hb, w2b, b2, nullptr, eobuf, Tt, Dm, HIDm);

    // combine + aux loss
    combine_kernel<<<Tt, 256>>>(out);
    mece_kernel<<<Ee, 256>>>();
    loss_kernel<<<1, 32>>>(out, out_size);
}

// round 9
// speedup vs baseline: 7.7319x; 1.0074x over previous
#include <cuda_runtime.h>
#include <cuda_bf16.h>
#include <math.h>
#include <stdint.h>

// Problem constants
#define Dm    1024
#define Hh    16
#define DHd   64
#define Ee    8
#define HIDm  2048
#define TOPKk 2
#define Bb    2
#define Ll    2048
#define Tt    4096          // B*L
#define QKV3  3072
#define NASS  (Tt*TOPKk)

typedef __nv_bfloat16 bf16;

// ---------------- scratch (static device memory) ---------------------------
__device__ float g_qkv [Tt*QKV3];
__device__ float g_x1  [Tt*Dm];
__device__ float g_probs[Tt*Ee];
__device__ int   g_idx [NASS];
__device__ float g_wts [NASS];
__device__ int   g_counts[Ee];
__device__ int   g_offsets[Ee+1];
__device__ int   g_fill[Ee];
__device__ int   g_assign_row[NASS];
__device__ int   g_pos_of[NASS];
__device__ float g_eo [(size_t)NASS*Dm];
__device__ float g_me [Ee];
__device__ float g_ce [Ee];
// bf16 operand buffers
__device__ bf16  g_wqkv_bf[QKV3*Dm];
__device__ bf16  g_wo_bf  [Dm*Dm];
__device__ bf16  g_w1_bf  [(size_t)Ee*Dm*HIDm];
__device__ bf16  g_w2_bf  [(size_t)Ee*HIDm*Dm];
__device__ bf16  g_xn1b   [Tt*Dm];
__device__ bf16  g_xn2b   [Tt*Dm];
__device__ bf16  g_aob    [Tt*Dm];
__device__ bf16  g_hb     [(size_t)NASS*HIDm];

// ---------------------------------------------------------------- helpers
__device__ __forceinline__ uint32_t packbf2(float a, float b) {
    __nv_bfloat162 h = __floats2bfloat162_rn(a, b);
    return *reinterpret_cast<uint32_t*>(&h);
}
__device__ __forceinline__ void mma_tf32(float* c, const uint32_t* a, const uint32_t* b) {
    asm volatile(
        "mma.sync.aligned.m16n8k8.row.col.f32.tf32.tf32.f32 "
        "{%0,%1,%2,%3}, {%4,%5,%6,%7}, {%8,%9}, {%0,%1,%2,%3};"
        : "+f"(c[0]), "+f"(c[1]), "+f"(c[2]), "+f"(c[3])
        : "r"(a[0]), "r"(a[1]), "r"(a[2]), "r"(a[3]), "r"(b[0]), "r"(b[1]));
}
__device__ __forceinline__ void mma_bf16(float* c, const uint32_t* a, const uint32_t* b) {
    asm volatile(
        "mma.sync.aligned.m16n8k16.row.col.f32.bf16.bf16.f32 "
        "{%0,%1,%2,%3}, {%4,%5,%6,%7}, {%8,%9}, {%0,%1,%2,%3};"
        : "+f"(c[0]), "+f"(c[1]), "+f"(c[2]), "+f"(c[3])
        : "r"(a[0]), "r"(a[1]), "r"(a[2]), "r"(a[3]), "r"(b[0]), "r"(b[1]));
}
__device__ __forceinline__ void ldm_x4(uint32_t* r, uint32_t addr) {
    asm volatile("ldmatrix.sync.aligned.m8n8.x4.shared.b16 {%0,%1,%2,%3}, [%4];"
        : "=r"(r[0]), "=r"(r[1]), "=r"(r[2]), "=r"(r[3]) : "r"(addr));
}
__device__ __forceinline__ void ldm_x4_t(uint32_t* r, uint32_t addr) {
    asm volatile("ldmatrix.sync.aligned.m8n8.x4.trans.shared.b16 {%0,%1,%2,%3}, [%4];"
        : "=r"(r[0]), "=r"(r[1]), "=r"(r[2]), "=r"(r[3]) : "r"(addr));
}
__device__ __forceinline__ void cpasync16(uint32_t dst, const void* src) {
    asm volatile("cp.async.cg.shared.global [%0], [%1], 16;" :: "r"(dst), "l"(src));
}
__device__ __forceinline__ void cpcommit() {
    asm volatile("cp.async.commit_group;");
}
template<int N> __device__ __forceinline__ void cpwait() {
    asm volatile("cp.async.wait_group %0;" :: "n"(N));
}

// ---------------------------------------------------------------- utilities
__global__ void init_kernel() {
    int i = threadIdx.x;
    if (i < Ee) { g_counts[i] = 0; g_fill[i] = 0; }
}

__global__ __launch_bounds__(256) void f2bf_kernel(
    const float* __restrict__ in, bf16* __restrict__ out)
{
    int i = (blockIdx.x*256 + threadIdx.x)*8;
    float4 a = *(const float4*)(in+i);
    float4 b = *(const float4*)(in+i+4);
    uint4 u;
    u.x = packbf2(a.x,a.y); u.y = packbf2(a.z,a.w);
    u.z = packbf2(b.x,b.y); u.w = packbf2(b.z,b.w);
    *(uint4*)&out[i] = u;
}

// LN1: bf16 out only
__global__ __launch_bounds__(256) void ln_kernel(
    const float* __restrict__ x, const float* __restrict__ g,
    const float* __restrict__ b, bf16* __restrict__ outb)
{
    int t = blockIdx.x, tid = threadIdx.x;
    const float* xr = x + (size_t)t*Dm;
    float s = 0.f, s2 = 0.f;
    for (int d = tid; d < Dm; d += 256) { float v = xr[d]; s += v; s2 += v*v; }
    __shared__ float sh1[256], sh2[256];
    sh1[tid] = s; sh2[tid] = s2; __syncthreads();
    for (int st = 128; st > 0; st >>= 1) {
        if (tid < st) { sh1[tid] += sh1[tid+st]; sh2[tid] += sh2[tid+st]; }
        __syncthreads();
    }
    float mu  = sh1[0] * (1.f/Dm);
    float var = sh2[0] * (1.f/Dm) - mu*mu;
    float inv = rsqrtf(var + 1e-5f);
    for (int d = tid*2; d < Dm; d += 512) {
        float v0 = (xr[d]-mu)*inv*g[d] + b[d];
        float v1 = (xr[d+1]-mu)*inv*g[d+1] + b[d+1];
        *(uint32_t*)&outb[(size_t)t*Dm + d] = packbf2(v0, v1);
    }
}

// LN2 fused with gate: bf16 out + routing (probs, top-2, counts)
__global__ __launch_bounds__(256) void ln2_gate_kernel(
    const float* __restrict__ x, const float* __restrict__ g,
    const float* __restrict__ b, const float* __restrict__ Wg,
    const float* __restrict__ bg, bf16* __restrict__ outb)
{
    int t = blockIdx.x, tid = threadIdx.x;
    int lane = tid & 31, wid = tid >> 5;
    const float* xr = x + (size_t)t*Dm;
    float s = 0.f, s2 = 0.f;
    for (int d = tid; d < Dm; d += 256) { float v = xr[d]; s += v; s2 += v*v; }
    __shared__ float sh1[256], sh2[256];
    sh1[tid] = s; sh2[tid] = s2; __syncthreads();
    for (int st = 128; st > 0; st >>= 1) {
        if (tid < st) { sh1[tid] += sh1[tid+st]; sh2[tid] += sh2[tid+st]; }
        __syncthreads();
    }
    float mu  = sh1[0] * (1.f/Dm);
    float var = sh2[0] * (1.f/Dm) - mu*mu;
    float inv = rsqrtf(var + 1e-5f);

    // each thread owns 4 contiguous dims
    int d0 = tid*4;
    float v[4];
    #pragma unroll
    for (int j = 0; j < 4; j++)
        v[j] = (xr[d0+j]-mu)*inv*g[d0+j] + b[d0+j];
    *(uint2*)&outb[(size_t)t*Dm + d0] =
        make_uint2(packbf2(v[0], v[1]), packbf2(v[2], v[3]));

    // gate partials
    float part[Ee] = {};
    #pragma unroll
    for (int j = 0; j < 4; j++) {
        const float4* wr = (const float4*)(Wg + (size_t)(d0+j)*Ee);
        float4 w0 = wr[0], w1 = wr[1];
        part[0] += v[j]*w0.x; part[1] += v[j]*w0.y;
        part[2] += v[j]*w0.z; part[3] += v[j]*w0.w;
        part[4] += v[j]*w1.x; part[5] += v[j]*w1.y;
        part[6] += v[j]*w1.z; part[7] += v[j]*w1.w;
    }
    #pragma unroll
    for (int e = 0; e < Ee; e++) {
        part[e] += __shfl_xor_sync(0xffffffffu, part[e], 16);
        part[e] += __shfl_xor_sync(0xffffffffu, part[e], 8);
        part[e] += __shfl_xor_sync(0xffffffffu, part[e], 4);
        part[e] += __shfl_xor_sync(0xffffffffu, part[e], 2);
        part[e] += __shfl_xor_sync(0xffffffffu, part[e], 1);
    }
    __shared__ float red[8][Ee];
    if (lane == 0)
        #pragma unroll
        for (int e = 0; e < Ee; e++) red[wid][e] = part[e];
    __syncthreads();
    if (tid == 0) {
        float logits[Ee];
        #pragma unroll
        for (int e = 0; e < Ee; e++) {
            float a = 0.f;
            #pragma unroll
            for (int w = 0; w < 8; w++) a += red[w][e];
            logits[e] = a + bg[e];
        }
        float mx = -1e30f;
        #pragma unroll
        for (int e = 0; e < Ee; e++) mx = fmaxf(mx, logits[e]);
        float p[Ee], se = 0.f;
        #pragma unroll
        for (int e = 0; e < Ee; e++) { p[e] = expf(logits[e]-mx); se += p[e]; }
        float isz = 1.f/se;
        #pragma unroll
        for (int e = 0; e < Ee; e++) { p[e] *= isz; g_probs[t*Ee+e] = p[e]; }
        int i0 = 0;
        #pragma unroll
        for (int e = 1; e < Ee; e++) if (p[e] > p[i0]) i0 = e;
        int i1 = (i0 == 0) ? 1 : 0;
        #pragma unroll
        for (int e = 0; e < Ee; e++) if (e != i0 && p[e] > p[i1]) i1 = e;
        float v0 = p[i0], v1 = p[i1], s01 = v0 + v1;
        g_idx[2*t]   = i0; g_idx[2*t+1] = i1;
        g_wts[2*t]   = v0/s01; g_wts[2*t+1] = v1/s01;
        atomicAdd(&g_counts[i0], 1);
        atomicAdd(&g_counts[i1], 1);
    }
}

// -------------------- tensor-core GEMM (bf16, 4-stage cp.async, 1 bar/iter)
#define BM 128
#define BN 128
#define BK 32
#define ASTW 20
#define BSTW 68
#define GST  4
#define A_STG (BM*ASTW)
#define B_STG (BM*ASTW)
#define GEMM_SMEM ((GST*(A_STG + B_STG))*4)

template<int GATHER, int TRANSB, int GELU, int RES, int MOE, int OUTBF>
__global__ __launch_bounds__(256) void mma_gemm_bf16(
    const bf16* __restrict__ A, const bf16* __restrict__ Bmat,
    const float* __restrict__ bias, const float* __restrict__ res,
    void* __restrict__ Cv, int M, int N, int K)
{
    extern __shared__ uint32_t gsm[];
    __shared__ int rowsrc[BM];

    int e = MOE ? blockIdx.z : 0;
    int cnt = M, off = 0;
    if (MOE) {
        cnt = g_counts[e]; off = g_offsets[e];
        if ((int)blockIdx.y * BM >= cnt) return;
    }
    int m0 = blockIdx.y * BM;
    int n0 = blockIdx.x * BN;
    int tid = threadIdx.x;

    const bf16* Bbase = Bmat + (size_t)e * K * N;
    const float* bi   = bias + (size_t)e * N;

    if (tid < BM) {
        int lr = m0 + tid;
        int r;
        if (MOE) {
            int l = lr < cnt ? lr : cnt - 1;
            r = GATHER ? g_assign_row[off + l] : (off + l);
        } else r = lr;
        rowsrc[tid] = r;
    }
    __syncthreads();

    int lane = tid & 31;
    int wid  = tid >> 5;
    int wm = (wid >> 2) * 64;
    int wn = (wid & 3) * 32;
    int g  = lane >> 2;
    int tg = lane & 3;

    uint32_t as_base = (uint32_t)__cvta_generic_to_shared(gsm);
    uint32_t bs_base = as_base + GST*A_STG*4u;
    int a_row  = (lane & 7) + ((lane >> 3) & 1) * 8;
    int a_colw = (lane >> 4) * 4;
    int b_nt_sub = (lane >> 4) & 1;
    int b_row  = (lane & 7);
    int b_colw = ((lane >> 3) & 1) * 4;
    int jj = lane >> 3;
    int nn_krow = (lane & 7) + 8*(jj & 1);
    int nn_ncol = 8*(jj >> 1);

    float acc[4][4][4];
    #pragma unroll
    for (int i = 0; i < 4; i++)
        #pragma unroll
        for (int j = 0; j < 4; j++)
            #pragma unroll
            for (int q = 0; q < 4; q++) acc[i][j][q] = 0.f;

    auto stageAB = [&](int k0, int s) {
        #pragma unroll
        for (int p = 0; p < 2; p++) {
            int idx = p*256 + tid;
            int r = idx >> 2, c = idx & 3;
            const bf16* src = A + (size_t)rowsrc[r]*K + k0 + c*8;
            cpasync16(as_base + (((s*BM + r)*ASTW) + c*4)*4u, src);
        }
        if (!TRANSB) {
            #pragma unroll
            for (int p = 0; p < 2; p++) {
                int idx = p*256 + tid;
                int r = idx >> 2, c = idx & 3;
                const bf16* src = Bbase + (size_t)(n0 + r)*K + k0 + c*8;
                cpasync16(bs_base + (((s*BM + r)*ASTW) + c*4)*4u, src);
            }
        } else {
            #pragma unroll
            for (int p = 0; p < 2; p++) {
                int idx = p*256 + tid;
                int kr = idx >> 4, c = idx & 15;
                const bf16* src = Bbase + (size_t)(k0 + kr)*N + n0 + c*8;
                cpasync16(bs_base + (((s*32 + kr)*BSTW) + c*4)*4u, src);
            }
        }
    };

    auto compute = [&](int s) {
        #pragma unroll
        for (int ks = 0; ks < 2; ks++) {
            int k0w = ks * 8;
            uint32_t af[4][4];
            #pragma unroll
            for (int mt = 0; mt < 4; mt++) {
                uint32_t addr = as_base +
                    ((s*BM + wm + mt*16 + a_row)*ASTW + k0w + a_colw) * 4u;
                ldm_x4(af[mt], addr);
            }
            uint32_t bf[2][4];
            if (!TRANSB) {
                #pragma unroll
                for (int ntp = 0; ntp < 2; ntp++) {
                    int nrow = wn + (2*ntp + b_nt_sub)*8 + b_row;
                    uint32_t addr = bs_base + ((s*BN + nrow)*ASTW + k0w + b_colw) * 4u;
                    ldm_x4(bf[ntp], addr);
                }
            } else {
                int krow = s*32 + ks*16 + nn_krow;
                #pragma unroll
                for (int ntp = 0; ntp < 2; ntp++) {
                    uint32_t addr = bs_base + (uint32_t)(krow*BSTW)*4u
                                  + (uint32_t)(wn + ntp*16 + nn_ncol)*2u;
                    ldm_x4_t(bf[ntp], addr);
                }
            }
            #pragma unroll
            for (int mt = 0; mt < 4; mt++) {
                #pragma unroll
                for (int nt = 0; nt < 4; nt++) {
                    const uint32_t* bb = &bf[nt >> 1][(nt & 1) * 2];
                    mma_bf16(acc[mt][nt], af[mt], bb);
                }
            }
        }
    };

    int KT = K / BK;
    stageAB(0, 0);      cpcommit();
    stageAB(BK, 1);     cpcommit();
    stageAB(2*BK, 2);   cpcommit();
    for (int t = 0; t < KT; t++) {
        cpwait<2>();
        __syncthreads();
        if (t + 3 < KT) stageAB((t+3)*BK, (t+3) & 3);
        cpcommit();
        compute(t & 3);
    }

    #pragma unroll
    for (int mt = 0; mt < 4; mt++) {
        #pragma unroll
        for (int h = 0; h < 2; h++) {
            int lr = m0 + wm + mt*16 + g + 8*h;
            if (MOE && lr >= cnt) continue;
            int gr = MOE ? (off + lr) : lr;
            #pragma unroll
            for (int nt = 0; nt < 4; nt++) {
                int cc = n0 + wn + nt*8 + 2*tg;
                float v0 = acc[mt][nt][2*h + 0] + bi[cc];
                float v1 = acc[mt][nt][2*h + 1] + bi[cc + 1];
                if (GELU) {
                    v0 = 0.5f*v0*(1.f + erff(v0*0.70710678118f));
                    v1 = 0.5f*v1*(1.f + erff(v1*0.70710678118f));
                }
                if (RES) {
                    v0 += res[(size_t)gr*N + cc];
                    v1 += res[(size_t)gr*N + cc + 1];
                }
                if (OUTBF)
                    *(uint32_t*)&((bf16*)Cv)[(size_t)gr*N + cc] = packbf2(v0, v1);
                else
                    *(float2*)&((float*)Cv)[(size_t)gr*N + cc] = make_float2(v0, v1);
            }
        }
    }
}

// -- tensor-core flash attention (tf32): 4 warps x 32 Q rows, 3-stage KV ring
// grid (L/128, H, B), 128 threads; each warp owns TWO m16 tiles (32 rows).
#define AST 68
#define VST 72
#define PST 36
#define KVT 32
#define NT3 (Ll/KVT)   // 64 tiles
#define ATT_SMEM ((3*KVT*AST + 3*KVT*VST + 128*PST)*4 + 128)

__global__ __launch_bounds__(128) void flash_attn_tc(
    const float* __restrict__ qkv, const unsigned char* __restrict__ mask,
    bf16* __restrict__ ao)
{
    extern __shared__ uint32_t dsm[];
    uint32_t* Ks = dsm;                          // [3][32][AST]
    uint32_t* Vs = dsm + 3*KVT*AST;              // [3][32][VST]
    uint32_t* Ps = dsm + 3*KVT*AST + 3*KVT*VST;  // [128][PST]
    unsigned char* smask = (unsigned char*)(Ps + 128*PST);  // [3][32]

    int b = blockIdx.z, h = blockIdx.y, qt = blockIdx.x;
    int tid = threadIdx.x;
    int lane = tid & 31, wid = tid >> 5;
    int g = lane >> 2, tg = lane & 3;
    int wq = wid * 32;           // warp's 32 Q rows
    int t0 = b*Ll + qt*128;

    uint32_t sbase = (uint32_t)__cvta_generic_to_shared(dsm);
    uint32_t ks_b = sbase;
    uint32_t vs_b = sbase + 3*KVT*AST*4;
    uint32_t ps_b = vs_b + 3*KVT*VST*4;
    uint32_t mk_b = ps_b + 128*PST*4;

    auto stageKV = [&](int u, int s) {
        int base_t = b*Ll + u*KVT;
        #pragma unroll
        for (int p = 0; p < 4; p++) {
            int idx = p*128 + tid;
            int r = idx >> 4, c = (idx & 15) * 4;
            size_t gb = (size_t)(base_t + r)*QKV3 + h*DHd + c;
            cpasync16(ks_b + (((s*KVT) + r)*AST + c)*4u, &qkv[gb + Dm]);
            cpasync16(vs_b + (((s*KVT) + r)*VST + c)*4u, &qkv[gb + 2*Dm]);
        }
        if (tid < 2)
            cpasync16(mk_b + (uint32_t)(s*KVT + tid*16), &mask[base_t + tid*16]);
        cpcommit();
    };

    stageKV(0, 0);
    stageKV(1, 1);

    // Q fragments for both m-tiles: raw fp32 bits (HW tf32 truncation)
    const uint32_t* qbits = (const uint32_t*)qkv;
    uint32_t qf[2][8][4];
    #pragma unroll
    for (int mt = 0; mt < 2; mt++) {
        size_t r0q = (size_t)(t0+wq+mt*16+g)*QKV3 + h*DHd;
        size_t r1q = (size_t)(t0+wq+mt*16+g+8)*QKV3 + h*DHd;
        #pragma unroll
        for (int ks = 0; ks < 8; ks++) {
            int k0 = ks*8;
            qf[mt][ks][0] = qbits[r0q + k0 + tg];
            qf[mt][ks][1] = qbits[r1q + k0 + tg];
            qf[mt][ks][2] = qbits[r0q + k0 + 4 + tg];
            qf[mt][ks][3] = qbits[r1q + k0 + 4 + tg];
        }
    }

    float oacc[2][8][4];
    #pragma unroll
    for (int mt = 0; mt < 2; mt++)
        #pragma unroll
        for (int nt = 0; nt < 8; nt++)
            #pragma unroll
            for (int q = 0; q < 4; q++) oacc[mt][nt][q] = 0.f;
    float mrow[2][2] = {{-1e30f,-1e30f},{-1e30f,-1e30f}};
    float lrow[2][2] = {{0.f,0.f},{0.f,0.f}};

    for (int u = 0; u < NT3; u++) {
        int s = u % 3;
        cpwait<1>();
        __syncthreads();
        if (u + 2 < NT3) stageKV(u + 2, (u + 2) % 3);
        else cpcommit();

        // ---- S = Q K^T : each K fragment feeds BOTH m-tiles
        float sacc[2][4][4];
        #pragma unroll
        for (int mt = 0; mt < 2; mt++)
            #pragma unroll
            for (int nt = 0; nt < 4; nt++)
                #pragma unroll
                for (int q = 0; q < 4; q++) sacc[mt][nt][q] = 0.f;
        #pragma unroll
        for (int ks = 0; ks < 8; ks++) {
            int k0 = ks*8;
            #pragma unroll
            for (int nt = 0; nt < 4; nt++) {
                uint32_t bf[2];
                bf[0] = Ks[(s*KVT + nt*8+g)*AST + k0 + tg];
                bf[1] = Ks[(s*KVT + nt*8+g)*AST + k0 + 4 + tg];
                mma_tf32(sacc[0][nt], qf[0][ks], bf);
                mma_tf32(sacc[1][nt], qf[1][ks], bf);
            }
        }

        // ---- online softmax (per m-tile)
        #pragma unroll
        for (int mt = 0; mt < 2; mt++) {
            float mx0 = -1e30f, mx1 = -1e30f;
            #pragma unroll
            for (int nt = 0; nt < 4; nt++) {
                #pragma unroll
                for (int j = 0; j < 2; j++) {
                    int c = nt*8 + 2*tg + j;
                    bool mk = smask[s*KVT + c] != 0;
                    float s0 = mk ? -1e9f : sacc[mt][nt][j]   * 0.125f;
                    float s1 = mk ? -1e9f : sacc[mt][nt][2+j] * 0.125f;
                    sacc[mt][nt][j] = s0; sacc[mt][nt][2+j] = s1;
                    mx0 = fmaxf(mx0, s0); mx1 = fmaxf(mx1, s1);
                }
            }
            mx0 = fmaxf(mx0, __shfl_xor_sync(0xffffffffu, mx0, 1));
            mx0 = fmaxf(mx0, __shfl_xor_sync(0xffffffffu, mx0, 2));
            mx1 = fmaxf(mx1, __shfl_xor_sync(0xffffffffu, mx1, 1));
            mx1 = fmaxf(mx1, __shfl_xor_sync(0xffffffffu, mx1, 2));
            float nm0 = fmaxf(mrow[mt][0], mx0), nm1 = fmaxf(mrow[mt][1], mx1);
            float corr0 = __expf(mrow[mt][0] - nm0), corr1 = __expf(mrow[mt][1] - nm1);
            mrow[mt][0] = nm0; mrow[mt][1] = nm1;
            float ls0 = 0.f, ls1 = 0.f;
            #pragma unroll
            for (int nt = 0; nt < 4; nt++) {
                float p00 = __expf(sacc[mt][nt][0] - nm0);
                float p01 = __expf(sacc[mt][nt][1] - nm0);
                float p10 = __expf(sacc[mt][nt][2] - nm1);
                float p11 = __expf(sacc[mt][nt][3] - nm1);
                ls0 += p00 + p01; ls1 += p10 + p11;
                *(uint2*)&Ps[(wq+mt*16+g)*PST   + nt*8 + 2*tg] =
                    make_uint2(__float_as_uint(p00), __float_as_uint(p01));
                *(uint2*)&Ps[(wq+mt*16+g+8)*PST + nt*8 + 2*tg] =
                    make_uint2(__float_as_uint(p10), __float_as_uint(p11));
            }
            ls0 += __shfl_xor_sync(0xffffffffu, ls0, 1);
            ls0 += __shfl_xor_sync(0xffffffffu, ls0, 2);
            ls1 += __shfl_xor_sync(0xffffffffu, ls1, 1);
            ls1 += __shfl_xor_sync(0xffffffffu, ls1, 2);
            lrow[mt][0] = lrow[mt][0]*corr0 + ls0;
            lrow[mt][1] = lrow[mt][1]*corr1 + ls1;
            #pragma unroll
            for (int nt = 0; nt < 8; nt++) {
                oacc[mt][nt][0] *= corr0; oacc[mt][nt][1] *= corr0;
                oacc[mt][nt][2] *= corr1; oacc[mt][nt][3] *= corr1;
            }
        }
        __syncwarp();

        // ---- O += P V : each V fragment feeds BOTH m-tiles
        #pragma unroll
        for (int ks = 0; ks < 4; ks++) {
            int k0 = ks*8;
            uint32_t af[2][4];
            #pragma unroll
            for (int mt = 0; mt < 2; mt++) {
                af[mt][0] = Ps[(wq+mt*16+g)*PST + k0 + tg];
                af[mt][1] = Ps[(wq+mt*16+g+8)*PST + k0 + tg];
                af[mt][2] = Ps[(wq+mt*16+g)*PST + k0 + 4 + tg];
                af[mt][3] = Ps[(wq+mt*16+g+8)*PST + k0 + 4 + tg];
            }
            #pragma unroll
            for (int nt = 0; nt < 8; nt++) {
                uint32_t bf[2];
                bf[0] = Vs[(s*KVT + k0+tg)*VST   + nt*8 + g];
                bf[1] = Vs[(s*KVT + k0+tg+4)*VST + nt*8 + g];
                mma_tf32(oacc[0][nt], af[0], bf);
                mma_tf32(oacc[1][nt], af[1], bf);
            }
        }
    }

    #pragma unroll
    for (int mt = 0; mt < 2; mt++) {
        float inv0 = 1.f / lrow[mt][0], inv1 = 1.f / lrow[mt][1];
        int r0 = t0 + wq + mt*16 + g, r1 = r0 + 8;
        #pragma unroll
        for (int nt = 0; nt < 8; nt++) {
            int c = nt*8 + 2*tg;
            *(uint32_t*)&ao[(size_t)r0*Dm + h*DHd + c] =
                packbf2(oacc[mt][nt][0]*inv0, oacc[mt][nt][1]*inv0);
            *(uint32_t*)&ao[(size_t)r1*Dm + h*DHd + c] =
                packbf2(oacc[mt][nt][2]*inv1, oacc[mt][nt][3]*inv1);
        }
    }
}

// ---------------------------------------------------------- routing helpers
__global__ void offsets_kernel() {
    if (threadIdx.x == 0) {
        int o = 0;
        for (int e = 0; e < Ee; e++) { g_offsets[e] = o; o += g_counts[e]; }
        g_offsets[Ee] = o;
    }
}

__global__ void scatter_kernel() {
    int a = blockIdx.x*blockDim.x + threadIdx.x;
    if (a < NASS) {
        int e = g_idx[a];
        int pos = g_offsets[e] + atomicAdd(&g_fill[e], 1);
        g_assign_row[pos] = a >> 1;
        g_pos_of[a] = pos;
    }
}

// ------------------------------------------------------ combine + moe loss
__global__ __launch_bounds__(256) void combine_kernel(float* __restrict__ out) {
    int t = blockIdx.x, tid = threadIdx.x;
    int p0 = g_pos_of[2*t], p1 = g_pos_of[2*t+1];
    float w0 = g_wts[2*t], w1 = g_wts[2*t+1];
    const float* e0 = g_eo + (size_t)p0*Dm;
    const float* e1 = g_eo + (size_t)p1*Dm;
    const float* xr = g_x1 + (size_t)t*Dm;
    float* orow = out + (size_t)t*Dm;
    for (int d = tid; d < Dm; d += 256)
        orow[d] = xr[d] + w0*e0[d] + w1*e1[d];
}

__global__ __launch_bounds__(256) void mece_kernel() {
    int e = blockIdx.x, tid = threadIdx.x;
    float s = 0.f, c = 0.f;
    for (int t = tid; t < Tt; t += 256) s += g_probs[t*Ee + e];
    for (int a = tid; a < NASS; a += 256) c += (g_idx[a] == e) ? 1.f : 0.f;
    __shared__ float sh1[256], sh2[256];
    sh1[tid] = s; sh2[tid] = c; __syncthreads();
    for (int st = 128; st > 0; st >>= 1) {
        if (tid < st) { sh1[tid] += sh1[tid+st]; sh2[tid] += sh2[tid+st]; }
        __syncthreads();
    }
    if (tid == 0) { g_me[e] = sh1[0]*(1.f/Tt); g_ce[e] = sh2[0]*(1.f/Tt); }
}

__global__ void loss_kernel(float* __restrict__ out, int out_size) {
    if (threadIdx.x == 0 && out_size > Tt*Dm) {
        float L = 0.f;
        for (int e = 0; e < Ee; e++) L += g_me[e]*g_ce[e];
        out[Tt*Dm] = (float)Ee * L;
    }
}

// ------------------------------------------------------------------ driver
extern "C" void kernel_launch(void* const* d_in, const int* in_sizes, int n_in,
                              void* d_out, int out_size)
{
    const float* x     = (const float*)d_in[0];
    const unsigned char* mask = (const unsigned char*)d_in[1];
    const float* ln1_g = (const float*)d_in[2];
    const float* ln1_b = (const float*)d_in[3];
    const float* Wqkv  = (const float*)d_in[4];
    const float* bqkv  = (const float*)d_in[5];
    const float* Wo    = (const float*)d_in[6];
    const float* bo    = (const float*)d_in[7];
    const float* ln2_g = (const float*)d_in[8];
    const float* ln2_b = (const float*)d_in[9];
    const float* Wg    = (const float*)d_in[10];
    const float* bg    = (const float*)d_in[11];
    const float* W1    = (const float*)d_in[12];
    const float* b1    = (const float*)d_in[13];
    const float* W2    = (const float*)d_in[14];
    const float* b2    = (const float*)d_in[15];
    float* out = (float*)d_out;

    float *qkv, *x1, *eobuf;
    bf16 *wqkvb, *wob, *w1b, *w2b, *xn1b, *xn2b, *aob, *hb;
    cudaGetSymbolAddress((void**)&qkv,   g_qkv);
    cudaGetSymbolAddress((void**)&x1,    g_x1);
    cudaGetSymbolAddress((void**)&eobuf, g_eo);
    cudaGetSymbolAddress((void**)&wqkvb, g_wqkv_bf);
    cudaGetSymbolAddress((void**)&wob,   g_wo_bf);
    cudaGetSymbolAddress((void**)&w1b,   g_w1_bf);
    cudaGetSymbolAddress((void**)&w2b,   g_w2_bf);
    cudaGetSymbolAddress((void**)&xn1b,  g_xn1b);
    cudaGetSymbolAddress((void**)&xn2b,  g_xn2b);
    cudaGetSymbolAddress((void**)&aob,   g_aob);
    cudaGetSymbolAddress((void**)&hb,    g_hb);

    static bool attr_set = false;
    static cudaStream_t s2;
    static cudaEvent_t evF, evJ;
    if (!attr_set) {
        cudaFuncSetAttribute(flash_attn_tc,
                             cudaFuncAttributeMaxDynamicSharedMemorySize, ATT_SMEM);
        cudaFuncSetAttribute(mma_gemm_bf16<0,0,0,0,0,0>,
                             cudaFuncAttributeMaxDynamicSharedMemorySize, GEMM_SMEM);
        cudaFuncSetAttribute(mma_gemm_bf16<0,0,0,1,0,0>,
                             cudaFuncAttributeMaxDynamicSharedMemorySize, GEMM_SMEM);
        cudaFuncSetAttribute(mma_gemm_bf16<1,1,1,0,1,1>,
                             cudaFuncAttributeMaxDynamicSharedMemorySize, GEMM_SMEM);
        cudaFuncSetAttribute(mma_gemm_bf16<0,1,0,0,1,0>,
                             cudaFuncAttributeMaxDynamicSharedMemorySize, GEMM_SMEM);
        cudaStreamCreateWithFlags(&s2, cudaStreamNonBlocking);
        cudaEventCreateWithFlags(&evF, cudaEventDisableTiming);
        cudaEventCreateWithFlags(&evJ, cudaEventDisableTiming);
        attr_set = true;
    }

    init_kernel<<<1, 32>>>();

    // QKV weights converted on the main stream (needed immediately)
    f2bf_kernel<<<(QKV3*Dm)/2048, 256>>>(Wqkv, wqkvb);

    // fork: Wo/W1/W2 conversions overlap with LN1 -> QKV -> attention
    cudaEventRecord(evF, 0);
    cudaStreamWaitEvent(s2, evF, 0);
    f2bf_kernel<<<(Dm*Dm)/2048, 256, 0, s2>>>(Wo, wob);
    f2bf_kernel<<<(Ee*Dm*HIDm)/2048, 256, 0, s2>>>(W1, w1b);
    f2bf_kernel<<<(Ee*HIDm*Dm)/2048, 256, 0, s2>>>(W2, w2b);
    cudaEventRecord(evJ, s2);

    // LN1 -> QKV GEMM
    ln_kernel<<<Tt, 256>>>(x, ln1_g, ln1_b, xn1b);
    mma_gemm_bf16<0,0,0,0,0,0><<<dim3(QKV3/BN, Tt/BM), 256, GEMM_SMEM>>>(
        xn1b, wqkvb, bqkv, nullptr, qkv, Tt, QKV3, Dm);

    // attention (tf32 tensor-core flash, 32 rows/warp) -> bf16 ao
    flash_attn_tc<<<dim3(Ll/128, Hh, Bb), 128, ATT_SMEM>>>(qkv, mask, aob);

    // join: Wo/W1/W2 conversions must be done before Wo GEMM
    cudaStreamWaitEvent(0, evJ, 0);

    // output proj + residual (fp32 out)
    mma_gemm_bf16<0,0,0,1,0,0><<<dim3(Dm/BN, Tt/BM), 256, GEMM_SMEM>>>(
        aob, wob, bo, x, x1, Tt, Dm, Dm);

    // LN2 fused with gate -> routing
    ln2_gate_kernel<<<Tt, 256>>>(x1, ln2_g, ln2_b, Wg, bg, xn2b);
    offsets_kernel<<<1, 32>>>();
    scatter_kernel<<<(NASS+255)/256, 256>>>();

    // sparse MoE: up (gather + GELU, NN, bf16 out), down (NN, fp32 out)
    mma_gemm_bf16<1,1,1,0,1,1><<<dim3(HIDm/BN, NASS/BM, Ee), 256, GEMM_SMEM>>>(
        xn2b, w1b, b1, nullptr, hb, Tt, HIDm, Dm);
    mma_gemm_bf16<0,1,0,0,1,0><<<dim3(Dm/BN, NASS/BM, Ee), 256, GEMM_SMEM>>>(
        hb, w2b, b2, nullptr, eobuf, Tt, Dm, HIDm);

    // combine + aux loss
    combine_kernel<<<Tt, 256>>>(out);
    mece_kernel<<<Ee, 256>>>();
    loss_kernel<<<1, 32>>>(out, out_size);
}

// round 10
// speedup vs baseline: 7.7325x; 1.0001x over previous
#include <cuda_runtime.h>
#include <cuda_bf16.h>
#include <math.h>
#include <stdint.h>

// Problem constants
#define Dm    1024
#define Hh    16
#define DHd   64
#define Ee    8
#define HIDm  2048
#define TOPKk 2
#define Bb    2
#define Ll    2048
#define Tt    4096          // B*L
#define QKV3  3072
#define NASS  (Tt*TOPKk)

typedef __nv_bfloat16 bf16;

// ---------------- scratch (static device memory) ---------------------------
__device__ float g_qkv [Tt*QKV3];
__device__ float g_x1  [Tt*Dm];
__device__ float g_probs[Tt*Ee];
__device__ int   g_idx [NASS];
__device__ float g_wts [NASS];
__device__ int   g_counts[Ee];
__device__ int   g_offsets[Ee+1];
__device__ int   g_fill[Ee];
__device__ int   g_assign_row[NASS];
__device__ int   g_pos_of[NASS];
__device__ float g_eo [(size_t)NASS*Dm];
__device__ float g_me [Ee];
__device__ float g_ce [Ee];
// bf16 operand buffers
__device__ bf16  g_wqkv_bf[QKV3*Dm];
__device__ bf16  g_wo_bf  [Dm*Dm];
__device__ bf16  g_w1_bf  [(size_t)Ee*Dm*HIDm];
__device__ bf16  g_w2_bf  [(size_t)Ee*HIDm*Dm];
__device__ bf16  g_xn1b   [Tt*Dm];
__device__ bf16  g_xn2b   [Tt*Dm];
__device__ bf16  g_aob    [Tt*Dm];
__device__ bf16  g_hb     [(size_t)NASS*HIDm];

// ---------------------------------------------------------------- helpers
__device__ __forceinline__ uint32_t packbf2(float a, float b) {
    __nv_bfloat162 h = __floats2bfloat162_rn(a, b);
    return *reinterpret_cast<uint32_t*>(&h);
}
__device__ __forceinline__ void mma_tf32(float* c, const uint32_t* a, const uint32_t* b) {
    asm volatile(
        "mma.sync.aligned.m16n8k8.row.col.f32.tf32.tf32.f32 "
        "{%0,%1,%2,%3}, {%4,%5,%6,%7}, {%8,%9}, {%0,%1,%2,%3};"
        : "+f"(c[0]), "+f"(c[1]), "+f"(c[2]), "+f"(c[3])
        : "r"(a[0]), "r"(a[1]), "r"(a[2]), "r"(a[3]), "r"(b[0]), "r"(b[1]));
}
__device__ __forceinline__ void mma_bf16(float* c, const uint32_t* a, const uint32_t* b) {
    asm volatile(
        "mma.sync.aligned.m16n8k16.row.col.f32.bf16.bf16.f32 "
        "{%0,%1,%2,%3}, {%4,%5,%6,%7}, {%8,%9}, {%0,%1,%2,%3};"
        : "+f"(c[0]), "+f"(c[1]), "+f"(c[2]), "+f"(c[3])
        : "r"(a[0]), "r"(a[1]), "r"(a[2]), "r"(a[3]), "r"(b[0]), "r"(b[1]));
}
__device__ __forceinline__ void ldm_x4(uint32_t* r, uint32_t addr) {
    asm volatile("ldmatrix.sync.aligned.m8n8.x4.shared.b16 {%0,%1,%2,%3}, [%4];"
        : "=r"(r[0]), "=r"(r[1]), "=r"(r[2]), "=r"(r[3]) : "r"(addr));
}
__device__ __forceinline__ void ldm_x4_t(uint32_t* r, uint32_t addr) {
    asm volatile("ldmatrix.sync.aligned.m8n8.x4.trans.shared.b16 {%0,%1,%2,%3}, [%4];"
        : "=r"(r[0]), "=r"(r[1]), "=r"(r[2]), "=r"(r[3]) : "r"(addr));
}
__device__ __forceinline__ void cpasync16(uint32_t dst, const void* src) {
    asm volatile("cp.async.cg.shared.global [%0], [%1], 16;" :: "r"(dst), "l"(src));
}
__device__ __forceinline__ void cpcommit() {
    asm volatile("cp.async.commit_group;");
}
template<int N> __device__ __forceinline__ void cpwait() {
    asm volatile("cp.async.wait_group %0;" :: "n"(N));
}

// ---------------------------------------------------------------- utilities
__global__ void init_kernel() {
    int i = threadIdx.x;
    if (i < Ee) { g_counts[i] = 0; g_fill[i] = 0; }
}

__global__ __launch_bounds__(256) void f2bf_kernel(
    const float* __restrict__ in, bf16* __restrict__ out)
{
    int i = (blockIdx.x*256 + threadIdx.x)*8;
    float4 a = *(const float4*)(in+i);
    float4 b = *(const float4*)(in+i+4);
    uint4 u;
    u.x = packbf2(a.x,a.y); u.y = packbf2(a.z,a.w);
    u.z = packbf2(b.x,b.y); u.w = packbf2(b.z,b.w);
    *(uint4*)&out[i] = u;
}

// LN1: bf16 out only
__global__ __launch_bounds__(256) void ln_kernel(
    const float* __restrict__ x, const float* __restrict__ g,
    const float* __restrict__ b, bf16* __restrict__ outb)
{
    int t = blockIdx.x, tid = threadIdx.x;
    const float* xr = x + (size_t)t*Dm;
    float s = 0.f, s2 = 0.f;
    for (int d = tid; d < Dm; d += 256) { float v = xr[d]; s += v; s2 += v*v; }
    __shared__ float sh1[256], sh2[256];
    sh1[tid] = s; sh2[tid] = s2; __syncthreads();
    for (int st = 128; st > 0; st >>= 1) {
        if (tid < st) { sh1[tid] += sh1[tid+st]; sh2[tid] += sh2[tid+st]; }
        __syncthreads();
    }
    float mu  = sh1[0] * (1.f/Dm);
    float var = sh2[0] * (1.f/Dm) - mu*mu;
    float inv = rsqrtf(var + 1e-5f);
    for (int d = tid*2; d < Dm; d += 512) {
        float v0 = (xr[d]-mu)*inv*g[d] + b[d];
        float v1 = (xr[d+1]-mu)*inv*g[d+1] + b[d+1];
        *(uint32_t*)&outb[(size_t)t*Dm + d] = packbf2(v0, v1);
    }
}

// LN2 fused with gate: bf16 out + routing (probs, top-2, counts)
__global__ __launch_bounds__(256) void ln2_gate_kernel(
    const float* __restrict__ x, const float* __restrict__ g,
    const float* __restrict__ b, const float* __restrict__ Wg,
    const float* __restrict__ bg, bf16* __restrict__ outb)
{
    int t = blockIdx.x, tid = threadIdx.x;
    int lane = tid & 31, wid = tid >> 5;
    const float* xr = x + (size_t)t*Dm;
    float s = 0.f, s2 = 0.f;
    for (int d = tid; d < Dm; d += 256) { float v = xr[d]; s += v; s2 += v*v; }
    __shared__ float sh1[256], sh2[256];
    sh1[tid] = s; sh2[tid] = s2; __syncthreads();
    for (int st = 128; st > 0; st >>= 1) {
        if (tid < st) { sh1[tid] += sh1[tid+st]; sh2[tid] += sh2[tid+st]; }
        __syncthreads();
    }
    float mu  = sh1[0] * (1.f/Dm);
    float var = sh2[0] * (1.f/Dm) - mu*mu;
    float inv = rsqrtf(var + 1e-5f);

    // each thread owns 4 contiguous dims
    int d0 = tid*4;
    float v[4];
    #pragma unroll
    for (int j = 0; j < 4; j++)
        v[j] = (xr[d0+j]-mu)*inv*g[d0+j] + b[d0+j];
    *(uint2*)&outb[(size_t)t*Dm + d0] =
        make_uint2(packbf2(v[0], v[1]), packbf2(v[2], v[3]));

    // gate partials
    float part[Ee] = {};
    #pragma unroll
    for (int j = 0; j < 4; j++) {
        const float4* wr = (const float4*)(Wg + (size_t)(d0+j)*Ee);
        float4 w0 = wr[0], w1 = wr[1];
        part[0] += v[j]*w0.x; part[1] += v[j]*w0.y;
        part[2] += v[j]*w0.z; part[3] += v[j]*w0.w;
        part[4] += v[j]*w1.x; part[5] += v[j]*w1.y;
        part[6] += v[j]*w1.z; part[7] += v[j]*w1.w;
    }
    #pragma unroll
    for (int e = 0; e < Ee; e++) {
        part[e] += __shfl_xor_sync(0xffffffffu, part[e], 16);
        part[e] += __shfl_xor_sync(0xffffffffu, part[e], 8);
        part[e] += __shfl_xor_sync(0xffffffffu, part[e], 4);
        part[e] += __shfl_xor_sync(0xffffffffu, part[e], 2);
        part[e] += __shfl_xor_sync(0xffffffffu, part[e], 1);
    }
    __shared__ float red[8][Ee];
    if (lane == 0)
        #pragma unroll
        for (int e = 0; e < Ee; e++) red[wid][e] = part[e];
    __syncthreads();
    if (tid == 0) {
        float logits[Ee];
        #pragma unroll
        for (int e = 0; e < Ee; e++) {
            float a = 0.f;
            #pragma unroll
            for (int w = 0; w < 8; w++) a += red[w][e];
            logits[e] = a + bg[e];
        }
        float mx = -1e30f;
        #pragma unroll
        for (int e = 0; e < Ee; e++) mx = fmaxf(mx, logits[e]);
        float p[Ee], se = 0.f;
        #pragma unroll
        for (int e = 0; e < Ee; e++) { p[e] = expf(logits[e]-mx); se += p[e]; }
        float isz = 1.f/se;
        #pragma unroll
        for (int e = 0; e < Ee; e++) { p[e] *= isz; g_probs[t*Ee+e] = p[e]; }
        int i0 = 0;
        #pragma unroll
        for (int e = 1; e < Ee; e++) if (p[e] > p[i0]) i0 = e;
        int i1 = (i0 == 0) ? 1 : 0;
        #pragma unroll
        for (int e = 0; e < Ee; e++) if (e != i0 && p[e] > p[i1]) i1 = e;
        float v0 = p[i0], v1 = p[i1], s01 = v0 + v1;
        g_idx[2*t]   = i0; g_idx[2*t+1] = i1;
        g_wts[2*t]   = v0/s01; g_wts[2*t+1] = v1/s01;
        atomicAdd(&g_counts[i0], 1);
        atomicAdd(&g_counts[i1], 1);
    }
}

// -------------------- tensor-core GEMM (bf16, 4-stage cp.async, 1 bar/iter)
#define BM 128
#define BN 128
#define BK 32
#define ASTW 20
#define BSTW 68
#define GST  4
#define A_STG (BM*ASTW)
#define B_STG (BM*ASTW)
#define GEMM_SMEM ((GST*(A_STG + B_STG))*4)

template<int GATHER, int TRANSB, int GELU, int RES, int MOE, int OUTBF>
__global__ __launch_bounds__(256) void mma_gemm_bf16(
    const bf16* __restrict__ A, const bf16* __restrict__ Bmat,
    const float* __restrict__ bias, const float* __restrict__ res,
    void* __restrict__ Cv, int M, int N, int K)
{
    extern __shared__ uint32_t gsm[];
    __shared__ int rowsrc[BM];

    int e = MOE ? blockIdx.z : 0;
    int cnt = M, off = 0;
    if (MOE) {
        cnt = g_counts[e]; off = g_offsets[e];
        if ((int)blockIdx.y * BM >= cnt) return;
    }
    int m0 = blockIdx.y * BM;
    int n0 = blockIdx.x * BN;
    int tid = threadIdx.x;

    const bf16* Bbase = Bmat + (size_t)e * K * N;
    const float* bi   = bias + (size_t)e * N;

    if (tid < BM) {
        int lr = m0 + tid;
        int r;
        if (MOE) {
            int l = lr < cnt ? lr : cnt - 1;
            r = GATHER ? g_assign_row[off + l] : (off + l);
        } else r = lr;
        rowsrc[tid] = r;
    }
    __syncthreads();

    int lane = tid & 31;
    int wid  = tid >> 5;
    int wm = (wid >> 2) * 64;
    int wn = (wid & 3) * 32;
    int g  = lane >> 2;
    int tg = lane & 3;

    uint32_t as_base = (uint32_t)__cvta_generic_to_shared(gsm);
    uint32_t bs_base = as_base + GST*A_STG*4u;
    int a_row  = (lane & 7) + ((lane >> 3) & 1) * 8;
    int a_colw = (lane >> 4) * 4;
    int b_nt_sub = (lane >> 4) & 1;
    int b_row  = (lane & 7);
    int b_colw = ((lane >> 3) & 1) * 4;
    int jj = lane >> 3;
    int nn_krow = (lane & 7) + 8*(jj & 1);
    int nn_ncol = 8*(jj >> 1);

    float acc[4][4][4];
    #pragma unroll
    for (int i = 0; i < 4; i++)
        #pragma unroll
        for (int j = 0; j < 4; j++)
            #pragma unroll
            for (int q = 0; q < 4; q++) acc[i][j][q] = 0.f;

    auto stageAB = [&](int k0, int s) {
        #pragma unroll
        for (int p = 0; p < 2; p++) {
            int idx = p*256 + tid;
            int r = idx >> 2, c = idx & 3;
            const bf16* src = A + (size_t)rowsrc[r]*K + k0 + c*8;
            cpasync16(as_base + (((s*BM + r)*ASTW) + c*4)*4u, src);
        }
        if (!TRANSB) {
            #pragma unroll
            for (int p = 0; p < 2; p++) {
                int idx = p*256 + tid;
                int r = idx >> 2, c = idx & 3;
                const bf16* src = Bbase + (size_t)(n0 + r)*K + k0 + c*8;
                cpasync16(bs_base + (((s*BM + r)*ASTW) + c*4)*4u, src);
            }
        } else {
            #pragma unroll
            for (int p = 0; p < 2; p++) {
                int idx = p*256 + tid;
                int kr = idx >> 4, c = idx & 15;
                const bf16* src = Bbase + (size_t)(k0 + kr)*N + n0 + c*8;
                cpasync16(bs_base + (((s*32 + kr)*BSTW) + c*4)*4u, src);
            }
        }
    };

    auto compute = [&](int s) {
        #pragma unroll
        for (int ks = 0; ks < 2; ks++) {
            int k0w = ks * 8;
            uint32_t af[4][4];
            #pragma unroll
            for (int mt = 0; mt < 4; mt++) {
                uint32_t addr = as_base +
                    ((s*BM + wm + mt*16 + a_row)*ASTW + k0w + a_colw) * 4u;
                ldm_x4(af[mt], addr);
            }
            uint32_t bf[2][4];
            if (!TRANSB) {
                #pragma unroll
                for (int ntp = 0; ntp < 2; ntp++) {
                    int nrow = wn + (2*ntp + b_nt_sub)*8 + b_row;
                    uint32_t addr = bs_base + ((s*BN + nrow)*ASTW + k0w + b_colw) * 4u;
                    ldm_x4(bf[ntp], addr);
                }
            } else {
                int krow = s*32 + ks*16 + nn_krow;
                #pragma unroll
                for (int ntp = 0; ntp < 2; ntp++) {
                    uint32_t addr = bs_base + (uint32_t)(krow*BSTW)*4u
                                  + (uint32_t)(wn + ntp*16 + nn_ncol)*2u;
                    ldm_x4_t(bf[ntp], addr);
                }
            }
            #pragma unroll
            for (int mt = 0; mt < 4; mt++) {
                #pragma unroll
                for (int nt = 0; nt < 4; nt++) {
                    const uint32_t* bb = &bf[nt >> 1][(nt & 1) * 2];
                    mma_bf16(acc[mt][nt], af[mt], bb);
                }
            }
        }
    };

    int KT = K / BK;
    stageAB(0, 0);      cpcommit();
    stageAB(BK, 1);     cpcommit();
    stageAB(2*BK, 2);   cpcommit();
    for (int t = 0; t < KT; t++) {
        cpwait<2>();
        __syncthreads();
        if (t + 3 < KT) stageAB((t+3)*BK, (t+3) & 3);
        cpcommit();
        compute(t & 3);
    }

    #pragma unroll
    for (int mt = 0; mt < 4; mt++) {
        #pragma unroll
        for (int h = 0; h < 2; h++) {
            int lr = m0 + wm + mt*16 + g + 8*h;
            if (MOE && lr >= cnt) continue;
            int gr = MOE ? (off + lr) : lr;
            #pragma unroll
            for (int nt = 0; nt < 4; nt++) {
                int cc = n0 + wn + nt*8 + 2*tg;
                float v0 = acc[mt][nt][2*h + 0] + bi[cc];
                float v1 = acc[mt][nt][2*h + 1] + bi[cc + 1];
                if (GELU) {
                    v0 = 0.5f*v0*(1.f + erff(v0*0.70710678118f));
                    v1 = 0.5f*v1*(1.f + erff(v1*0.70710678118f));
                }
                if (RES) {
                    v0 += res[(size_t)gr*N + cc];
                    v1 += res[(size_t)gr*N + cc + 1];
                }
                if (OUTBF)
                    *(uint32_t*)&((bf16*)Cv)[(size_t)gr*N + cc] = packbf2(v0, v1);
                else
                    *(float2*)&((float*)Cv)[(size_t)gr*N + cc] = make_float2(v0, v1);
            }
        }
    }
}

// -- tensor-core flash attention (tf32): 4 warps x 32 Q rows, 3-stage KV ring
// grid (L/128, H, B), 128 threads; each warp owns TWO m16 tiles (32 rows).
#define AST 68
#define VST 72
#define PST 36
#define KVT 32
#define NT3 (Ll/KVT)   // 64 tiles
#define ATT_SMEM ((3*KVT*AST + 3*KVT*VST + 128*PST)*4 + 128)

__global__ __launch_bounds__(128) void flash_attn_tc(
    const float* __restrict__ qkv, const unsigned char* __restrict__ mask,
    bf16* __restrict__ ao)
{
    extern __shared__ uint32_t dsm[];
    uint32_t* Ks = dsm;                          // [3][32][AST]
    uint32_t* Vs = dsm + 3*KVT*AST;              // [3][32][VST]
    uint32_t* Ps = dsm + 3*KVT*AST + 3*KVT*VST;  // [128][PST]
    unsigned char* smask = (unsigned char*)(Ps + 128*PST);  // [3][32]

    int b = blockIdx.z, h = blockIdx.y, qt = blockIdx.x;
    int tid = threadIdx.x;
    int lane = tid & 31, wid = tid >> 5;
    int g = lane >> 2, tg = lane & 3;
    int wq = wid * 32;           // warp's 32 Q rows
    int t0 = b*Ll + qt*128;

    uint32_t sbase = (uint32_t)__cvta_generic_to_shared(dsm);
    uint32_t ks_b = sbase;
    uint32_t vs_b = sbase + 3*KVT*AST*4;
    uint32_t ps_b = vs_b + 3*KVT*VST*4;
    uint32_t mk_b = ps_b + 128*PST*4;

    auto stageKV = [&](int u, int s) {
        int base_t = b*Ll + u*KVT;
        #pragma unroll
        for (int p = 0; p < 4; p++) {
            int idx = p*128 + tid;
            int r = idx >> 4, c = (idx & 15) * 4;
            size_t gb = (size_t)(base_t + r)*QKV3 + h*DHd + c;
            cpasync16(ks_b + (((s*KVT) + r)*AST + c)*4u, &qkv[gb + Dm]);
            cpasync16(vs_b + (((s*KVT) + r)*VST + c)*4u, &qkv[gb + 2*Dm]);
        }
        if (tid < 2)
            cpasync16(mk_b + (uint32_t)(s*KVT + tid*16), &mask[base_t + tid*16]);
        cpcommit();
    };

    stageKV(0, 0);
    stageKV(1, 1);

    // Q fragments for both m-tiles: raw fp32 bits (HW tf32 truncation)
    const uint32_t* qbits = (const uint32_t*)qkv;
    uint32_t qf[2][8][4];
    #pragma unroll
    for (int mt = 0; mt < 2; mt++) {
        size_t r0q = (size_t)(t0+wq+mt*16+g)*QKV3 + h*DHd;
        size_t r1q = (size_t)(t0+wq+mt*16+g+8)*QKV3 + h*DHd;
        #pragma unroll
        for (int ks = 0; ks < 8; ks++) {
            int k0 = ks*8;
            qf[mt][ks][0] = qbits[r0q + k0 + tg];
            qf[mt][ks][1] = qbits[r1q + k0 + tg];
            qf[mt][ks][2] = qbits[r0q + k0 + 4 + tg];
            qf[mt][ks][3] = qbits[r1q + k0 + 4 + tg];
        }
    }

    float oacc[2][8][4];
    #pragma unroll
    for (int mt = 0; mt < 2; mt++)
        #pragma unroll
        for (int nt = 0; nt < 8; nt++)
            #pragma unroll
            for (int q = 0; q < 4; q++) oacc[mt][nt][q] = 0.f;
    float mrow[2][2] = {{-1e30f,-1e30f},{-1e30f,-1e30f}};
    float lrow[2][2] = {{0.f,0.f},{0.f,0.f}};

    for (int u = 0; u < NT3; u++) {
        int s = u % 3;
        cpwait<1>();
        __syncthreads();
        if (u + 2 < NT3) stageKV(u + 2, (u + 2) % 3);
        else cpcommit();

        // ---- S = Q K^T : each K fragment feeds BOTH m-tiles
        float sacc[2][4][4];
        #pragma unroll
        for (int mt = 0; mt < 2; mt++)
            #pragma unroll
            for (int nt = 0; nt < 4; nt++)
                #pragma unroll
                for (int q = 0; q < 4; q++) sacc[mt][nt][q] = 0.f;
        #pragma unroll
        for (int ks = 0; ks < 8; ks++) {
            int k0 = ks*8;
            #pragma unroll
            for (int nt = 0; nt < 4; nt++) {
                uint32_t bf[2];
                bf[0] = Ks[(s*KVT + nt*8+g)*AST + k0 + tg];
                bf[1] = Ks[(s*KVT + nt*8+g)*AST + k0 + 4 + tg];
                mma_tf32(sacc[0][nt], qf[0][ks], bf);
                mma_tf32(sacc[1][nt], qf[1][ks], bf);
            }
        }

        // ---- online softmax (per m-tile)
        #pragma unroll
        for (int mt = 0; mt < 2; mt++) {
            float mx0 = -1e30f, mx1 = -1e30f;
            #pragma unroll
            for (int nt = 0; nt < 4; nt++) {
                #pragma unroll
                for (int j = 0; j < 2; j++) {
                    int c = nt*8 + 2*tg + j;
                    bool mk = smask[s*KVT + c] != 0;
                    float s0 = mk ? -1e9f : sacc[mt][nt][j]   * 0.125f;
                    float s1 = mk ? -1e9f : sacc[mt][nt][2+j] * 0.125f;
                    sacc[mt][nt][j] = s0; sacc[mt][nt][2+j] = s1;
                    mx0 = fmaxf(mx0, s0); mx1 = fmaxf(mx1, s1);
                }
            }
            mx0 = fmaxf(mx0, __shfl_xor_sync(0xffffffffu, mx0, 1));
            mx0 = fmaxf(mx0, __shfl_xor_sync(0xffffffffu, mx0, 2));
            mx1 = fmaxf(mx1, __shfl_xor_sync(0xffffffffu, mx1, 1));
            mx1 = fmaxf(mx1, __shfl_xor_sync(0xffffffffu, mx1, 2));
            float nm0 = fmaxf(mrow[mt][0], mx0), nm1 = fmaxf(mrow[mt][1], mx1);
            float corr0 = __expf(mrow[mt][0] - nm0), corr1 = __expf(mrow[mt][1] - nm1);
            mrow[mt][0] = nm0; mrow[mt][1] = nm1;
            float ls0 = 0.f, ls1 = 0.f;
            #pragma unroll
            for (int nt = 0; nt < 4; nt++) {
                float p00 = __expf(sacc[mt][nt][0] - nm0);
                float p01 = __expf(sacc[mt][nt][1] - nm0);
                float p10 = __expf(sacc[mt][nt][2] - nm1);
                float p11 = __expf(sacc[mt][nt][3] - nm1);
                ls0 += p00 + p01; ls1 += p10 + p11;
                *(uint2*)&Ps[(wq+mt*16+g)*PST   + nt*8 + 2*tg] =
                    make_uint2(__float_as_uint(p00), __float_as_uint(p01));
                *(uint2*)&Ps[(wq+mt*16+g+8)*PST + nt*8 + 2*tg] =
                    make_uint2(__float_as_uint(p10), __float_as_uint(p11));
            }
            ls0 += __shfl_xor_sync(0xffffffffu, ls0, 1);
            ls0 += __shfl_xor_sync(0xffffffffu, ls0, 2);
            ls1 += __shfl_xor_sync(0xffffffffu, ls1, 1);
            ls1 += __shfl_xor_sync(0xffffffffu, ls1, 2);
            lrow[mt][0] = lrow[mt][0]*corr0 + ls0;
            lrow[mt][1] = lrow[mt][1]*corr1 + ls1;
            #pragma unroll
            for (int nt = 0; nt < 8; nt++) {
                oacc[mt][nt][0] *= corr0; oacc[mt][nt][1] *= corr0;
                oacc[mt][nt][2] *= corr1; oacc[mt][nt][3] *= corr1;
            }
        }
        __syncwarp();

        // ---- O += P V : each V fragment feeds BOTH m-tiles
        #pragma unroll
        for (int ks = 0; ks < 4; ks++) {
            int k0 = ks*8;
            uint32_t af[2][4];
            #pragma unroll
            for (int mt = 0; mt < 2; mt++) {
                af[mt][0] = Ps[(wq+mt*16+g)*PST + k0 + tg];
                af[mt][1] = Ps[(wq+mt*16+g+8)*PST + k0 + tg];
                af[mt][2] = Ps[(wq+mt*16+g)*PST + k0 + 4 + tg];
                af[mt][3] = Ps[(wq+mt*16+g+8)*PST + k0 + 4 + tg];
            }
            #pragma unroll
            for (int nt = 0; nt < 8; nt++) {
                uint32_t bf[2];
                bf[0] = Vs[(s*KVT + k0+tg)*VST   + nt*8 + g];
                bf[1] = Vs[(s*KVT + k0+tg+4)*VST + nt*8 + g];
                mma_tf32(oacc[0][nt], af[0], bf);
                mma_tf32(oacc[1][nt], af[1], bf);
            }
        }
    }

    #pragma unroll
    for (int mt = 0; mt < 2; mt++) {
        float inv0 = 1.f / lrow[mt][0], inv1 = 1.f / lrow[mt][1];
        int r0 = t0 + wq + mt*16 + g, r1 = r0 + 8;
        #pragma unroll
        for (int nt = 0; nt < 8; nt++) {
            int c = nt*8 + 2*tg;
            *(uint32_t*)&ao[(size_t)r0*Dm + h*DHd + c] =
                packbf2(oacc[mt][nt][0]*inv0, oacc[mt][nt][1]*inv0);
            *(uint32_t*)&ao[(size_t)r1*Dm + h*DHd + c] =
                packbf2(oacc[mt][nt][2]*inv1, oacc[mt][nt][3]*inv1);
        }
    }
}

// ---------------------------------------------------------- routing helpers
__global__ void offsets_kernel() {
    if (threadIdx.x == 0) {
        int o = 0;
        for (int e = 0; e < Ee; e++) { g_offsets[e] = o; o += g_counts[e]; }
        g_offsets[Ee] = o;
    }
}

__global__ void scatter_kernel() {
    int a = blockIdx.x*blockDim.x + threadIdx.x;
    if (a < NASS) {
        int e = g_idx[a];
        int pos = g_offsets[e] + atomicAdd(&g_fill[e], 1);
        g_assign_row[pos] = a >> 1;
        g_pos_of[a] = pos;
    }
}

// ------------------------------------------------------ combine + moe loss
__global__ __launch_bounds__(256) void combine_kernel(float* __restrict__ out) {
    int t = blockIdx.x, tid = threadIdx.x;
    int p0 = g_pos_of[2*t], p1 = g_pos_of[2*t+1];
    float w0 = g_wts[2*t], w1 = g_wts[2*t+1];
    const float* e0 = g_eo + (size_t)p0*Dm;
    const float* e1 = g_eo + (size_t)p1*Dm;
    const float* xr = g_x1 + (size_t)t*Dm;
    float* orow = out + (size_t)t*Dm;
    for (int d = tid; d < Dm; d += 256)
        orow[d] = xr[d] + w0*e0[d] + w1*e1[d];
}

__global__ __launch_bounds__(256) void mece_kernel() {
    int e = blockIdx.x, tid = threadIdx.x;
    float s = 0.f, c = 0.f;
    for (int t = tid; t < Tt; t += 256) s += g_probs[t*Ee + e];
    for (int a = tid; a < NASS; a += 256) c += (g_idx[a] == e) ? 1.f : 0.f;
    __shared__ float sh1[256], sh2[256];
    sh1[tid] = s; sh2[tid] = c; __syncthreads();
    for (int st = 128; st > 0; st >>= 1) {
        if (tid < st) { sh1[tid] += sh1[tid+st]; sh2[tid] += sh2[tid+st]; }
        __syncthreads();
    }
    if (tid == 0) { g_me[e] = sh1[0]*(1.f/Tt); g_ce[e] = sh2[0]*(1.f/Tt); }
}

__global__ void loss_kernel(float* __restrict__ out, int out_size) {
    if (threadIdx.x == 0 && out_size > Tt*Dm) {
        float L = 0.f;
        for (int e = 0; e < Ee; e++) L += g_me[e]*g_ce[e];
        out[Tt*Dm] = (float)Ee * L;
    }
}

// ------------------------------------------------------------------ driver
extern "C" void kernel_launch(void* const* d_in, const int* in_sizes, int n_in,
                              void* d_out, int out_size)
{
    const float* x     = (const float*)d_in[0];
    const unsigned char* mask = (const unsigned char*)d_in[1];
    const float* ln1_g = (const float*)d_in[2];
    const float* ln1_b = (const float*)d_in[3];
    const float* Wqkv  = (const float*)d_in[4];
    const float* bqkv  = (const float*)d_in[5];
    const float* Wo    = (const float*)d_in[6];
    const float* bo    = (const float*)d_in[7];
    const float* ln2_g = (const float*)d_in[8];
    const float* ln2_b = (const float*)d_in[9];
    const float* Wg    = (const float*)d_in[10];
    const float* bg    = (const float*)d_in[11];
    const float* W1    = (const float*)d_in[12];
    const float* b1    = (const float*)d_in[13];
    const float* W2    = (const float*)d_in[14];
    const float* b2    = (const float*)d_in[15];
    float* out = (float*)d_out;

    float *qkv, *x1, *eobuf;
    bf16 *wqkvb, *wob, *w1b, *w2b, *xn1b, *xn2b, *aob, *hb;
    cudaGetSymbolAddress((void**)&qkv,   g_qkv);
    cudaGetSymbolAddress((void**)&x1,    g_x1);
    cudaGetSymbolAddress((void**)&eobuf, g_eo);
    cudaGetSymbolAddress((void**)&wqkvb, g_wqkv_bf);
    cudaGetSymbolAddress((void**)&wob,   g_wo_bf);
    cudaGetSymbolAddress((void**)&w1b,   g_w1_bf);
    cudaGetSymbolAddress((void**)&w2b,   g_w2_bf);
    cudaGetSymbolAddress((void**)&xn1b,  g_xn1b);
    cudaGetSymbolAddress((void**)&xn2b,  g_xn2b);
    cudaGetSymbolAddress((void**)&aob,   g_aob);
    cudaGetSymbolAddress((void**)&hb,    g_hb);

    static bool attr_set = false;
    static cudaStream_t s2;
    static cudaEvent_t evF, evJ;
    if (!attr_set) {
        cudaFuncSetAttribute(flash_attn_tc,
                             cudaFuncAttributeMaxDynamicSharedMemorySize, ATT_SMEM);
        cudaFuncSetAttribute(mma_gemm_bf16<0,0,0,0,0,0>,
                             cudaFuncAttributeMaxDynamicSharedMemorySize, GEMM_SMEM);
        cudaFuncSetAttribute(mma_gemm_bf16<0,0,0,1,0,0>,
                             cudaFuncAttributeMaxDynamicSharedMemorySize, GEMM_SMEM);
        cudaFuncSetAttribute(mma_gemm_bf16<1,1,1,0,1,1>,
                             cudaFuncAttributeMaxDynamicSharedMemorySize, GEMM_SMEM);
        cudaFuncSetAttribute(mma_gemm_bf16<0,1,0,0,1,0>,
                             cudaFuncAttributeMaxDynamicSharedMemorySize, GEMM_SMEM);
        cudaStreamCreateWithFlags(&s2, cudaStreamNonBlocking);
        cudaEventCreateWithFlags(&evF, cudaEventDisableTiming);
        cudaEventCreateWithFlags(&evJ, cudaEventDisableTiming);
        attr_set = true;
    }

    init_kernel<<<1, 32>>>();

    // QKV weights converted on the main stream (needed immediately)
    f2bf_kernel<<<(QKV3*Dm)/2048, 256>>>(Wqkv, wqkvb);

    // fork: Wo/W1/W2 conversions overlap with LN1 -> QKV -> attention
    cudaEventRecord(evF, 0);
    cudaStreamWaitEvent(s2, evF, 0);
    f2bf_kernel<<<(Dm*Dm)/2048, 256, 0, s2>>>(Wo, wob);
    f2bf_kernel<<<(Ee*Dm*HIDm)/2048, 256, 0, s2>>>(W1, w1b);
    f2bf_kernel<<<(Ee*HIDm*Dm)/2048, 256, 0, s2>>>(W2, w2b);
    cudaEventRecord(evJ, s2);

    // LN1 -> QKV GEMM
    ln_kernel<<<Tt, 256>>>(x, ln1_g, ln1_b, xn1b);
    mma_gemm_bf16<0,0,0,0,0,0><<<dim3(QKV3/BN, Tt/BM), 256, GEMM_SMEM>>>(
        xn1b, wqkvb, bqkv, nullptr, qkv, Tt, QKV3, Dm);

    // attention (tf32 tensor-core flash, 32 rows/warp) -> bf16 ao
    flash_attn_tc<<<dim3(Ll/128, Hh, Bb), 128, ATT_SMEM>>>(qkv, mask, aob);

    // join: Wo/W1/W2 conversions must be done before Wo GEMM
    cudaStreamWaitEvent(0, evJ, 0);

    // output proj + residual (fp32 out)
    mma_gemm_bf16<0,0,0,1,0,0><<<dim3(Dm/BN, Tt/BM), 256, GEMM_SMEM>>>(
        aob, wob, bo, x, x1, Tt, Dm, Dm);

    // LN2 fused with gate -> routing
    ln2_gate_kernel<<<Tt, 256>>>(x1, ln2_g, ln2_b, Wg, bg, xn2b);
    offsets_kernel<<<1, 32>>>();
    scatter_kernel<<<(NASS+255)/256, 256>>>();

    // sparse MoE: up (gather + GELU, NN, bf16 out), down (NN, fp32 out)
    mma_gemm_bf16<1,1,1,0,1,1><<<dim3(HIDm/BN, NASS/BM, Ee), 256, GEMM_SMEM>>>(
        xn2b, w1b, b1, nullptr, hb, Tt, HIDm, Dm);
    mma_gemm_bf16<0,1,0,0,1,0><<<dim3(Dm/BN, NASS/BM, Ee), 256, GEMM_SMEM>>>(
        hb, w2b, b2, nullptr, eobuf, Tt, Dm, HIDm);

    // combine + aux loss
    combine_kernel<<<Tt, 256>>>(out);
    mece_kernel<<<Ee, 256>>>();
    loss_kernel<<<1, 32>>>(out, out_size);
}